// round 1
// baseline (speedup 1.0000x reference)
#include <cuda_runtime.h>
#include <cuda_bf16.h>

// Problem constants
#define BATCH 2
#define SEQ   2048
#define DMODEL 1024
#define NHEAD 16
#define HDIM  64
#define MROWS (BATCH*SEQ)          // 4096
#define NEG_INF_V (-1.0e9f)

// ---------------- scratch (no allocation allowed) ----------------
__device__ float g_Q[BATCH*NHEAD*SEQ*HDIM];   // [B,H,L,Hd]
__device__ float g_K[BATCH*NHEAD*SEQ*HDIM];
__device__ float g_V[BATCH*NHEAD*SEQ*HDIM];
__device__ float g_O[BATCH*SEQ*DMODEL];       // [B,L,D] head-concat

// =================================================================
// GEMM: C[m,n] = sum_k A[m,k] * W[n,k]   (A:[M,K] row-major, W:[N,K] row-major)
// Tile 128x128x8, 256 threads, 8x8 microtiles.
// MODE 0: write to [B,H,L,Hd] head layout (projections)
// MODE 1: write plain row-major [M,N] (output projection)
// =================================================================
template<int MODE>
__global__ __launch_bounds__(256)
void gemm128(const float* __restrict__ A, const float* __restrict__ W,
             float* __restrict__ C)
{
    const int K = DMODEL;   // 1024
    __shared__ float As[8][128];
    __shared__ float Bs[8][128];

    const int tid = threadIdx.x;
    const int tx = tid & 15;          // 0..15
    const int ty = tid >> 4;          // 0..15
    const int row_l = tid >> 1;       // 0..127 (load row)
    const int ka    = (tid & 1) * 4;  // 0 or 4

    const float* Ab = A + (blockIdx.y * 128 + row_l) * K + ka;
    const float* Wb = W + (blockIdx.x * 128 + row_l) * K + ka;

    float acc[8][8];
#pragma unroll
    for (int i = 0; i < 8; i++)
#pragma unroll
        for (int j = 0; j < 8; j++) acc[i][j] = 0.f;

    for (int k0 = 0; k0 < K; k0 += 8) {
        float4 av = *(const float4*)(Ab + k0);
        float4 bv = *(const float4*)(Wb + k0);
        __syncthreads();
        As[ka+0][row_l] = av.x; As[ka+1][row_l] = av.y;
        As[ka+2][row_l] = av.z; As[ka+3][row_l] = av.w;
        Bs[ka+0][row_l] = bv.x; Bs[ka+1][row_l] = bv.y;
        Bs[ka+2][row_l] = bv.z; Bs[ka+3][row_l] = bv.w;
        __syncthreads();
#pragma unroll
        for (int kk = 0; kk < 8; kk++) {
            float4 a0 = *(const float4*)&As[kk][ty*8];
            float4 a1 = *(const float4*)&As[kk][ty*8+4];
            float4 b0 = *(const float4*)&Bs[kk][tx*8];
            float4 b1 = *(const float4*)&Bs[kk][tx*8+4];
            float a[8] = {a0.x,a0.y,a0.z,a0.w,a1.x,a1.y,a1.z,a1.w};
            float b[8] = {b0.x,b0.y,b0.z,b0.w,b1.x,b1.y,b1.z,b1.w};
#pragma unroll
            for (int i = 0; i < 8; i++)
#pragma unroll
                for (int j = 0; j < 8; j++)
                    acc[i][j] += a[i]*b[j];
        }
    }

#pragma unroll
    for (int i = 0; i < 8; i++) {
        int m = blockIdx.y*128 + ty*8 + i;
#pragma unroll
        for (int j = 0; j < 8; j++) {
            int n = blockIdx.x*128 + tx*8 + j;
            if (MODE == 0) {
                int b = m >> 11;          // /SEQ
                int l = m & (SEQ-1);
                int h = n >> 6;           // /HDIM
                int d = n & (HDIM-1);
                C[(((b*NHEAD + h)*SEQ) + l)*HDIM + d] = acc[i][j];
            } else {
                C[m*DMODEL + n] = acc[i][j];
            }
        }
    }
}

// =================================================================
// Flash attention: one block = 64 queries of one (b,h).
// 256 threads (16x16), 4x4 microtiles; key tiles of 64.
// Reads g_Q/g_K/g_V [B,H,L,Hd], writes g_O [B,L,D] (head-concat).
// =================================================================
#define PS_STRIDE 65
#define SMEM_ATTN ((3*64*64 + 64*PS_STRIDE) * (int)sizeof(float))

__global__ __launch_bounds__(256)
void flash_attn(const int* __restrict__ mask,
                const float* __restrict__ Qg,
                const float* __restrict__ Kg,
                const float* __restrict__ Vg,
                float* __restrict__ Og)
{
    extern __shared__ float sm[];
    float* Qs = sm;               // [d][q]  64x64
    float* Ks = Qs + 64*64;       // [d][k]  64x64
    float* Vs = Ks + 64*64;       // [k][d]  64x64
    float* Ps = Vs + 64*64;       // [k][q]  64 x PS_STRIDE
    __shared__ int msk[64];

    const int tid = threadIdx.x;
    const int tx = tid & 15;
    const int ty = tid >> 4;
    const int bh = blockIdx.y;
    const int b  = bh / NHEAD;
    const int h  = bh % NHEAD;
    const int q0 = blockIdx.x * 64;

    const long bhBase = ((long)(b*NHEAD + h)) * SEQ * HDIM;

    // ---- load Q tile, transposed to [d][q] ----
    {
        int r = tid >> 2;               // 0..63 query row
        int dbase = (tid & 3) * 16;
        const float4* src = (const float4*)(Qg + bhBase + (q0 + r)*HDIM + dbase);
#pragma unroll
        for (int c = 0; c < 4; c++) {
            float4 v = src[c];
            int d = dbase + c*4;
            Qs[(d+0)*64 + r] = v.x;
            Qs[(d+1)*64 + r] = v.y;
            Qs[(d+2)*64 + r] = v.z;
            Qs[(d+3)*64 + r] = v.w;
        }
    }

    float o[4][4];
    float mrow[4], lrow[4];
#pragma unroll
    for (int i = 0; i < 4; i++) {
        mrow[i] = -1e30f; lrow[i] = 0.f;
#pragma unroll
        for (int j = 0; j < 4; j++) o[i][j] = 0.f;
    }

    const float scale = 0.125f;   // 1/sqrt(64)

    for (int kt = 0; kt < SEQ; kt += 64) {
        // ---- load K (transposed) and V (natural) tiles + mask ----
        int r = tid >> 2;
        int dbase = (tid & 3) * 16;
        const float4* ksrc = (const float4*)(Kg + bhBase + (kt + r)*HDIM + dbase);
        const float4* vsrc = (const float4*)(Vg + bhBase + (kt + r)*HDIM + dbase);
        float4 kv[4], vv[4];
#pragma unroll
        for (int c = 0; c < 4; c++) { kv[c] = ksrc[c]; vv[c] = vsrc[c]; }
        int mval = 0;
        if (tid < 64) mval = mask[b*SEQ + kt + tid];

        __syncthreads();   // prior iteration finished reading Ks/Vs/Ps
#pragma unroll
        for (int c = 0; c < 4; c++) {
            int d = dbase + c*4;
            Ks[(d+0)*64 + r] = kv[c].x;
            Ks[(d+1)*64 + r] = kv[c].y;
            Ks[(d+2)*64 + r] = kv[c].z;
            Ks[(d+3)*64 + r] = kv[c].w;
            *(float4*)&Vs[r*64 + d] = vv[c];
        }
        if (tid < 64) msk[tid] = mval;
        __syncthreads();

        // ---- S = Q K^T (scaled) ----
        float s[4][4];
#pragma unroll
        for (int i = 0; i < 4; i++)
#pragma unroll
            for (int j = 0; j < 4; j++) s[i][j] = 0.f;

#pragma unroll 8
        for (int d = 0; d < 64; d++) {
            float4 a = *(const float4*)&Qs[d*64 + ty*4];
            float4 bb = *(const float4*)&Ks[d*64 + tx*4];
            float av[4] = {a.x,a.y,a.z,a.w};
            float bvv[4] = {bb.x,bb.y,bb.z,bb.w};
#pragma unroll
            for (int i = 0; i < 4; i++)
#pragma unroll
                for (int j = 0; j < 4; j++)
                    s[i][j] += av[i]*bvv[j];
        }

#pragma unroll
        for (int i = 0; i < 4; i++)
#pragma unroll
            for (int j = 0; j < 4; j++) {
                float v = s[i][j]*scale;
                s[i][j] = (msk[tx*4+j] == 0) ? NEG_INF_V : v;
            }

        // ---- online softmax (rows shared across the 16 tx lanes) ----
#pragma unroll
        for (int i = 0; i < 4; i++) {
            float tm = fmaxf(fmaxf(s[i][0], s[i][1]), fmaxf(s[i][2], s[i][3]));
#pragma unroll
            for (int off = 8; off >= 1; off >>= 1)
                tm = fmaxf(tm, __shfl_xor_sync(0xffffffffu, tm, off));
            float mnew = fmaxf(mrow[i], tm);
            float fac = __expf(mrow[i] - mnew);
            float rs = 0.f;
#pragma unroll
            for (int j = 0; j < 4; j++) {
                float p = __expf(s[i][j] - mnew);
                s[i][j] = p;
                rs += p;
            }
#pragma unroll
            for (int off = 8; off >= 1; off >>= 1)
                rs += __shfl_xor_sync(0xffffffffu, rs, off);
            lrow[i] = lrow[i]*fac + rs;
            mrow[i] = mnew;
#pragma unroll
            for (int j = 0; j < 4; j++) o[i][j] *= fac;
        }

        // ---- write P transposed [k][q] ----
#pragma unroll
        for (int i = 0; i < 4; i++)
#pragma unroll
            for (int j = 0; j < 4; j++)
                Ps[(tx*4+j)*PS_STRIDE + ty*4 + i] = s[i][j];
        __syncthreads();

        // ---- O += P V ----
#pragma unroll 8
        for (int k = 0; k < 64; k++) {
            float a0 = Ps[k*PS_STRIDE + ty*4 + 0];
            float a1 = Ps[k*PS_STRIDE + ty*4 + 1];
            float a2 = Ps[k*PS_STRIDE + ty*4 + 2];
            float a3 = Ps[k*PS_STRIDE + ty*4 + 3];
            float4 bb = *(const float4*)&Vs[k*64 + tx*4];
            float bvv[4] = {bb.x,bb.y,bb.z,bb.w};
            float av[4] = {a0,a1,a2,a3};
#pragma unroll
            for (int i = 0; i < 4; i++)
#pragma unroll
                for (int j = 0; j < 4; j++)
                    o[i][j] += av[i]*bvv[j];
        }
        // sync at top of next iteration protects Ps/Vs
    }

    // ---- epilogue: normalize and write [B,L,D] head-concat ----
#pragma unroll
    for (int i = 0; i < 4; i++) {
        float inv = 1.f / lrow[i];
        int qg = q0 + ty*4 + i;
#pragma unroll
        for (int j = 0; j < 4; j++) {
            int d = tx*4 + j;
            Og[((long)(b*SEQ + qg))*DMODEL + h*HDIM + d] = o[i][j] * inv;
        }
    }
}

// =================================================================
// Host launcher
// =================================================================
extern "C" void kernel_launch(void* const* d_in, const int* in_sizes, int n_in,
                              void* d_out, int out_size)
{
    const float* q    = (const float*)d_in[0];
    const float* k    = (const float*)d_in[1];
    const float* v    = (const float*)d_in[2];
    const int*   am   = (const int*)  d_in[3];
    const float* Wq   = (const float*)d_in[4];
    const float* Wk   = (const float*)d_in[5];
    const float* Wv   = (const float*)d_in[6];
    const float* Wo   = (const float*)d_in[7];
    float* out = (float*)d_out;

    float *gQ, *gK, *gV, *gO;
    cudaGetSymbolAddress((void**)&gQ, g_Q);
    cudaGetSymbolAddress((void**)&gK, g_K);
    cudaGetSymbolAddress((void**)&gV, g_V);
    cudaGetSymbolAddress((void**)&gO, g_O);

    cudaFuncSetAttribute(flash_attn, cudaFuncAttributeMaxDynamicSharedMemorySize,
                         SMEM_ATTN);

    dim3 gGrid(DMODEL/128, MROWS/128);  // (8, 32)
    gemm128<0><<<gGrid, 256>>>(q, Wq, gQ);
    gemm128<0><<<gGrid, 256>>>(k, Wk, gK);
    gemm128<0><<<gGrid, 256>>>(v, Wv, gV);

    dim3 aGrid(SEQ/64, BATCH*NHEAD);    // (32, 32)
    flash_attn<<<aGrid, 256, SMEM_ATTN>>>(am, gQ, gK, gV, gO);

    gemm128<1><<<gGrid, 256>>>(gO, Wo, out);
}

// round 3
// speedup vs baseline: 3.3032x; 3.3032x over previous
#include <cuda_runtime.h>
#include <cuda_bf16.h>
#include <cstdint>

// Problem constants
#define BATCH 2
#define SEQ   2048
#define DMODEL 1024
#define NHEAD 16
#define HDIM  64
#define MROWS (BATCH*SEQ)          // 4096
#define NEG_INF_V (-1.0e9f)

// ---------------- scratch (no allocation allowed) ----------------
__device__ float g_Q[BATCH*NHEAD*SEQ*HDIM];   // [B,H,L,Hd]
__device__ float g_K[BATCH*NHEAD*SEQ*HDIM];
__device__ float g_V[BATCH*NHEAD*SEQ*HDIM];
__device__ float g_O[BATCH*SEQ*DMODEL];       // [B,L,D] head-concat

// ---------------- mma.sync tf32 helpers (base sm_80+ PTX, no 'a' features)
__device__ __forceinline__ float f2tf32(float f) {
    uint32_t r;
    asm("cvt.rna.tf32.f32 %0, %1;" : "=r"(r) : "f"(f));
    return __uint_as_float(r);
}
__device__ __forceinline__ void mma_tf32(float c[4], const uint32_t a[4],
                                         uint32_t b0, uint32_t b1) {
    asm volatile(
        "mma.sync.aligned.m16n8k8.row.col.f32.tf32.tf32.f32 "
        "{%0,%1,%2,%3},{%4,%5,%6,%7},{%8,%9},{%0,%1,%2,%3};"
        : "+f"(c[0]), "+f"(c[1]), "+f"(c[2]), "+f"(c[3])
        : "r"(a[0]), "r"(a[1]), "r"(a[2]), "r"(a[3]), "r"(b0), "r"(b1));
}

// =================================================================
// tcgen-free tensor GEMM:  C[m,n] = sum_k A[m,k] * W[n,k]
//   CTA tile 128x128, BK=32, 256 threads = 8 warps (2m x 4n),
//   warp tile 64x32 (4 m-tiles x 4 n-tiles of m16n8k8).
//   SMEM: As[128][36], Bs[128][36] (pad 36 -> conflict-free frags),
//   double buffered.
// MODE 0: write [B,H,L,Hd]; MODE 1: row-major [M,1024].
// =================================================================
#define GPAD 36
#define GBUF (128*GPAD)                   // floats per operand buffer
#define GT_SMEM_BYTES (4*GBUF*4)          // A0,B0,A1,B1 = 73728 B

template<int MODE>
__global__ __launch_bounds__(256)
void gemm_mma(const float* __restrict__ A, const float* __restrict__ W,
              float* __restrict__ C)
{
    extern __shared__ float sm[];
    float* As[2] = { sm,          sm + 2*GBUF };
    float* Bs[2] = { sm + GBUF,   sm + 3*GBUF };

    const int tid  = threadIdx.x;
    const int wid  = tid >> 5;
    const int lane = tid & 31;
    const int g    = lane >> 2;      // group id 0..7
    const int tig  = lane & 3;       // thread in group 0..3
    const int wm   = wid & 1;        // 2 warps in m
    const int wn   = wid >> 1;       // 4 warps in n
    const int m0 = blockIdx.y * 128;
    const int n0 = blockIdx.x * 128;

    // global load mapping: r = tid/8 (0..31), f = tid%8 (float4 in 32-wide k)
    const int lr = tid >> 3;
    const int lf = tid & 7;
    const float* Ap = A + (size_t)(m0 + lr) * DMODEL + lf * 4;
    const float* Wp = W + (size_t)(n0 + lr) * DMODEL + lf * 4;

    float acc[4][4][4];
#pragma unroll
    for (int i = 0; i < 4; i++)
#pragma unroll
        for (int j = 0; j < 4; j++)
#pragma unroll
            for (int q = 0; q < 4; q++) acc[i][j][q] = 0.f;

    float4 av[4], bv[4];
    // prologue: chunk 0
#pragma unroll
    for (int p = 0; p < 4; p++) {
        av[p] = *(const float4*)(Ap + (size_t)(p*32) * DMODEL);
        bv[p] = *(const float4*)(Wp + (size_t)(p*32) * DMODEL);
    }
#pragma unroll
    for (int p = 0; p < 4; p++) {
        float* a = &As[0][(lr + p*32) * GPAD + lf*4];
        float* b = &Bs[0][(lr + p*32) * GPAD + lf*4];
        a[0]=f2tf32(av[p].x); a[1]=f2tf32(av[p].y); a[2]=f2tf32(av[p].z); a[3]=f2tf32(av[p].w);
        b[0]=f2tf32(bv[p].x); b[1]=f2tf32(bv[p].y); b[2]=f2tf32(bv[p].z); b[3]=f2tf32(bv[p].w);
    }
    __syncthreads();

    for (int c = 0; c < 32; c++) {
        const int buf = c & 1;
        if (c < 31) {
#pragma unroll
            for (int p = 0; p < 4; p++) {
                av[p] = *(const float4*)(Ap + (size_t)(p*32) * DMODEL + (c+1)*32);
                bv[p] = *(const float4*)(Wp + (size_t)(p*32) * DMODEL + (c+1)*32);
            }
        }
        // compute on current buffer
        const float* Ab = As[buf];
        const float* Bb = Bs[buf];
#pragma unroll
        for (int ks = 0; ks < 4; ks++) {
            const int kb = ks * 8;
            uint32_t afr[4][4];
#pragma unroll
            for (int mt = 0; mt < 4; mt++) {
                int row = wm*64 + mt*16 + g;
                afr[mt][0] = __float_as_uint(Ab[ row      *GPAD + kb + tig    ]);
                afr[mt][1] = __float_as_uint(Ab[(row + 8) *GPAD + kb + tig    ]);
                afr[mt][2] = __float_as_uint(Ab[ row      *GPAD + kb + tig + 4]);
                afr[mt][3] = __float_as_uint(Ab[(row + 8) *GPAD + kb + tig + 4]);
            }
#pragma unroll
            for (int nt = 0; nt < 4; nt++) {
                int n = wn*32 + nt*8 + g;
                uint32_t b0 = __float_as_uint(Bb[n*GPAD + kb + tig    ]);
                uint32_t b1 = __float_as_uint(Bb[n*GPAD + kb + tig + 4]);
#pragma unroll
                for (int mt = 0; mt < 4; mt++)
                    mma_tf32(acc[mt][nt], afr[mt], b0, b1);
            }
        }
        if (c < 31) {
            const int nb = 1 - buf;
#pragma unroll
            for (int p = 0; p < 4; p++) {
                float* a = &As[nb][(lr + p*32) * GPAD + lf*4];
                float* b = &Bs[nb][(lr + p*32) * GPAD + lf*4];
                a[0]=f2tf32(av[p].x); a[1]=f2tf32(av[p].y); a[2]=f2tf32(av[p].z); a[3]=f2tf32(av[p].w);
                b[0]=f2tf32(bv[p].x); b[1]=f2tf32(bv[p].y); b[2]=f2tf32(bv[p].z); b[3]=f2tf32(bv[p].w);
            }
            __syncthreads();
        }
    }

    // epilogue: write float2 pairs straight to global
#pragma unroll
    for (int mt = 0; mt < 4; mt++) {
#pragma unroll
        for (int nt = 0; nt < 4; nt++) {
            int m = m0 + wm*64 + mt*16 + g;
            int n = n0 + wn*32 + nt*8 + 2*tig;
#pragma unroll
            for (int half = 0; half < 2; half++) {
                int mm = m + half*8;
                float2 v = make_float2(acc[mt][nt][half*2], acc[mt][nt][half*2+1]);
                if (MODE == 0) {
                    int b = mm >> 11;
                    int l = mm & (SEQ - 1);
                    int h = n >> 6;
                    int d = n & (HDIM - 1);
                    *(float2*)&C[(size_t)(((b*NHEAD + h)*SEQ) + l)*HDIM + d] = v;
                } else {
                    *(float2*)&C[(size_t)mm * DMODEL + n] = v;
                }
            }
        }
    }
}

// =================================================================
// Flash attention with mma.sync tf32.
//   Block = 64 queries of one (b,h); 128 threads = 4 warps, each
//   warp owns 16 query rows (softmax reductions stay in-warp).
//   Key chunks of 64. SMEM tiles padded to 68 floats/row.
// =================================================================
#define FPAD 68
#define FT (64*FPAD)
#define FA_SMEM_BYTES (4*FT*4)   // Qs,Ks,Vt,Ps = 69632 B

__global__ __launch_bounds__(128)
void flash_mma(const int* __restrict__ mask,
               const float* __restrict__ Qg,
               const float* __restrict__ Kg,
               const float* __restrict__ Vg,
               float* __restrict__ Og)
{
    extern __shared__ float sm[];
    float* Qs = sm;            // [q][d]   64 x 68
    float* Ks = sm + FT;       // [key][d] 64 x 68
    float* Vt = sm + 2*FT;     // [d][key] 64 x 68 (V transposed)
    float* Ps = sm + 3*FT;     // [q][key] 64 x 68
    __shared__ int msk[64];

    const int tid  = threadIdx.x;
    const int wid  = tid >> 5;
    const int lane = tid & 31;
    const int g    = lane >> 2;
    const int tig  = lane & 3;
    const int qb   = wid * 16;           // warp's query base (within tile)

    const int bh = blockIdx.y;
    const int b  = bh / NHEAD;
    const int h  = bh % NHEAD;
    const int q0 = blockIdx.x * 64;

    const size_t bhBase = (size_t)(b*NHEAD + h) * SEQ * HDIM;

    // load Q tile [64][64] (tf32-converted)
    {
        int r = tid >> 1;
        int dbase = (tid & 1) * 32;
        const float4* src = (const float4*)(Qg + bhBase + (size_t)(q0 + r)*HDIM + dbase);
#pragma unroll
        for (int i = 0; i < 8; i++) {
            float4 v = src[i];
            float* dst = &Qs[r*FPAD + dbase + i*4];
            dst[0]=f2tf32(v.x); dst[1]=f2tf32(v.y); dst[2]=f2tf32(v.z); dst[3]=f2tf32(v.w);
        }
    }

    float o[8][4];
#pragma unroll
    for (int nt = 0; nt < 8; nt++)
#pragma unroll
        for (int q = 0; q < 4; q++) o[nt][q] = 0.f;
    float mrow0 = -1e30f, mrow1 = -1e30f, lrow0 = 0.f, lrow1 = 0.f;
    const float scale = 0.125f;   // 1/sqrt(64)

    for (int kt = 0; kt < SEQ; kt += 64) {
        // ---- stage K (natural [key][d]) and V (transposed [d][key]) ----
        int r = tid >> 1;
        int dbase = (tid & 1) * 32;
        const float4* ksrc = (const float4*)(Kg + bhBase + (size_t)(kt + r)*HDIM + dbase);
        const float4* vsrc = (const float4*)(Vg + bhBase + (size_t)(kt + r)*HDIM + dbase);
        float4 kv[8], vv[8];
#pragma unroll
        for (int i = 0; i < 8; i++) { kv[i] = ksrc[i]; vv[i] = vsrc[i]; }
        int mval = 0;
        if (tid < 64) mval = mask[b*SEQ + kt + tid];

        __syncthreads();   // previous chunk fully consumed
#pragma unroll
        for (int i = 0; i < 8; i++) {
            float* kd = &Ks[r*FPAD + dbase + i*4];
            kd[0]=f2tf32(kv[i].x); kd[1]=f2tf32(kv[i].y); kd[2]=f2tf32(kv[i].z); kd[3]=f2tf32(kv[i].w);
            int d = dbase + i*4;
            Vt[(d+0)*FPAD + r] = f2tf32(vv[i].x);
            Vt[(d+1)*FPAD + r] = f2tf32(vv[i].y);
            Vt[(d+2)*FPAD + r] = f2tf32(vv[i].z);
            Vt[(d+3)*FPAD + r] = f2tf32(vv[i].w);
        }
        if (tid < 64) msk[tid] = mval;
        __syncthreads();

        // ---- S = Q K^T (warp: 16q x 64key = 1 m-tile x 8 n-tiles) ----
        float s[8][4];
#pragma unroll
        for (int nt = 0; nt < 8; nt++)
#pragma unroll
            for (int q = 0; q < 4; q++) s[nt][q] = 0.f;

#pragma unroll
        for (int ks = 0; ks < 8; ks++) {
            const int kb = ks * 8;
            uint32_t a[4];
            a[0] = __float_as_uint(Qs[(qb + g    )*FPAD + kb + tig    ]);
            a[1] = __float_as_uint(Qs[(qb + g + 8)*FPAD + kb + tig    ]);
            a[2] = __float_as_uint(Qs[(qb + g    )*FPAD + kb + tig + 4]);
            a[3] = __float_as_uint(Qs[(qb + g + 8)*FPAD + kb + tig + 4]);
#pragma unroll
            for (int nt = 0; nt < 8; nt++) {
                int n = nt*8 + g;
                uint32_t b0 = __float_as_uint(Ks[n*FPAD + kb + tig    ]);
                uint32_t b1 = __float_as_uint(Ks[n*FPAD + kb + tig + 4]);
                mma_tf32(s[nt], a, b0, b1);
            }
        }

        // ---- scale + mask ----
#pragma unroll
        for (int nt = 0; nt < 8; nt++) {
            int j0 = nt*8 + 2*tig;
            bool k0 = (msk[j0]   != 0);
            bool k1 = (msk[j0+1] != 0);
            s[nt][0] = k0 ? s[nt][0]*scale : NEG_INF_V;
            s[nt][1] = k1 ? s[nt][1]*scale : NEG_INF_V;
            s[nt][2] = k0 ? s[nt][2]*scale : NEG_INF_V;
            s[nt][3] = k1 ? s[nt][3]*scale : NEG_INF_V;
        }

        // ---- online softmax: rows r0=g, r1=g+8 (reduce across tig lanes) ----
        float rm0 = -1e30f, rm1 = -1e30f;
#pragma unroll
        for (int nt = 0; nt < 8; nt++) {
            rm0 = fmaxf(rm0, fmaxf(s[nt][0], s[nt][1]));
            rm1 = fmaxf(rm1, fmaxf(s[nt][2], s[nt][3]));
        }
        rm0 = fmaxf(rm0, __shfl_xor_sync(0xffffffffu, rm0, 1));
        rm0 = fmaxf(rm0, __shfl_xor_sync(0xffffffffu, rm0, 2));
        rm1 = fmaxf(rm1, __shfl_xor_sync(0xffffffffu, rm1, 1));
        rm1 = fmaxf(rm1, __shfl_xor_sync(0xffffffffu, rm1, 2));

        float mn0 = fmaxf(mrow0, rm0);
        float mn1 = fmaxf(mrow1, rm1);
        float fac0 = __expf(mrow0 - mn0);
        float fac1 = __expf(mrow1 - mn1);
        float rs0 = 0.f, rs1 = 0.f;
#pragma unroll
        for (int nt = 0; nt < 8; nt++) {
            s[nt][0] = __expf(s[nt][0] - mn0);
            s[nt][1] = __expf(s[nt][1] - mn0);
            s[nt][2] = __expf(s[nt][2] - mn1);
            s[nt][3] = __expf(s[nt][3] - mn1);
            rs0 += s[nt][0] + s[nt][1];
            rs1 += s[nt][2] + s[nt][3];
        }
        rs0 += __shfl_xor_sync(0xffffffffu, rs0, 1);
        rs0 += __shfl_xor_sync(0xffffffffu, rs0, 2);
        rs1 += __shfl_xor_sync(0xffffffffu, rs1, 1);
        rs1 += __shfl_xor_sync(0xffffffffu, rs1, 2);
        lrow0 = lrow0*fac0 + rs0;
        lrow1 = lrow1*fac1 + rs1;
        mrow0 = mn0;
        mrow1 = mn1;
#pragma unroll
        for (int nt = 0; nt < 8; nt++) {
            o[nt][0] *= fac0; o[nt][1] *= fac0;
            o[nt][2] *= fac1; o[nt][3] *= fac1;
        }

        // ---- write P (tf32) to warp-private rows of Ps ----
#pragma unroll
        for (int nt = 0; nt < 8; nt++) {
            int col = nt*8 + 2*tig;
            *(float2*)&Ps[(qb + g    )*FPAD + col] = make_float2(f2tf32(s[nt][0]), f2tf32(s[nt][1]));
            *(float2*)&Ps[(qb + g + 8)*FPAD + col] = make_float2(f2tf32(s[nt][2]), f2tf32(s[nt][3]));
        }
        __syncwarp();

        // ---- O += P V  (A = Ps rows, B = Vt [d][key] col-major kk x d) ----
#pragma unroll
        for (int ks = 0; ks < 8; ks++) {
            const int kb = ks * 8;
            uint32_t a[4];
            a[0] = __float_as_uint(Ps[(qb + g    )*FPAD + kb + tig    ]);
            a[1] = __float_as_uint(Ps[(qb + g + 8)*FPAD + kb + tig    ]);
            a[2] = __float_as_uint(Ps[(qb + g    )*FPAD + kb + tig + 4]);
            a[3] = __float_as_uint(Ps[(qb + g + 8)*FPAD + kb + tig + 4]);
#pragma unroll
            for (int nt = 0; nt < 8; nt++) {
                int d = nt*8 + g;
                uint32_t b0 = __float_as_uint(Vt[d*FPAD + kb + tig    ]);
                uint32_t b1 = __float_as_uint(Vt[d*FPAD + kb + tig + 4]);
                mma_tf32(o[nt], a, b0, b1);
            }
        }
    }

    // ---- epilogue: normalize, write [B,L,D] head-concat ----
    float inv0 = 1.f / lrow0;
    float inv1 = 1.f / lrow1;
    int qg0 = q0 + qb + g;
    int qg1 = qg0 + 8;
#pragma unroll
    for (int nt = 0; nt < 8; nt++) {
        int d = h*HDIM + nt*8 + 2*tig;
        *(float2*)&Og[(size_t)(b*SEQ + qg0)*DMODEL + d] =
            make_float2(o[nt][0]*inv0, o[nt][1]*inv0);
        *(float2*)&Og[(size_t)(b*SEQ + qg1)*DMODEL + d] =
            make_float2(o[nt][2]*inv1, o[nt][3]*inv1);
    }
}

// =================================================================
// Host launcher
// =================================================================
extern "C" void kernel_launch(void* const* d_in, const int* in_sizes, int n_in,
                              void* d_out, int out_size)
{
    const float* q    = (const float*)d_in[0];
    const float* k    = (const float*)d_in[1];
    const float* v    = (const float*)d_in[2];
    const int*   am   = (const int*)  d_in[3];
    const float* Wq   = (const float*)d_in[4];
    const float* Wk   = (const float*)d_in[5];
    const float* Wv   = (const float*)d_in[6];
    const float* Wo   = (const float*)d_in[7];
    float* out = (float*)d_out;

    float *gQ, *gK, *gV, *gO;
    cudaGetSymbolAddress((void**)&gQ, g_Q);
    cudaGetSymbolAddress((void**)&gK, g_K);
    cudaGetSymbolAddress((void**)&gV, g_V);
    cudaGetSymbolAddress((void**)&gO, g_O);

    cudaFuncSetAttribute(gemm_mma<0>, cudaFuncAttributeMaxDynamicSharedMemorySize, GT_SMEM_BYTES);
    cudaFuncSetAttribute(gemm_mma<1>, cudaFuncAttributeMaxDynamicSharedMemorySize, GT_SMEM_BYTES);
    cudaFuncSetAttribute(flash_mma,   cudaFuncAttributeMaxDynamicSharedMemorySize, FA_SMEM_BYTES);

    dim3 gGrid(DMODEL/128, MROWS/128);  // (8, 32)
    gemm_mma<0><<<gGrid, 256, GT_SMEM_BYTES>>>(q, Wq, gQ);
    gemm_mma<0><<<gGrid, 256, GT_SMEM_BYTES>>>(k, Wk, gK);
    gemm_mma<0><<<gGrid, 256, GT_SMEM_BYTES>>>(v, Wv, gV);

    dim3 aGrid(SEQ/64, BATCH*NHEAD);    // (32, 32)
    flash_mma<<<aGrid, 128, FA_SMEM_BYTES>>>(am, gQ, gK, gV, gO);

    gemm_mma<1><<<gGrid, 256, GT_SMEM_BYTES>>>(gO, Wo, out);
}

// round 5
// speedup vs baseline: 4.4269x; 1.3402x over previous
#include <cuda_runtime.h>
#include <cuda_bf16.h>
#include <cstdint>

// Problem constants
#define BATCH 2
#define SEQ   2048
#define DMODEL 1024
#define NHEAD 16
#define HDIM  64
#define MROWS (BATCH*SEQ)          // 4096
#define NEG_INF_V (-1.0e9f)

// ---------------- scratch (no allocation allowed) ----------------
__device__ float g_Q[BATCH*NHEAD*SEQ*HDIM];   // [B,H,L,Hd]
__device__ float g_K[BATCH*NHEAD*SEQ*HDIM];
__device__ float g_V[BATCH*NHEAD*SEQ*HDIM];
__device__ float g_O[BATCH*SEQ*DMODEL];       // [B,L,D] head-concat

// ---------------- mma.sync tf32 helpers (base sm_80+ PTX)
__device__ __forceinline__ float f2tf32(float f) {
    uint32_t r;
    asm("cvt.rna.tf32.f32 %0, %1;" : "=r"(r) : "f"(f));
    return __uint_as_float(r);
}
__device__ __forceinline__ void mma_tf32(float c[4], const uint32_t a[4],
                                         uint32_t b0, uint32_t b1) {
    asm volatile(
        "mma.sync.aligned.m16n8k8.row.col.f32.tf32.tf32.f32 "
        "{%0,%1,%2,%3},{%4,%5,%6,%7},{%8,%9},{%0,%1,%2,%3};"
        : "+f"(c[0]), "+f"(c[1]), "+f"(c[2]), "+f"(c[3])
        : "r"(a[0]), "r"(a[1]), "r"(a[2]), "r"(a[3]), "r"(b0), "r"(b1));
}

// Column permutation within each 8-col group: [c0,c4,c1,c5,c2,c6,c3,c7].
// Then cols (kb+tig, kb+tig+4) sit at positions (kb+2tig, kb+2tig+1) -> LDS.64.

// =================================================================
// Fused tensor GEMM:  C[m,n] = sum_k A[m,k] * W[n,k]
//   CTA tile 128x128, BK=32, 256 threads = 8 warps (2m x 4n),
//   warp tile 64x32. Permuted SMEM (pad 40, 32 data cols) -> LDS.64.
//   blockIdx.z selects one of up to 3 (A,W,C) problem triples.
// MODE 0: write [B,H,L,Hd]; MODE 1: row-major [M,1024].
// =================================================================
#define GPAD 40
#define GBUF (128*GPAD)                   // floats per operand buffer
#define GT_SMEM_BYTES (4*GBUF*4)          // A0,B0,A1,B1 = 81920 B

template<int MODE>
__global__ __launch_bounds__(256, 2)
void gemm_mma(const float* __restrict__ A0, const float* __restrict__ W0, float* __restrict__ C0,
              const float* __restrict__ A1, const float* __restrict__ W1, float* __restrict__ C1,
              const float* __restrict__ A2, const float* __restrict__ W2, float* __restrict__ C2)
{
    extern __shared__ float sm[];
    float* As[2] = { sm,          sm + 2*GBUF };
    float* Bs[2] = { sm + GBUF,   sm + 3*GBUF };

    const float* A = A0; const float* W = W0; float* C = C0;
    if (blockIdx.z == 1)      { A = A1; W = W1; C = C1; }
    else if (blockIdx.z == 2) { A = A2; W = W2; C = C2; }

    const int tid  = threadIdx.x;
    const int wid  = tid >> 5;
    const int lane = tid & 31;
    const int g    = lane >> 2;
    const int tig  = lane & 3;
    const int wm   = wid & 1;
    const int wn   = wid >> 1;
    const int m0 = blockIdx.y * 128;
    const int n0 = blockIdx.x * 128;

    // global load mapping: lr = row 0..31 (+32 steps), lf*4 = col group
    const int lr = tid >> 3;
    const int lf = tid & 7;
    const float* Ap = A + (size_t)(m0 + lr) * DMODEL + lf * 4;
    const float* Wp = W + (size_t)(n0 + lr) * DMODEL + lf * 4;
    // permuted store base: cols 4lf..4lf+3 -> pos 8*(lf>>1)+(lf&1) + 2j  (max 31 < 40)
    const int sbase = lr * GPAD + 8 * (lf >> 1) + (lf & 1);

    float acc[4][4][4];
#pragma unroll
    for (int i = 0; i < 4; i++)
#pragma unroll
        for (int j = 0; j < 4; j++)
#pragma unroll
            for (int q = 0; q < 4; q++) acc[i][j][q] = 0.f;

    float4 av[4], bv[4];
#pragma unroll
    for (int p = 0; p < 4; p++) {
        av[p] = *(const float4*)(Ap + (size_t)(p*32) * DMODEL);
        bv[p] = *(const float4*)(Wp + (size_t)(p*32) * DMODEL);
    }
#pragma unroll
    for (int p = 0; p < 4; p++) {
        float* a = &As[0][sbase + p*32*GPAD];
        float* b = &Bs[0][sbase + p*32*GPAD];
        a[0]=f2tf32(av[p].x); a[2]=f2tf32(av[p].y); a[4]=f2tf32(av[p].z); a[6]=f2tf32(av[p].w);
        b[0]=f2tf32(bv[p].x); b[2]=f2tf32(bv[p].y); b[4]=f2tf32(bv[p].z); b[6]=f2tf32(bv[p].w);
    }
    __syncthreads();

    for (int c = 0; c < 32; c++) {
        const int buf = c & 1;
        if (c < 31) {
#pragma unroll
            for (int p = 0; p < 4; p++) {
                av[p] = *(const float4*)(Ap + (size_t)(p*32) * DMODEL + (c+1)*32);
                bv[p] = *(const float4*)(Wp + (size_t)(p*32) * DMODEL + (c+1)*32);
            }
        }
        const float* Ab = As[buf];
        const float* Bb = Bs[buf];
#pragma unroll
        for (int ks = 0; ks < 4; ks++) {
            const int kb = ks * 8;
            float2 af[4][2];
#pragma unroll
            for (int mt = 0; mt < 4; mt++) {
                int row = wm*64 + mt*16 + g;
                af[mt][0] = *(const float2*)&Ab[ row      *GPAD + kb + 2*tig];
                af[mt][1] = *(const float2*)&Ab[(row + 8) *GPAD + kb + 2*tig];
            }
#pragma unroll
            for (int nt = 0; nt < 4; nt++) {
                int n = wn*32 + nt*8 + g;
                float2 bf = *(const float2*)&Bb[n*GPAD + kb + 2*tig];
                uint32_t b0 = __float_as_uint(bf.x);
                uint32_t b1 = __float_as_uint(bf.y);
#pragma unroll
                for (int mt = 0; mt < 4; mt++) {
                    uint32_t a4[4] = {
                        __float_as_uint(af[mt][0].x), __float_as_uint(af[mt][1].x),
                        __float_as_uint(af[mt][0].y), __float_as_uint(af[mt][1].y) };
                    mma_tf32(acc[mt][nt], a4, b0, b1);
                }
            }
        }
        if (c < 31) {
            const int nb = 1 - buf;
#pragma unroll
            for (int p = 0; p < 4; p++) {
                float* a = &As[nb][sbase + p*32*GPAD];
                float* b = &Bs[nb][sbase + p*32*GPAD];
                a[0]=f2tf32(av[p].x); a[2]=f2tf32(av[p].y); a[4]=f2tf32(av[p].z); a[6]=f2tf32(av[p].w);
                b[0]=f2tf32(bv[p].x); b[2]=f2tf32(bv[p].y); b[4]=f2tf32(bv[p].z); b[6]=f2tf32(bv[p].w);
            }
            __syncthreads();
        }
    }

    // epilogue: write float2 pairs straight to global
#pragma unroll
    for (int mt = 0; mt < 4; mt++) {
#pragma unroll
        for (int nt = 0; nt < 4; nt++) {
            int m = m0 + wm*64 + mt*16 + g;
            int n = n0 + wn*32 + nt*8 + 2*tig;
#pragma unroll
            for (int half = 0; half < 2; half++) {
                int mm = m + half*8;
                float2 v = make_float2(acc[mt][nt][half*2], acc[mt][nt][half*2+1]);
                if (MODE == 0) {
                    int b = mm >> 11;
                    int l = mm & (SEQ - 1);
                    int h = n >> 6;
                    int d = n & (HDIM - 1);
                    *(float2*)&C[(size_t)(((b*NHEAD + h)*SEQ) + l)*HDIM + d] = v;
                } else {
                    *(float2*)&C[(size_t)mm * DMODEL + n] = v;
                }
            }
        }
    }
}

// =================================================================
// Flash attention v2 (fixed pads): 128 queries/block, 4 warps x 32q,
// 64-key chunks. Tiles have 64 data columns:
//   Qs/Ks permuted, pad 72 (72%32==8 -> LDS.64 conflict-free per phase)
//   Vs natural [key][d], pad 72 (scalar B-reads: banks 8*tig+g, all 32)
//   Ps plain, pad 68 (68%32==4 -> scalar A-reads: banks 4g+tig, all 32)
// =================================================================
#define QPAD 72
#define KPAD 72
#define VPAD 72
#define PPAD 68
#define FA_SMEM_FLOATS (128*QPAD + 64*KPAD + 64*VPAD + 128*PPAD)  // 27136
#define FA_SMEM_BYTES (FA_SMEM_FLOATS*4)                          // 108544

__global__ __launch_bounds__(128, 2)
void flash_mma(const int* __restrict__ mask,
               const float* __restrict__ Qg,
               const float* __restrict__ Kg,
               const float* __restrict__ Vg,
               float* __restrict__ Og)
{
    extern __shared__ float sm[];
    float* Qs = sm;                          // [128][72] permuted
    float* Ks = Qs + 128*QPAD;               // [64][72]  permuted
    float* Vs = Ks + 64*KPAD;                // [64][72]  natural [key][d]
    float* Ps = Vs + 64*VPAD;                // [128][68] plain
    __shared__ int msk[64];

    const int tid  = threadIdx.x;
    const int wid  = tid >> 5;
    const int lane = tid & 31;
    const int g    = lane >> 2;
    const int tig  = lane & 3;
    const int qb   = wid * 32;               // warp's query base (2 m-tiles)

    const int bh = blockIdx.y;
    const int b  = bh / NHEAD;
    const int h  = bh % NHEAD;
    const int q0 = blockIdx.x * 128;

    const size_t bhBase = (size_t)(b*NHEAD + h) * SEQ * HDIM;

    // ---- stage Q tile [128][64], permuted + tf32 (once) ----
    {
        const int rr = tid >> 4;             // 0..7
        const int lf = tid & 15;             // col group (4 floats)
        const int sb = 8*(lf>>1) + (lf&1);   // max 57, +6 = 63 < 72
#pragma unroll
        for (int i = 0; i < 16; i++) {
            int row = i*8 + rr;
            float4 v = *(const float4*)(Qg + bhBase + (size_t)(q0 + row)*HDIM + lf*4);
            float* dst = &Qs[row*QPAD + sb];
            dst[0]=f2tf32(v.x); dst[2]=f2tf32(v.y); dst[4]=f2tf32(v.z); dst[6]=f2tf32(v.w);
        }
    }

    float o[2][8][4];
#pragma unroll
    for (int mt = 0; mt < 2; mt++)
#pragma unroll
        for (int nt = 0; nt < 8; nt++)
#pragma unroll
            for (int q = 0; q < 4; q++) o[mt][nt][q] = 0.f;
    float mrow[2][2], lrow[2][2];
#pragma unroll
    for (int mt = 0; mt < 2; mt++) { mrow[mt][0]=mrow[mt][1]=-1e30f; lrow[mt][0]=lrow[mt][1]=0.f; }
    const float scale = 0.125f;   // 1/sqrt(64)

    const int rr = tid >> 4;
    const int lf = tid & 15;
    const int ksb = 8*(lf>>1) + (lf&1);

    for (int kt = 0; kt < SEQ; kt += 64) {
        // ---- prefetch K/V chunk into regs ----
        float4 kreg[8], vreg[8];
#pragma unroll
        for (int i = 0; i < 8; i++) {
            int row = i*8 + rr;
            kreg[i] = *(const float4*)(Kg + bhBase + (size_t)(kt + row)*HDIM + lf*4);
            vreg[i] = *(const float4*)(Vg + bhBase + (size_t)(kt + row)*HDIM + lf*4);
        }
        int mreg = (tid < 64) ? mask[b*SEQ + kt + tid] : 0;

        __syncthreads();   // everyone done reading previous Ks/Vs/Ps
#pragma unroll
        for (int i = 0; i < 8; i++) {
            int row = i*8 + rr;
            float* kd = &Ks[row*KPAD + ksb];
            kd[0]=f2tf32(kreg[i].x); kd[2]=f2tf32(kreg[i].y);
            kd[4]=f2tf32(kreg[i].z); kd[6]=f2tf32(kreg[i].w);
            float4 vc = make_float4(f2tf32(vreg[i].x), f2tf32(vreg[i].y),
                                    f2tf32(vreg[i].z), f2tf32(vreg[i].w));
            *(float4*)&Vs[row*VPAD + lf*4] = vc;
        }
        if (tid < 64) msk[tid] = mreg;
        __syncthreads();

        // ---- S = Q K^T : 2 m-tiles x 8 n-tiles ----
        float s[2][8][4];
#pragma unroll
        for (int mt = 0; mt < 2; mt++)
#pragma unroll
            for (int nt = 0; nt < 8; nt++)
#pragma unroll
                for (int q = 0; q < 4; q++) s[mt][nt][q] = 0.f;

#pragma unroll
        for (int ks = 0; ks < 8; ks++) {
            const int kb = ks * 8;
            float2 aa[2][2];
#pragma unroll
            for (int mt = 0; mt < 2; mt++) {
                int row = qb + mt*16 + g;
                aa[mt][0] = *(const float2*)&Qs[ row      *QPAD + kb + 2*tig];
                aa[mt][1] = *(const float2*)&Qs[(row + 8) *QPAD + kb + 2*tig];
            }
#pragma unroll
            for (int nt = 0; nt < 8; nt++) {
                int n = nt*8 + g;
                float2 bb = *(const float2*)&Ks[n*KPAD + kb + 2*tig];
                uint32_t b0 = __float_as_uint(bb.x);
                uint32_t b1 = __float_as_uint(bb.y);
#pragma unroll
                for (int mt = 0; mt < 2; mt++) {
                    uint32_t a4[4] = {
                        __float_as_uint(aa[mt][0].x), __float_as_uint(aa[mt][1].x),
                        __float_as_uint(aa[mt][0].y), __float_as_uint(aa[mt][1].y) };
                    mma_tf32(s[mt][nt], a4, b0, b1);
                }
            }
        }

        // ---- scale + mask + online softmax + Ps ----
#pragma unroll
        for (int mt = 0; mt < 2; mt++) {
#pragma unroll
            for (int nt = 0; nt < 8; nt++) {
                int j0 = nt*8 + 2*tig;
                bool k0 = (msk[j0]   != 0);
                bool k1 = (msk[j0+1] != 0);
                s[mt][nt][0] = k0 ? s[mt][nt][0]*scale : NEG_INF_V;
                s[mt][nt][1] = k1 ? s[mt][nt][1]*scale : NEG_INF_V;
                s[mt][nt][2] = k0 ? s[mt][nt][2]*scale : NEG_INF_V;
                s[mt][nt][3] = k1 ? s[mt][nt][3]*scale : NEG_INF_V;
            }
            float rm0 = -1e30f, rm1 = -1e30f;
#pragma unroll
            for (int nt = 0; nt < 8; nt++) {
                rm0 = fmaxf(rm0, fmaxf(s[mt][nt][0], s[mt][nt][1]));
                rm1 = fmaxf(rm1, fmaxf(s[mt][nt][2], s[mt][nt][3]));
            }
            rm0 = fmaxf(rm0, __shfl_xor_sync(0xffffffffu, rm0, 1));
            rm0 = fmaxf(rm0, __shfl_xor_sync(0xffffffffu, rm0, 2));
            rm1 = fmaxf(rm1, __shfl_xor_sync(0xffffffffu, rm1, 1));
            rm1 = fmaxf(rm1, __shfl_xor_sync(0xffffffffu, rm1, 2));

            float mn0 = fmaxf(mrow[mt][0], rm0);
            float mn1 = fmaxf(mrow[mt][1], rm1);
            float fac0 = __expf(mrow[mt][0] - mn0);
            float fac1 = __expf(mrow[mt][1] - mn1);
            float rs0 = 0.f, rs1 = 0.f;
#pragma unroll
            for (int nt = 0; nt < 8; nt++) {
                s[mt][nt][0] = __expf(s[mt][nt][0] - mn0);
                s[mt][nt][1] = __expf(s[mt][nt][1] - mn0);
                s[mt][nt][2] = __expf(s[mt][nt][2] - mn1);
                s[mt][nt][3] = __expf(s[mt][nt][3] - mn1);
                rs0 += s[mt][nt][0] + s[mt][nt][1];
                rs1 += s[mt][nt][2] + s[mt][nt][3];
            }
            rs0 += __shfl_xor_sync(0xffffffffu, rs0, 1);
            rs0 += __shfl_xor_sync(0xffffffffu, rs0, 2);
            rs1 += __shfl_xor_sync(0xffffffffu, rs1, 1);
            rs1 += __shfl_xor_sync(0xffffffffu, rs1, 2);
            lrow[mt][0] = lrow[mt][0]*fac0 + rs0;
            lrow[mt][1] = lrow[mt][1]*fac1 + rs1;
            mrow[mt][0] = mn0;
            mrow[mt][1] = mn1;
#pragma unroll
            for (int nt = 0; nt < 8; nt++) {
                o[mt][nt][0] *= fac0; o[mt][nt][1] *= fac0;
                o[mt][nt][2] *= fac1; o[mt][nt][3] *= fac1;
            }
            // write P (tf32) to warp-private rows of Ps (plain layout)
            int row = qb + mt*16 + g;
#pragma unroll
            for (int nt = 0; nt < 8; nt++) {
                int col = nt*8 + 2*tig;
                *(float2*)&Ps[ row      *PPAD + col] =
                    make_float2(f2tf32(s[mt][nt][0]), f2tf32(s[mt][nt][1]));
                *(float2*)&Ps[(row + 8) *PPAD + col] =
                    make_float2(f2tf32(s[mt][nt][2]), f2tf32(s[mt][nt][3]));
            }
        }
        __syncwarp();

        // ---- O += P V ----
#pragma unroll
        for (int ks = 0; ks < 8; ks++) {
            const int kb = ks * 8;
            uint32_t pa[2][4];
#pragma unroll
            for (int mt = 0; mt < 2; mt++) {
                int row = qb + mt*16 + g;
                pa[mt][0] = __float_as_uint(Ps[ row      *PPAD + kb + tig    ]);
                pa[mt][1] = __float_as_uint(Ps[(row + 8) *PPAD + kb + tig    ]);
                pa[mt][2] = __float_as_uint(Ps[ row      *PPAD + kb + tig + 4]);
                pa[mt][3] = __float_as_uint(Ps[(row + 8) *PPAD + kb + tig + 4]);
            }
#pragma unroll
            for (int nt = 0; nt < 8; nt++) {
                int n = nt*8 + g;
                uint32_t b0 = __float_as_uint(Vs[(kb + tig    )*VPAD + n]);
                uint32_t b1 = __float_as_uint(Vs[(kb + tig + 4)*VPAD + n]);
#pragma unroll
                for (int mt = 0; mt < 2; mt++)
                    mma_tf32(o[mt][nt], pa[mt], b0, b1);
            }
        }
    }

    // ---- epilogue: normalize, write [B,L,D] head-concat ----
#pragma unroll
    for (int mt = 0; mt < 2; mt++) {
        float inv0 = 1.f / lrow[mt][0];
        float inv1 = 1.f / lrow[mt][1];
        int qg0 = q0 + qb + mt*16 + g;
        int qg1 = qg0 + 8;
#pragma unroll
        for (int nt = 0; nt < 8; nt++) {
            int d = h*HDIM + nt*8 + 2*tig;
            *(float2*)&Og[(size_t)(b*SEQ + qg0)*DMODEL + d] =
                make_float2(o[mt][nt][0]*inv0, o[mt][nt][1]*inv0);
            *(float2*)&Og[(size_t)(b*SEQ + qg1)*DMODEL + d] =
                make_float2(o[mt][nt][2]*inv1, o[mt][nt][3]*inv1);
        }
    }
}

// =================================================================
// Host launcher
// =================================================================
extern "C" void kernel_launch(void* const* d_in, const int* in_sizes, int n_in,
                              void* d_out, int out_size)
{
    const float* q    = (const float*)d_in[0];
    const float* k    = (const float*)d_in[1];
    const float* v    = (const float*)d_in[2];
    const int*   am   = (const int*)  d_in[3];
    const float* Wq   = (const float*)d_in[4];
    const float* Wk   = (const float*)d_in[5];
    const float* Wv   = (const float*)d_in[6];
    const float* Wo   = (const float*)d_in[7];
    float* out = (float*)d_out;

    float *gQ, *gK, *gV, *gO;
    cudaGetSymbolAddress((void**)&gQ, g_Q);
    cudaGetSymbolAddress((void**)&gK, g_K);
    cudaGetSymbolAddress((void**)&gV, g_V);
    cudaGetSymbolAddress((void**)&gO, g_O);

    cudaFuncSetAttribute(gemm_mma<0>, cudaFuncAttributeMaxDynamicSharedMemorySize, GT_SMEM_BYTES);
    cudaFuncSetAttribute(gemm_mma<1>, cudaFuncAttributeMaxDynamicSharedMemorySize, GT_SMEM_BYTES);
    cudaFuncSetAttribute(flash_mma,   cudaFuncAttributeMaxDynamicSharedMemorySize, FA_SMEM_BYTES);

    // fused QKV projections: one launch, z picks the problem
    dim3 gGrid(DMODEL/128, MROWS/128, 3);  // (8, 32, 3)
    gemm_mma<0><<<gGrid, 256, GT_SMEM_BYTES>>>(q, Wq, gQ,
                                               k, Wk, gK,
                                               v, Wv, gV);

    dim3 aGrid(SEQ/128, BATCH*NHEAD);      // (16, 32)
    flash_mma<<<aGrid, 128, FA_SMEM_BYTES>>>(am, gQ, gK, gV, gO);

    dim3 oGrid(DMODEL/128, MROWS/128, 1);  // (8, 32)
    gemm_mma<1><<<oGrid, 256, GT_SMEM_BYTES>>>(gO, Wo, out,
                                               gO, Wo, out,
                                               gO, Wo, out);
}

// round 6
// speedup vs baseline: 4.4327x; 1.0013x over previous
#include <cuda_runtime.h>
#include <cuda_bf16.h>
#include <cstdint>

// Problem constants
#define BATCH 2
#define SEQ   2048
#define DMODEL 1024
#define NHEAD 16
#define HDIM  64
#define MROWS (BATCH*SEQ)          // 4096
#define NEG_INF_V (-1.0e9f)

// ---------------- scratch (no allocation allowed) ----------------
__device__ float g_Q[BATCH*NHEAD*SEQ*HDIM];   // [B,H,L,Hd]
__device__ float g_K[BATCH*NHEAD*SEQ*HDIM];
__device__ float g_V[BATCH*NHEAD*SEQ*HDIM];
__device__ float g_O[BATCH*SEQ*DMODEL];       // [B,L,D] head-concat

// ---------------- mma.sync tf32 helpers (base sm_80+ PTX)
__device__ __forceinline__ float f2tf32(float f) {
    uint32_t r;
    asm("cvt.rna.tf32.f32 %0, %1;" : "=r"(r) : "f"(f));
    return __uint_as_float(r);
}
__device__ __forceinline__ void mma_tf32(float c[4], const uint32_t a[4],
                                         uint32_t b0, uint32_t b1) {
    asm volatile(
        "mma.sync.aligned.m16n8k8.row.col.f32.tf32.tf32.f32 "
        "{%0,%1,%2,%3},{%4,%5,%6,%7},{%8,%9},{%0,%1,%2,%3};"
        : "+f"(c[0]), "+f"(c[1]), "+f"(c[2]), "+f"(c[3])
        : "r"(a[0]), "r"(a[1]), "r"(a[2]), "r"(a[3]), "r"(b0), "r"(b1));
}

// Column permutation within each 8-col group: [c0,c4,c1,c5,c2,c6,c3,c7].
// Then cols (kb+tig, kb+tig+4) sit at positions (kb+2tig, kb+2tig+1) -> LDS.64.

// =================================================================
// Fused tensor GEMM (unchanged from R5):  C[m,n] = sum_k A[m,k]*W[n,k]
// =================================================================
#define GPAD 40
#define GBUF (128*GPAD)                   // floats per operand buffer
#define GT_SMEM_BYTES (4*GBUF*4)          // A0,B0,A1,B1 = 81920 B

template<int MODE>
__global__ __launch_bounds__(256, 2)
void gemm_mma(const float* __restrict__ A0, const float* __restrict__ W0, float* __restrict__ C0,
              const float* __restrict__ A1, const float* __restrict__ W1, float* __restrict__ C1,
              const float* __restrict__ A2, const float* __restrict__ W2, float* __restrict__ C2)
{
    extern __shared__ float sm[];
    float* As[2] = { sm,          sm + 2*GBUF };
    float* Bs[2] = { sm + GBUF,   sm + 3*GBUF };

    const float* A = A0; const float* W = W0; float* C = C0;
    if (blockIdx.z == 1)      { A = A1; W = W1; C = C1; }
    else if (blockIdx.z == 2) { A = A2; W = W2; C = C2; }

    const int tid  = threadIdx.x;
    const int wid  = tid >> 5;
    const int lane = tid & 31;
    const int g    = lane >> 2;
    const int tig  = lane & 3;
    const int wm   = wid & 1;
    const int wn   = wid >> 1;
    const int m0 = blockIdx.y * 128;
    const int n0 = blockIdx.x * 128;

    const int lr = tid >> 3;
    const int lf = tid & 7;
    const float* Ap = A + (size_t)(m0 + lr) * DMODEL + lf * 4;
    const float* Wp = W + (size_t)(n0 + lr) * DMODEL + lf * 4;
    const int sbase = lr * GPAD + 8 * (lf >> 1) + (lf & 1);

    float acc[4][4][4];
#pragma unroll
    for (int i = 0; i < 4; i++)
#pragma unroll
        for (int j = 0; j < 4; j++)
#pragma unroll
            for (int q = 0; q < 4; q++) acc[i][j][q] = 0.f;

    float4 av[4], bv[4];
#pragma unroll
    for (int p = 0; p < 4; p++) {
        av[p] = *(const float4*)(Ap + (size_t)(p*32) * DMODEL);
        bv[p] = *(const float4*)(Wp + (size_t)(p*32) * DMODEL);
    }
#pragma unroll
    for (int p = 0; p < 4; p++) {
        float* a = &As[0][sbase + p*32*GPAD];
        float* b = &Bs[0][sbase + p*32*GPAD];
        a[0]=f2tf32(av[p].x); a[2]=f2tf32(av[p].y); a[4]=f2tf32(av[p].z); a[6]=f2tf32(av[p].w);
        b[0]=f2tf32(bv[p].x); b[2]=f2tf32(bv[p].y); b[4]=f2tf32(bv[p].z); b[6]=f2tf32(bv[p].w);
    }
    __syncthreads();

    for (int c = 0; c < 32; c++) {
        const int buf = c & 1;
        if (c < 31) {
#pragma unroll
            for (int p = 0; p < 4; p++) {
                av[p] = *(const float4*)(Ap + (size_t)(p*32) * DMODEL + (c+1)*32);
                bv[p] = *(const float4*)(Wp + (size_t)(p*32) * DMODEL + (c+1)*32);
            }
        }
        const float* Ab = As[buf];
        const float* Bb = Bs[buf];
#pragma unroll
        for (int ks = 0; ks < 4; ks++) {
            const int kb = ks * 8;
            float2 af[4][2];
#pragma unroll
            for (int mt = 0; mt < 4; mt++) {
                int row = wm*64 + mt*16 + g;
                af[mt][0] = *(const float2*)&Ab[ row      *GPAD + kb + 2*tig];
                af[mt][1] = *(const float2*)&Ab[(row + 8) *GPAD + kb + 2*tig];
            }
#pragma unroll
            for (int nt = 0; nt < 4; nt++) {
                int n = wn*32 + nt*8 + g;
                float2 bf = *(const float2*)&Bb[n*GPAD + kb + 2*tig];
                uint32_t b0 = __float_as_uint(bf.x);
                uint32_t b1 = __float_as_uint(bf.y);
#pragma unroll
                for (int mt = 0; mt < 4; mt++) {
                    uint32_t a4[4] = {
                        __float_as_uint(af[mt][0].x), __float_as_uint(af[mt][1].x),
                        __float_as_uint(af[mt][0].y), __float_as_uint(af[mt][1].y) };
                    mma_tf32(acc[mt][nt], a4, b0, b1);
                }
            }
        }
        if (c < 31) {
            const int nb = 1 - buf;
#pragma unroll
            for (int p = 0; p < 4; p++) {
                float* a = &As[nb][sbase + p*32*GPAD];
                float* b = &Bs[nb][sbase + p*32*GPAD];
                a[0]=f2tf32(av[p].x); a[2]=f2tf32(av[p].y); a[4]=f2tf32(av[p].z); a[6]=f2tf32(av[p].w);
                b[0]=f2tf32(bv[p].x); b[2]=f2tf32(bv[p].y); b[4]=f2tf32(bv[p].z); b[6]=f2tf32(bv[p].w);
            }
            __syncthreads();
        }
    }

#pragma unroll
    for (int mt = 0; mt < 4; mt++) {
#pragma unroll
        for (int nt = 0; nt < 4; nt++) {
            int m = m0 + wm*64 + mt*16 + g;
            int n = n0 + wn*32 + nt*8 + 2*tig;
#pragma unroll
            for (int half = 0; half < 2; half++) {
                int mm = m + half*8;
                float2 v = make_float2(acc[mt][nt][half*2], acc[mt][nt][half*2+1]);
                if (MODE == 0) {
                    int b = mm >> 11;
                    int l = mm & (SEQ - 1);
                    int h = n >> 6;
                    int d = n & (HDIM - 1);
                    *(float2*)&C[(size_t)(((b*NHEAD + h)*SEQ) + l)*HDIM + d] = v;
                } else {
                    *(float2*)&C[(size_t)mm * DMODEL + n] = v;
                }
            }
        }
    }
}

// =================================================================
// Flash attention v3: 128 queries/block, 4 warps x 32q, 64-key chunks.
//   - P kept in REGISTERS (no Ps smem): PV k-slot j maps to key
//     key(8ks+w) = 8ks + (w<4 ? 2w : 2w-7), which makes the PV
//     A-fragment exactly {s0,s2,s1,s3} and B-fragment rows
//     (8ks+2tig, 8ks+2tig+1) of natural-order V.
//   - Qs/Ks permuted, pad 72 (LDS.64 conflict-free)
//   - Vs natural [key][d], pad 68: PV scalar B-reads banks
//     8*tig + 8*nt + g (+4 for b1) -> all 32 distinct.
//   - softmax scale folded into Q staging (exact, *0.125f)
//   - smem 72704 B -> 3 CTAs/SM (12 warps)
// =================================================================
#define QPAD 72
#define KPAD 72
#define VPAD 68
#define FA_SMEM_FLOATS (128*QPAD + 64*KPAD + 64*VPAD)   // 18176
#define FA_SMEM_BYTES (FA_SMEM_FLOATS*4)                // 72704

__global__ __launch_bounds__(128, 3)
void flash_mma(const int* __restrict__ mask,
               const float* __restrict__ Qg,
               const float* __restrict__ Kg,
               const float* __restrict__ Vg,
               float* __restrict__ Og)
{
    extern __shared__ float sm[];
    float* Qs = sm;                          // [128][72] permuted
    float* Ks = Qs + 128*QPAD;               // [64][72]  permuted
    float* Vs = Ks + 64*KPAD;                // [64][68]  natural [key][d]
    __shared__ int msk[64];

    const int tid  = threadIdx.x;
    const int wid  = tid >> 5;
    const int lane = tid & 31;
    const int g    = lane >> 2;
    const int tig  = lane & 3;
    const int qb   = wid * 32;               // warp's query base (2 m-tiles)

    const int bh = blockIdx.y;
    const int b  = bh / NHEAD;
    const int h  = bh % NHEAD;
    const int q0 = blockIdx.x * 128;

    const size_t bhBase = (size_t)(b*NHEAD + h) * SEQ * HDIM;

    // ---- stage Q tile [128][64], permuted + tf32, scaled by 1/8 (exact) ----
    {
        const int rr = tid >> 4;             // 0..7
        const int lf = tid & 15;             // col group (4 floats)
        const int sb = 8*(lf>>1) + (lf&1);   // max 57, +6 = 63 < 72
#pragma unroll
        for (int i = 0; i < 16; i++) {
            int row = i*8 + rr;
            float4 v = *(const float4*)(Qg + bhBase + (size_t)(q0 + row)*HDIM + lf*4);
            float* dst = &Qs[row*QPAD + sb];
            dst[0]=f2tf32(v.x*0.125f); dst[2]=f2tf32(v.y*0.125f);
            dst[4]=f2tf32(v.z*0.125f); dst[6]=f2tf32(v.w*0.125f);
        }
    }

    float o[2][8][4];
#pragma unroll
    for (int mt = 0; mt < 2; mt++)
#pragma unroll
        for (int nt = 0; nt < 8; nt++)
#pragma unroll
            for (int q = 0; q < 4; q++) o[mt][nt][q] = 0.f;
    float mrow[2][2], lrow[2][2];
#pragma unroll
    for (int mt = 0; mt < 2; mt++) { mrow[mt][0]=mrow[mt][1]=-1e30f; lrow[mt][0]=lrow[mt][1]=0.f; }

    const int rr = tid >> 4;
    const int lf = tid & 15;
    const int ksb = 8*(lf>>1) + (lf&1);

    for (int kt = 0; kt < SEQ; kt += 64) {
        // ---- prefetch K/V chunk into regs ----
        float4 kreg[8], vreg[8];
#pragma unroll
        for (int i = 0; i < 8; i++) {
            int row = i*8 + rr;
            kreg[i] = *(const float4*)(Kg + bhBase + (size_t)(kt + row)*HDIM + lf*4);
            vreg[i] = *(const float4*)(Vg + bhBase + (size_t)(kt + row)*HDIM + lf*4);
        }
        int mreg = (tid < 64) ? mask[b*SEQ + kt + tid] : 0;

        __syncthreads();   // everyone done reading previous Ks/Vs
#pragma unroll
        for (int i = 0; i < 8; i++) {
            int row = i*8 + rr;
            float* kd = &Ks[row*KPAD + ksb];
            kd[0]=f2tf32(kreg[i].x); kd[2]=f2tf32(kreg[i].y);
            kd[4]=f2tf32(kreg[i].z); kd[6]=f2tf32(kreg[i].w);
            float4 vc = make_float4(f2tf32(vreg[i].x), f2tf32(vreg[i].y),
                                    f2tf32(vreg[i].z), f2tf32(vreg[i].w));
            *(float4*)&Vs[row*VPAD + lf*4] = vc;
        }
        if (tid < 64) msk[tid] = mreg;
        __syncthreads();

        // ---- S = Q K^T : 2 m-tiles x 8 n-tiles (Q pre-scaled) ----
        float s[2][8][4];
#pragma unroll
        for (int mt = 0; mt < 2; mt++)
#pragma unroll
            for (int nt = 0; nt < 8; nt++)
#pragma unroll
                for (int q = 0; q < 4; q++) s[mt][nt][q] = 0.f;

#pragma unroll
        for (int ks = 0; ks < 8; ks++) {
            const int kb = ks * 8;
            float2 aa[2][2];
#pragma unroll
            for (int mt = 0; mt < 2; mt++) {
                int row = qb + mt*16 + g;
                aa[mt][0] = *(const float2*)&Qs[ row      *QPAD + kb + 2*tig];
                aa[mt][1] = *(const float2*)&Qs[(row + 8) *QPAD + kb + 2*tig];
            }
#pragma unroll
            for (int nt = 0; nt < 8; nt++) {
                int n = nt*8 + g;
                float2 bb = *(const float2*)&Ks[n*KPAD + kb + 2*tig];
                uint32_t b0 = __float_as_uint(bb.x);
                uint32_t b1 = __float_as_uint(bb.y);
#pragma unroll
                for (int mt = 0; mt < 2; mt++) {
                    uint32_t a4[4] = {
                        __float_as_uint(aa[mt][0].x), __float_as_uint(aa[mt][1].x),
                        __float_as_uint(aa[mt][0].y), __float_as_uint(aa[mt][1].y) };
                    mma_tf32(s[mt][nt], a4, b0, b1);
                }
            }
        }

        // ---- mask + online softmax (scale already in Q) ----
#pragma unroll
        for (int mt = 0; mt < 2; mt++) {
#pragma unroll
            for (int nt = 0; nt < 8; nt++) {
                int j0 = nt*8 + 2*tig;
                bool k0 = (msk[j0]   != 0);
                bool k1 = (msk[j0+1] != 0);
                s[mt][nt][0] = k0 ? s[mt][nt][0] : NEG_INF_V;
                s[mt][nt][1] = k1 ? s[mt][nt][1] : NEG_INF_V;
                s[mt][nt][2] = k0 ? s[mt][nt][2] : NEG_INF_V;
                s[mt][nt][3] = k1 ? s[mt][nt][3] : NEG_INF_V;
            }
            float rm0 = -1e30f, rm1 = -1e30f;
#pragma unroll
            for (int nt = 0; nt < 8; nt++) {
                rm0 = fmaxf(rm0, fmaxf(s[mt][nt][0], s[mt][nt][1]));
                rm1 = fmaxf(rm1, fmaxf(s[mt][nt][2], s[mt][nt][3]));
            }
            rm0 = fmaxf(rm0, __shfl_xor_sync(0xffffffffu, rm0, 1));
            rm0 = fmaxf(rm0, __shfl_xor_sync(0xffffffffu, rm0, 2));
            rm1 = fmaxf(rm1, __shfl_xor_sync(0xffffffffu, rm1, 1));
            rm1 = fmaxf(rm1, __shfl_xor_sync(0xffffffffu, rm1, 2));

            float mn0 = fmaxf(mrow[mt][0], rm0);
            float mn1 = fmaxf(mrow[mt][1], rm1);
            float fac0 = __expf(mrow[mt][0] - mn0);
            float fac1 = __expf(mrow[mt][1] - mn1);
            float rs0 = 0.f, rs1 = 0.f;
#pragma unroll
            for (int nt = 0; nt < 8; nt++) {
                s[mt][nt][0] = __expf(s[mt][nt][0] - mn0);
                s[mt][nt][1] = __expf(s[mt][nt][1] - mn0);
                s[mt][nt][2] = __expf(s[mt][nt][2] - mn1);
                s[mt][nt][3] = __expf(s[mt][nt][3] - mn1);
                rs0 += s[mt][nt][0] + s[mt][nt][1];
                rs1 += s[mt][nt][2] + s[mt][nt][3];
            }
            rs0 += __shfl_xor_sync(0xffffffffu, rs0, 1);
            rs0 += __shfl_xor_sync(0xffffffffu, rs0, 2);
            rs1 += __shfl_xor_sync(0xffffffffu, rs1, 1);
            rs1 += __shfl_xor_sync(0xffffffffu, rs1, 2);
            lrow[mt][0] = lrow[mt][0]*fac0 + rs0;
            lrow[mt][1] = lrow[mt][1]*fac1 + rs1;
            mrow[mt][0] = mn0;
            mrow[mt][1] = mn1;
#pragma unroll
            for (int nt = 0; nt < 8; nt++) {
                o[mt][nt][0] *= fac0; o[mt][nt][1] *= fac0;
                o[mt][nt][2] *= fac1; o[mt][nt][3] *= fac1;
            }
            // convert P to tf32 in place (registers)
#pragma unroll
            for (int nt = 0; nt < 8; nt++) {
                s[mt][nt][0] = f2tf32(s[mt][nt][0]);
                s[mt][nt][1] = f2tf32(s[mt][nt][1]);
                s[mt][nt][2] = f2tf32(s[mt][nt][2]);
                s[mt][nt][3] = f2tf32(s[mt][nt][3]);
            }
        }

        // ---- O += P V : A-fragment from registers, B rows permuted ----
        //   MMA k-slot 8ks+w corresponds to key 8ks + (w<4 ? 2w : 2w-7).
        //   a = {s0, s2, s1, s3}; b0 = V[8ks+2tig], b1 = V[8ks+2tig+1].
#pragma unroll
        for (int ks = 0; ks < 8; ks++) {
            const int kb = ks * 8;
#pragma unroll
            for (int nt = 0; nt < 8; nt++) {
                int n = nt*8 + g;
                uint32_t b0 = __float_as_uint(Vs[(kb + 2*tig    )*VPAD + n]);
                uint32_t b1 = __float_as_uint(Vs[(kb + 2*tig + 1)*VPAD + n]);
#pragma unroll
                for (int mt = 0; mt < 2; mt++) {
                    uint32_t a4[4] = {
                        __float_as_uint(s[mt][ks][0]), __float_as_uint(s[mt][ks][2]),
                        __float_as_uint(s[mt][ks][1]), __float_as_uint(s[mt][ks][3]) };
                    mma_tf32(o[mt][nt], a4, b0, b1);
                }
            }
        }
    }

    // ---- epilogue: normalize, write [B,L,D] head-concat ----
#pragma unroll
    for (int mt = 0; mt < 2; mt++) {
        float inv0 = 1.f / lrow[mt][0];
        float inv1 = 1.f / lrow[mt][1];
        int qg0 = q0 + qb + mt*16 + g;
        int qg1 = qg0 + 8;
#pragma unroll
        for (int nt = 0; nt < 8; nt++) {
            int d = h*HDIM + nt*8 + 2*tig;
            *(float2*)&Og[(size_t)(b*SEQ + qg0)*DMODEL + d] =
                make_float2(o[mt][nt][0]*inv0, o[mt][nt][1]*inv0);
            *(float2*)&Og[(size_t)(b*SEQ + qg1)*DMODEL + d] =
                make_float2(o[mt][nt][2]*inv1, o[mt][nt][3]*inv1);
        }
    }
}

// =================================================================
// Host launcher
// =================================================================
extern "C" void kernel_launch(void* const* d_in, const int* in_sizes, int n_in,
                              void* d_out, int out_size)
{
    const float* q    = (const float*)d_in[0];
    const float* k    = (const float*)d_in[1];
    const float* v    = (const float*)d_in[2];
    const int*   am   = (const int*)  d_in[3];
    const float* Wq   = (const float*)d_in[4];
    const float* Wk   = (const float*)d_in[5];
    const float* Wv   = (const float*)d_in[6];
    const float* Wo   = (const float*)d_in[7];
    float* out = (float*)d_out;

    float *gQ, *gK, *gV, *gO;
    cudaGetSymbolAddress((void**)&gQ, g_Q);
    cudaGetSymbolAddress((void**)&gK, g_K);
    cudaGetSymbolAddress((void**)&gV, g_V);
    cudaGetSymbolAddress((void**)&gO, g_O);

    cudaFuncSetAttribute(gemm_mma<0>, cudaFuncAttributeMaxDynamicSharedMemorySize, GT_SMEM_BYTES);
    cudaFuncSetAttribute(gemm_mma<1>, cudaFuncAttributeMaxDynamicSharedMemorySize, GT_SMEM_BYTES);
    cudaFuncSetAttribute(flash_mma,   cudaFuncAttributeMaxDynamicSharedMemorySize, FA_SMEM_BYTES);

    // fused QKV projections: one launch, z picks the problem
    dim3 gGrid(DMODEL/128, MROWS/128, 3);  // (8, 32, 3)
    gemm_mma<0><<<gGrid, 256, GT_SMEM_BYTES>>>(q, Wq, gQ,
                                               k, Wk, gK,
                                               v, Wv, gV);

    dim3 aGrid(SEQ/128, BATCH*NHEAD);      // (16, 32)
    flash_mma<<<aGrid, 128, FA_SMEM_BYTES>>>(am, gQ, gK, gV, gO);

    dim3 oGrid(DMODEL/128, MROWS/128, 1);  // (8, 32)
    gemm_mma<1><<<oGrid, 256, GT_SMEM_BYTES>>>(gO, Wo, out,
                                               gO, Wo, out,
                                               gO, Wo, out);
}

// round 7
// speedup vs baseline: 4.5205x; 1.0198x over previous
#include <cuda_runtime.h>
#include <cstdint>

// Problem constants
#define BATCH 2
#define SEQ   2048
#define DMODEL 1024
#define NHEAD 16
#define HDIM  64
#define MROWS (BATCH*SEQ)          // 4096
#define NEG_INF_V (-1.0e9f)

// ---------------- scratch (no allocation allowed) ----------------
__device__ float g_A[3u*MROWS*DMODEL];        // rounded+permuted q,k,v
__device__ float g_W[4u*DMODEL*DMODEL];       // rounded+permuted Wq,Wk,Wv,Wo
__device__ float g_Q[BATCH*NHEAD*SEQ*HDIM];   // [B,H,L,Hd] scaled+rounded+permuted
__device__ float g_K[BATCH*NHEAD*SEQ*HDIM];   // [B,H,L,Hd] rounded+permuted
__device__ float g_V[BATCH*NHEAD*SEQ*HDIM];   // [B,H,L,Hd] rounded, natural
__device__ float g_O[BATCH*SEQ*DMODEL];       // [B,L,D] rounded+permuted

// ---------------- helpers ----------------
__device__ __forceinline__ float f2tf32(float f) {
    uint32_t r;
    asm("cvt.rna.tf32.f32 %0, %1;" : "=r"(r) : "f"(f));
    return __uint_as_float(r);
}
__device__ __forceinline__ void mma_tf32(float c[4], const uint32_t a[4],
                                         uint32_t b0, uint32_t b1) {
    asm volatile(
        "mma.sync.aligned.m16n8k8.row.col.f32.tf32.tf32.f32 "
        "{%0,%1,%2,%3},{%4,%5,%6,%7},{%8,%9},{%0,%1,%2,%3};"
        : "+f"(c[0]), "+f"(c[1]), "+f"(c[2]), "+f"(c[3])
        : "r"(a[0]), "r"(a[1]), "r"(a[2]), "r"(a[3]), "r"(b0), "r"(b1));
}
__device__ __forceinline__ uint32_t smem_u32(const void* p) {
    uint32_t a;
    asm("{ .reg .u64 t; cvta.to.shared.u64 t, %1; cvt.u32.u64 %0, t; }" : "=r"(a) : "l"(p));
    return a;
}
__device__ __forceinline__ void cp16(uint32_t dst, const void* src) {
    asm volatile("cp.async.cg.shared.global [%0], [%1], 16;" :: "r"(dst), "l"(src) : "memory");
}
__device__ __forceinline__ void cp_commit() {
    asm volatile("cp.async.commit_group;" ::: "memory");
}
__device__ __forceinline__ void cp_wait0() {
    asm volatile("cp.async.wait_group 0;" ::: "memory");
}

// Column permutation within each 8-col group: [c0,c4,c1,c5,c2,c6,c3,c7].
// Fragment cols (kb+tig, kb+tig+4) then sit adjacent -> LDS.64.

// =================================================================
// Pre-pass: RNA-round to tf32 and permute 8-col groups.
// Each thread handles one group of 8 consecutive floats.
// =================================================================
__global__ __launch_bounds__(256)
void prep_permute(const float* __restrict__ s0, const float* __restrict__ s1,
                  const float* __restrict__ s2, const float* __restrict__ s3,
                  float* __restrict__ dst, int groupsPerMat)
{
    const float* s = (blockIdx.z == 0) ? s0 : (blockIdx.z == 1) ? s1 :
                     (blockIdx.z == 2) ? s2 : s3;
    int i = blockIdx.x * blockDim.x + threadIdx.x;
    if (i >= groupsPerMat) return;
    const float4* sp = (const float4*)(s + (size_t)i * 8);
    float4 a = sp[0], b = sp[1];
    float2* d = (float2*)(dst + ((size_t)blockIdx.z * groupsPerMat + i) * 8);
    d[0] = make_float2(f2tf32(a.x), f2tf32(b.x));
    d[1] = make_float2(f2tf32(a.y), f2tf32(b.y));
    d[2] = make_float2(f2tf32(a.z), f2tf32(b.z));
    d[3] = make_float2(f2tf32(a.w), f2tf32(b.w));
}

// =================================================================
// Tensor GEMM with cp.async 2-stage pipeline.
//   C[m,n] = sum_k A[m,k]*W[n,k]; A,W pre-rounded+permuted.
//   CTA tile 128x128, BK=32, 256 threads = 8 warps (2m x 4n).
//   Inner loop: LDS.64 + MMA only.
// MODE 0: write [B,H,L,Hd] per-z (z0:Q scale+round+permute,
//         z1:K round+permute, z2:V round natural)
// MODE 1: write row-major [M,1024] raw fp32 (final output)
// =================================================================
#define GPAD 40
#define GBUF (128*GPAD)                   // 5120 floats per operand
#define GT_SMEM_BYTES (4*GBUF*4)          // 2 stages x (A+B) = 81920 B

template<int MODE>
__global__ __launch_bounds__(256, 2)
void gemm_mma(const float* __restrict__ Abase, const float* __restrict__ Wbase,
              float* __restrict__ C0, float* __restrict__ C1, float* __restrict__ C2)
{
    extern __shared__ float sm[];
    const uint32_t smb = smem_u32(sm);

    const int z = blockIdx.z;
    const float* A = Abase + (size_t)z * ((size_t)MROWS * DMODEL);
    const float* W = Wbase + (size_t)z * ((size_t)DMODEL * DMODEL);
    float* C = (z == 0) ? C0 : (z == 1) ? C1 : C2;

    const int tid  = threadIdx.x;
    const int wid  = tid >> 5;
    const int lane = tid & 31;
    const int g    = lane >> 2;
    const int tig  = lane & 3;
    const int wm   = wid & 1;
    const int wn   = wid >> 1;
    const int m0 = blockIdx.y * 128;
    const int n0 = blockIdx.x * 128;

    // cp.async mapping: row lr (0..127), 4 x 16B chunks at qq = (tid&1)*4 + j
    const int lr = tid >> 1;
    const int qh = (tid & 1) * 4;
    const float* Asrc = A + (size_t)(m0 + lr) * DMODEL + qh * 4;
    const float* Wsrc = W + (size_t)(n0 + lr) * DMODEL + qh * 4;
    const uint32_t aDstBase = smb + lr * (GPAD*4) + qh * 16;

    float acc[4][4][4];
#pragma unroll
    for (int i = 0; i < 4; i++)
#pragma unroll
        for (int j = 0; j < 4; j++)
#pragma unroll
            for (int q = 0; q < 4; q++) acc[i][j][q] = 0.f;

    // prologue: stage 0 copies
    {
        const float* as = Asrc;
        const float* ws = Wsrc;
#pragma unroll
        for (int j = 0; j < 4; j++) {
            cp16(aDstBase + j*16, as + j*4);
            cp16(aDstBase + GBUF*4 + j*16, ws + j*4);
        }
        cp_commit();
    }

    for (int c = 0; c < 32; c++) {
        const int st = c & 1;
        cp_wait0();
        __syncthreads();
        if (c + 1 < 32) {
            const float* as = Asrc + (c+1)*32;
            const float* ws = Wsrc + (c+1)*32;
            const uint32_t ad = aDstBase + (st^1) * (2*GBUF*4);
#pragma unroll
            for (int j = 0; j < 4; j++) {
                cp16(ad + j*16, as + j*4);
                cp16(ad + GBUF*4 + j*16, ws + j*4);
            }
            cp_commit();
        }
        const float* Ab = sm + st * (2*GBUF);
        const float* Bb = Ab + GBUF;
#pragma unroll
        for (int ks = 0; ks < 4; ks++) {
            const int kb = ks * 8;
            float2 af[4][2];
#pragma unroll
            for (int mt = 0; mt < 4; mt++) {
                int row = wm*64 + mt*16 + g;
                af[mt][0] = *(const float2*)&Ab[ row      *GPAD + kb + 2*tig];
                af[mt][1] = *(const float2*)&Ab[(row + 8) *GPAD + kb + 2*tig];
            }
#pragma unroll
            for (int nt = 0; nt < 4; nt++) {
                int n = wn*32 + nt*8 + g;
                float2 bf = *(const float2*)&Bb[n*GPAD + kb + 2*tig];
                uint32_t b0 = __float_as_uint(bf.x);
                uint32_t b1 = __float_as_uint(bf.y);
#pragma unroll
                for (int mt = 0; mt < 4; mt++) {
                    uint32_t a4[4] = {
                        __float_as_uint(af[mt][0].x), __float_as_uint(af[mt][1].x),
                        __float_as_uint(af[mt][0].y), __float_as_uint(af[mt][1].y) };
                    mma_tf32(acc[mt][nt], a4, b0, b1);
                }
            }
        }
    }

    // epilogue
    const float sc = (MODE == 0 && z == 0) ? 0.125f : 1.0f;
    const int w0 = 2*tig;
    const int p0 = (w0   < 4) ? 2*w0     : 2*w0 - 7;
    const int p1 = (w0+1 < 4) ? 2*(w0+1) : 2*(w0+1) - 7;
#pragma unroll
    for (int mt = 0; mt < 4; mt++) {
#pragma unroll
        for (int nt = 0; nt < 4; nt++) {
            int m = m0 + wm*64 + mt*16 + g;
            int n = n0 + wn*32 + nt*8 + 2*tig;
#pragma unroll
            for (int half = 0; half < 2; half++) {
                int mm = m + half*8;
                float vx = acc[mt][nt][half*2];
                float vy = acc[mt][nt][half*2+1];
                if (MODE == 0) {
                    int b = mm >> 11;
                    int l = mm & (SEQ - 1);
                    int h = n >> 6;
                    int d = n & (HDIM - 1);
                    size_t base = ((size_t)((b*NHEAD + h)*SEQ) + l) * HDIM;
                    if (z == 2) {
                        // V: rounded, natural layout
                        *(float2*)&C[base + d] = make_float2(f2tf32(vx), f2tf32(vy));
                    } else {
                        // Q/K: rounded (+scale for Q), permuted within 8-group
                        int dg = d & ~7;
                        C[base + dg + p0] = f2tf32(vx * sc);
                        C[base + dg + p1] = f2tf32(vy * sc);
                    }
                } else {
                    *(float2*)&C[(size_t)mm * DMODEL + n] = make_float2(vx, vy);
                }
            }
        }
    }
}

// =================================================================
// Flash attention v4: cp.async-staged, zero conversions in loop.
//   128 queries/block, 4 warps x 32q, 64-key chunks, K/V double-
//   buffered via cp.async; Q staged once via cp.async.
//   g_Q scaled+rounded+permuted, g_K rounded+permuted, g_V rounded
//   natural. Writes g_O rounded+permuted for gemm<1>.
// =================================================================
#define QPAD 72
#define KPAD 72
#define VPAD 68
#define FA_Q (128*QPAD)                    // 9216 floats
#define FA_K (64*KPAD)                     // 4608
#define FA_V (64*VPAD)                     // 4352
#define FA_SMEM_FLOATS (FA_Q + 2*FA_K + 2*FA_V)   // 27136
#define FA_SMEM_BYTES (FA_SMEM_FLOATS*4)          // 108544

__global__ __launch_bounds__(128, 2)
void flash_mma(const int* __restrict__ mask,
               const float* __restrict__ Qg,
               const float* __restrict__ Kg,
               const float* __restrict__ Vg,
               float* __restrict__ Og)
{
    extern __shared__ float sm[];
    const uint32_t smb = smem_u32(sm);
    float* Qs = sm;                                 // [128][72] permuted
    __shared__ int msk[64];

    const int tid  = threadIdx.x;
    const int lane = tid & 31;
    const int wid  = tid >> 5;
    const int g    = lane >> 2;
    const int tig  = lane & 3;
    const int qb   = wid * 32;

    const int bh = blockIdx.y;
    const int b  = bh / NHEAD;
    const int h  = bh % NHEAD;
    const int q0 = blockIdx.x * 128;

    const size_t bhBase = (size_t)(b*NHEAD + h) * SEQ * HDIM;

    // K/V cp.async mapping: row lr2 (0..63), 8 x 16B at jj = (tid&1)*8 + j
    const int lr2 = tid >> 1;
    const int jbase = (tid & 1) * 8;
    const float* Ksrc = Kg + bhBase + (size_t)lr2 * HDIM + jbase * 4;
    const float* Vsrc = Vg + bhBase + (size_t)lr2 * HDIM + jbase * 4;
    const uint32_t kDst = smb + FA_Q*4 + lr2 * (KPAD*4) + jbase * 16;
    const uint32_t vDst = smb + (FA_Q + 2*FA_K)*4 + lr2 * (VPAD*4) + jbase * 16;

    // ---- prologue: Q tile (16 chunks) + K/V stage 0 (+ mask reg) ----
    {
        const float* qsrc = Qg + bhBase + (size_t)(q0 + tid) * HDIM;
        uint32_t qdst = smb + tid * (QPAD*4);
#pragma unroll
        for (int j = 0; j < 16; j++) cp16(qdst + j*16, qsrc + j*4);
#pragma unroll
        for (int j = 0; j < 8; j++) {
            cp16(kDst + j*16, Ksrc + j*4);
            cp16(vDst + j*16, Vsrc + j*4);
        }
        cp_commit();
    }
    int mreg = (tid < 64) ? mask[b*SEQ + tid] : 0;

    float o[2][8][4];
#pragma unroll
    for (int mt = 0; mt < 2; mt++)
#pragma unroll
        for (int nt = 0; nt < 8; nt++)
#pragma unroll
            for (int q = 0; q < 4; q++) o[mt][nt][q] = 0.f;
    float mrow[2][2], lrow[2][2];
#pragma unroll
    for (int mt = 0; mt < 2; mt++) { mrow[mt][0]=mrow[mt][1]=-1e30f; lrow[mt][0]=lrow[mt][1]=0.f; }

    for (int c = 0; c < 32; c++) {
        const int st = c & 1;
        cp_wait0();
        __syncthreads();
        if (c + 1 < 32) {
            const float* ks = Ksrc + (size_t)(c+1) * 64 * HDIM;
            const float* vs = Vsrc + (size_t)(c+1) * 64 * HDIM;
            const uint32_t kd = kDst + (st^1) * (FA_K*4);
            const uint32_t vd = vDst + (st^1) * (FA_V*4);
#pragma unroll
            for (int j = 0; j < 8; j++) {
                cp16(kd + j*16, ks + j*4);
                cp16(vd + j*16, vs + j*4);
            }
            cp_commit();
        }
        if (tid < 64) msk[tid] = mreg;
        if (c + 1 < 32 && tid < 64) mreg = mask[b*SEQ + (c+1)*64 + tid];
        __syncthreads();

        const float* Ks = sm + FA_Q + st * FA_K;
        const float* Vs = sm + FA_Q + 2*FA_K + st * FA_V;

        // ---- S = Q K^T : 2 m-tiles x 8 n-tiles (Q pre-scaled) ----
        float s[2][8][4];
#pragma unroll
        for (int mt = 0; mt < 2; mt++)
#pragma unroll
            for (int nt = 0; nt < 8; nt++)
#pragma unroll
                for (int q = 0; q < 4; q++) s[mt][nt][q] = 0.f;

#pragma unroll
        for (int ks = 0; ks < 8; ks++) {
            const int kb = ks * 8;
            float2 aa[2][2];
#pragma unroll
            for (int mt = 0; mt < 2; mt++) {
                int row = qb + mt*16 + g;
                aa[mt][0] = *(const float2*)&Qs[ row      *QPAD + kb + 2*tig];
                aa[mt][1] = *(const float2*)&Qs[(row + 8) *QPAD + kb + 2*tig];
            }
#pragma unroll
            for (int nt = 0; nt < 8; nt++) {
                int n = nt*8 + g;
                float2 bb = *(const float2*)&Ks[n*KPAD + kb + 2*tig];
                uint32_t b0 = __float_as_uint(bb.x);
                uint32_t b1 = __float_as_uint(bb.y);
#pragma unroll
                for (int mt = 0; mt < 2; mt++) {
                    uint32_t a4[4] = {
                        __float_as_uint(aa[mt][0].x), __float_as_uint(aa[mt][1].x),
                        __float_as_uint(aa[mt][0].y), __float_as_uint(aa[mt][1].y) };
                    mma_tf32(s[mt][nt], a4, b0, b1);
                }
            }
        }

        // ---- mask + online softmax ----
#pragma unroll
        for (int mt = 0; mt < 2; mt++) {
#pragma unroll
            for (int nt = 0; nt < 8; nt++) {
                int j0 = nt*8 + 2*tig;
                bool k0 = (msk[j0]   != 0);
                bool k1 = (msk[j0+1] != 0);
                s[mt][nt][0] = k0 ? s[mt][nt][0] : NEG_INF_V;
                s[mt][nt][1] = k1 ? s[mt][nt][1] : NEG_INF_V;
                s[mt][nt][2] = k0 ? s[mt][nt][2] : NEG_INF_V;
                s[mt][nt][3] = k1 ? s[mt][nt][3] : NEG_INF_V;
            }
            float rm0 = -1e30f, rm1 = -1e30f;
#pragma unroll
            for (int nt = 0; nt < 8; nt++) {
                rm0 = fmaxf(rm0, fmaxf(s[mt][nt][0], s[mt][nt][1]));
                rm1 = fmaxf(rm1, fmaxf(s[mt][nt][2], s[mt][nt][3]));
            }
            rm0 = fmaxf(rm0, __shfl_xor_sync(0xffffffffu, rm0, 1));
            rm0 = fmaxf(rm0, __shfl_xor_sync(0xffffffffu, rm0, 2));
            rm1 = fmaxf(rm1, __shfl_xor_sync(0xffffffffu, rm1, 1));
            rm1 = fmaxf(rm1, __shfl_xor_sync(0xffffffffu, rm1, 2));

            float mn0 = fmaxf(mrow[mt][0], rm0);
            float mn1 = fmaxf(mrow[mt][1], rm1);
            float fac0 = __expf(mrow[mt][0] - mn0);
            float fac1 = __expf(mrow[mt][1] - mn1);
            float rs0 = 0.f, rs1 = 0.f;
#pragma unroll
            for (int nt = 0; nt < 8; nt++) {
                s[mt][nt][0] = __expf(s[mt][nt][0] - mn0);
                s[mt][nt][1] = __expf(s[mt][nt][1] - mn0);
                s[mt][nt][2] = __expf(s[mt][nt][2] - mn1);
                s[mt][nt][3] = __expf(s[mt][nt][3] - mn1);
                rs0 += s[mt][nt][0] + s[mt][nt][1];
                rs1 += s[mt][nt][2] + s[mt][nt][3];
            }
            rs0 += __shfl_xor_sync(0xffffffffu, rs0, 1);
            rs0 += __shfl_xor_sync(0xffffffffu, rs0, 2);
            rs1 += __shfl_xor_sync(0xffffffffu, rs1, 1);
            rs1 += __shfl_xor_sync(0xffffffffu, rs1, 2);
            lrow[mt][0] = lrow[mt][0]*fac0 + rs0;
            lrow[mt][1] = lrow[mt][1]*fac1 + rs1;
            mrow[mt][0] = mn0;
            mrow[mt][1] = mn1;
#pragma unroll
            for (int nt = 0; nt < 8; nt++) {
                o[mt][nt][0] *= fac0; o[mt][nt][1] *= fac0;
                o[mt][nt][2] *= fac1; o[mt][nt][3] *= fac1;
            }
            // P -> tf32 in registers (needed: fresh from exp)
#pragma unroll
            for (int nt = 0; nt < 8; nt++) {
                s[mt][nt][0] = f2tf32(s[mt][nt][0]);
                s[mt][nt][1] = f2tf32(s[mt][nt][1]);
                s[mt][nt][2] = f2tf32(s[mt][nt][2]);
                s[mt][nt][3] = f2tf32(s[mt][nt][3]);
            }
        }

        // ---- O += P V (register A-fragment via key permutation) ----
#pragma unroll
        for (int ks = 0; ks < 8; ks++) {
            const int kb = ks * 8;
#pragma unroll
            for (int nt = 0; nt < 8; nt++) {
                int n = nt*8 + g;
                uint32_t b0 = __float_as_uint(Vs[(kb + 2*tig    )*VPAD + n]);
                uint32_t b1 = __float_as_uint(Vs[(kb + 2*tig + 1)*VPAD + n]);
#pragma unroll
                for (int mt = 0; mt < 2; mt++) {
                    uint32_t a4[4] = {
                        __float_as_uint(s[mt][ks][0]), __float_as_uint(s[mt][ks][2]),
                        __float_as_uint(s[mt][ks][1]), __float_as_uint(s[mt][ks][3]) };
                    mma_tf32(o[mt][nt], a4, b0, b1);
                }
            }
        }
    }

    // ---- epilogue: normalize, round, permute -> g_O [B,L,D] ----
    const int w0 = 2*tig;
    const int p0 = (w0   < 4) ? 2*w0     : 2*w0 - 7;
    const int p1 = (w0+1 < 4) ? 2*(w0+1) : 2*(w0+1) - 7;
#pragma unroll
    for (int mt = 0; mt < 2; mt++) {
        float inv0 = 1.f / lrow[mt][0];
        float inv1 = 1.f / lrow[mt][1];
        int qg0 = q0 + qb + mt*16 + g;
        int qg1 = qg0 + 8;
#pragma unroll
        for (int nt = 0; nt < 8; nt++) {
            int dg = h*HDIM + nt*8;
            float* r0 = &Og[(size_t)(b*SEQ + qg0)*DMODEL + dg];
            float* r1 = &Og[(size_t)(b*SEQ + qg1)*DMODEL + dg];
            r0[p0] = f2tf32(o[mt][nt][0]*inv0);
            r0[p1] = f2tf32(o[mt][nt][1]*inv0);
            r1[p0] = f2tf32(o[mt][nt][2]*inv1);
            r1[p1] = f2tf32(o[mt][nt][3]*inv1);
        }
    }
}

// =================================================================
// Host launcher
// =================================================================
extern "C" void kernel_launch(void* const* d_in, const int* in_sizes, int n_in,
                              void* d_out, int out_size)
{
    const float* q    = (const float*)d_in[0];
    const float* k    = (const float*)d_in[1];
    const float* v    = (const float*)d_in[2];
    const int*   am   = (const int*)  d_in[3];
    const float* Wq   = (const float*)d_in[4];
    const float* Wk   = (const float*)d_in[5];
    const float* Wv   = (const float*)d_in[6];
    const float* Wo   = (const float*)d_in[7];
    float* out = (float*)d_out;

    float *gA, *gW, *gQ, *gK, *gV, *gO;
    cudaGetSymbolAddress((void**)&gA, g_A);
    cudaGetSymbolAddress((void**)&gW, g_W);
    cudaGetSymbolAddress((void**)&gQ, g_Q);
    cudaGetSymbolAddress((void**)&gK, g_K);
    cudaGetSymbolAddress((void**)&gV, g_V);
    cudaGetSymbolAddress((void**)&gO, g_O);

    cudaFuncSetAttribute(gemm_mma<0>, cudaFuncAttributeMaxDynamicSharedMemorySize, GT_SMEM_BYTES);
    cudaFuncSetAttribute(gemm_mma<1>, cudaFuncAttributeMaxDynamicSharedMemorySize, GT_SMEM_BYTES);
    cudaFuncSetAttribute(flash_mma,   cudaFuncAttributeMaxDynamicSharedMemorySize, FA_SMEM_BYTES);

    // pre-pass: round + permute A inputs (q,k,v) and weights
    {
        int gpmA = MROWS*DMODEL/8;     // 524288
        dim3 pa((gpmA + 255)/256, 1, 3);
        prep_permute<<<pa, 256>>>(q, k, v, q, gA, gpmA);
        int gpmW = DMODEL*DMODEL/8;    // 131072
        dim3 pw((gpmW + 255)/256, 1, 4);
        prep_permute<<<pw, 256>>>(Wq, Wk, Wv, Wo, gW, gpmW);
    }

    // fused QKV projections
    dim3 gGrid(DMODEL/128, MROWS/128, 3);  // (8, 32, 3)
    gemm_mma<0><<<gGrid, 256, GT_SMEM_BYTES>>>(gA, gW, gQ, gK, gV);

    dim3 aGrid(SEQ/128, BATCH*NHEAD);      // (16, 32)
    flash_mma<<<aGrid, 128, FA_SMEM_BYTES>>>(am, gQ, gK, gV, gO);

    dim3 oGrid(DMODEL/128, MROWS/128, 1);  // (8, 32)
    gemm_mma<1><<<oGrid, 256, GT_SMEM_BYTES>>>(gO, gW + 3u*DMODEL*DMODEL,
                                               out, out, out);
}

// round 8
// speedup vs baseline: 4.7818x; 1.0578x over previous
#include <cuda_runtime.h>
#include <cstdint>

// Problem constants
#define BATCH 2
#define SEQ   2048
#define DMODEL 1024
#define NHEAD 16
#define HDIM  64
#define MROWS (BATCH*SEQ)          // 4096
#define NEG_INF_V (-1.0e9f)

// ---------------- scratch (no allocation allowed) ----------------
__device__ float g_A[3u*MROWS*DMODEL];        // rounded+permuted q,k,v
__device__ float g_W[4u*DMODEL*DMODEL];       // rounded+permuted Wq,Wk,Wv,Wo
__device__ float g_Q[BATCH*NHEAD*SEQ*HDIM];   // [B,H,L,Hd] scaled+rounded+permuted
__device__ float g_K[BATCH*NHEAD*SEQ*HDIM];   // [B,H,L,Hd] rounded+permuted
__device__ float g_V[BATCH*NHEAD*SEQ*HDIM];   // [B,H,L,Hd] rounded, natural
__device__ float g_O[BATCH*SEQ*DMODEL];       // [B,L,D] rounded+permuted

// ---------------- helpers ----------------
__device__ __forceinline__ float f2tf32(float f) {
    uint32_t r;
    asm("cvt.rna.tf32.f32 %0, %1;" : "=r"(r) : "f"(f));
    return __uint_as_float(r);
}
__device__ __forceinline__ void mma_tf32(float c[4], const uint32_t a[4],
                                         uint32_t b0, uint32_t b1) {
    asm volatile(
        "mma.sync.aligned.m16n8k8.row.col.f32.tf32.tf32.f32 "
        "{%0,%1,%2,%3},{%4,%5,%6,%7},{%8,%9},{%0,%1,%2,%3};"
        : "+f"(c[0]), "+f"(c[1]), "+f"(c[2]), "+f"(c[3])
        : "r"(a[0]), "r"(a[1]), "r"(a[2]), "r"(a[3]), "r"(b0), "r"(b1));
}
__device__ __forceinline__ uint32_t smem_u32(const void* p) {
    uint32_t a;
    asm("{ .reg .u64 t; cvta.to.shared.u64 t, %1; cvt.u32.u64 %0, t; }" : "=r"(a) : "l"(p));
    return a;
}
__device__ __forceinline__ void cp16(uint32_t dst, const void* src) {
    asm volatile("cp.async.cg.shared.global [%0], [%1], 16;" :: "r"(dst), "l"(src) : "memory");
}
__device__ __forceinline__ void cp_commit() {
    asm volatile("cp.async.commit_group;" ::: "memory");
}
__device__ __forceinline__ void cp_wait0() {
    asm volatile("cp.async.wait_group 0;" ::: "memory");
}

// Column permutation within each 8-col group: [c0,c4,c1,c5,c2,c6,c3,c7].
// Fragment cols (kb+tig, kb+tig+4) then sit adjacent -> LDS.64.

// =================================================================
// Pre-pass: RNA-round to tf32 and permute 8-col groups.
// =================================================================
__global__ __launch_bounds__(256)
void prep_permute(const float* __restrict__ s0, const float* __restrict__ s1,
                  const float* __restrict__ s2, const float* __restrict__ s3,
                  float* __restrict__ dst, int groupsPerMat)
{
    const float* s = (blockIdx.z == 0) ? s0 : (blockIdx.z == 1) ? s1 :
                     (blockIdx.z == 2) ? s2 : s3;
    int i = blockIdx.x * blockDim.x + threadIdx.x;
    if (i >= groupsPerMat) return;
    const float4* sp = (const float4*)(s + (size_t)i * 8);
    float4 a = sp[0], b = sp[1];
    float2* d = (float2*)(dst + ((size_t)blockIdx.z * groupsPerMat + i) * 8);
    d[0] = make_float2(f2tf32(a.x), f2tf32(b.x));
    d[1] = make_float2(f2tf32(a.y), f2tf32(b.y));
    d[2] = make_float2(f2tf32(a.z), f2tf32(b.z));
    d[3] = make_float2(f2tf32(a.w), f2tf32(b.w));
}

// =================================================================
// Tensor GEMM with cp.async 2-stage pipeline (unchanged from R7).
// =================================================================
#define GPAD 40
#define GBUF (128*GPAD)                   // 5120 floats per operand
#define GT_SMEM_BYTES (4*GBUF*4)          // 2 stages x (A+B) = 81920 B

template<int MODE>
__global__ __launch_bounds__(256, 2)
void gemm_mma(const float* __restrict__ Abase, const float* __restrict__ Wbase,
              float* __restrict__ C0, float* __restrict__ C1, float* __restrict__ C2)
{
    extern __shared__ float sm[];
    const uint32_t smb = smem_u32(sm);

    const int z = blockIdx.z;
    const float* A = Abase + (size_t)z * ((size_t)MROWS * DMODEL);
    const float* W = Wbase + (size_t)z * ((size_t)DMODEL * DMODEL);
    float* C = (z == 0) ? C0 : (z == 1) ? C1 : C2;

    const int tid  = threadIdx.x;
    const int wid  = tid >> 5;
    const int lane = tid & 31;
    const int g    = lane >> 2;
    const int tig  = lane & 3;
    const int wm   = wid & 1;
    const int wn   = wid >> 1;
    const int m0 = blockIdx.y * 128;
    const int n0 = blockIdx.x * 128;

    const int lr = tid >> 1;
    const int qh = (tid & 1) * 4;
    const float* Asrc = A + (size_t)(m0 + lr) * DMODEL + qh * 4;
    const float* Wsrc = W + (size_t)(n0 + lr) * DMODEL + qh * 4;
    const uint32_t aDstBase = smb + lr * (GPAD*4) + qh * 16;

    float acc[4][4][4];
#pragma unroll
    for (int i = 0; i < 4; i++)
#pragma unroll
        for (int j = 0; j < 4; j++)
#pragma unroll
            for (int q = 0; q < 4; q++) acc[i][j][q] = 0.f;

    {
#pragma unroll
        for (int j = 0; j < 4; j++) {
            cp16(aDstBase + j*16, Asrc + j*4);
            cp16(aDstBase + GBUF*4 + j*16, Wsrc + j*4);
        }
        cp_commit();
    }

    for (int c = 0; c < 32; c++) {
        const int st = c & 1;
        cp_wait0();
        __syncthreads();
        if (c + 1 < 32) {
            const float* as = Asrc + (c+1)*32;
            const float* ws = Wsrc + (c+1)*32;
            const uint32_t ad = aDstBase + (st^1) * (2*GBUF*4);
#pragma unroll
            for (int j = 0; j < 4; j++) {
                cp16(ad + j*16, as + j*4);
                cp16(ad + GBUF*4 + j*16, ws + j*4);
            }
            cp_commit();
        }
        const float* Ab = sm + st * (2*GBUF);
        const float* Bb = Ab + GBUF;
#pragma unroll
        for (int ks = 0; ks < 4; ks++) {
            const int kb = ks * 8;
            float2 af[4][2];
#pragma unroll
            for (int mt = 0; mt < 4; mt++) {
                int row = wm*64 + mt*16 + g;
                af[mt][0] = *(const float2*)&Ab[ row      *GPAD + kb + 2*tig];
                af[mt][1] = *(const float2*)&Ab[(row + 8) *GPAD + kb + 2*tig];
            }
#pragma unroll
            for (int nt = 0; nt < 4; nt++) {
                int n = wn*32 + nt*8 + g;
                float2 bf = *(const float2*)&Bb[n*GPAD + kb + 2*tig];
                uint32_t b0 = __float_as_uint(bf.x);
                uint32_t b1 = __float_as_uint(bf.y);
#pragma unroll
                for (int mt = 0; mt < 4; mt++) {
                    uint32_t a4[4] = {
                        __float_as_uint(af[mt][0].x), __float_as_uint(af[mt][1].x),
                        __float_as_uint(af[mt][0].y), __float_as_uint(af[mt][1].y) };
                    mma_tf32(acc[mt][nt], a4, b0, b1);
                }
            }
        }
    }

    const float sc = (MODE == 0 && z == 0) ? 0.125f : 1.0f;
    const int w0 = 2*tig;
    const int p0 = (w0   < 4) ? 2*w0     : 2*w0 - 7;
    const int p1 = (w0+1 < 4) ? 2*(w0+1) : 2*(w0+1) - 7;
#pragma unroll
    for (int mt = 0; mt < 4; mt++) {
#pragma unroll
        for (int nt = 0; nt < 4; nt++) {
            int m = m0 + wm*64 + mt*16 + g;
            int n = n0 + wn*32 + nt*8 + 2*tig;
#pragma unroll
            for (int half = 0; half < 2; half++) {
                int mm = m + half*8;
                float vx = acc[mt][nt][half*2];
                float vy = acc[mt][nt][half*2+1];
                if (MODE == 0) {
                    int b = mm >> 11;
                    int l = mm & (SEQ - 1);
                    int h = n >> 6;
                    int d = n & (HDIM - 1);
                    size_t base = ((size_t)((b*NHEAD + h)*SEQ) + l) * HDIM;
                    if (z == 2) {
                        *(float2*)&C[base + d] = make_float2(f2tf32(vx), f2tf32(vy));
                    } else {
                        int dg = d & ~7;
                        C[base + dg + p0] = f2tf32(vx * sc);
                        C[base + dg + p1] = f2tf32(vy * sc);
                    }
                } else {
                    *(float2*)&C[(size_t)mm * DMODEL + n] = make_float2(vx, vy);
                }
            }
        }
    }
}

// =================================================================
// Flash attention v5: 256 threads = 8 warps x 16 queries (128 q/blk),
// cp.async double-buffered K/V, zero in-loop conversions.
// Same arithmetic per query row as v4 -> bit-identical result.
// =================================================================
#define QPAD 72
#define KPAD 72
#define VPAD 68
#define FA_Q (128*QPAD)                    // 9216 floats
#define FA_K (64*KPAD)                     // 4608
#define FA_V (64*VPAD)                     // 4352
#define FA_SMEM_FLOATS (FA_Q + 2*FA_K + 2*FA_V)   // 27136
#define FA_SMEM_BYTES (FA_SMEM_FLOATS*4)          // 108544

__global__ __launch_bounds__(256, 2)
void flash_mma(const int* __restrict__ mask,
               const float* __restrict__ Qg,
               const float* __restrict__ Kg,
               const float* __restrict__ Vg,
               float* __restrict__ Og)
{
    extern __shared__ float sm[];
    const uint32_t smb = smem_u32(sm);
    float* Qs = sm;                                 // [128][72] permuted
    __shared__ int msk[64];

    const int tid  = threadIdx.x;
    const int lane = tid & 31;
    const int wid  = tid >> 5;          // 0..7
    const int g    = lane >> 2;
    const int tig  = lane & 3;
    const int qb   = wid * 16;          // warp's query base (1 m-tile)

    const int bh = blockIdx.y;
    const int b  = bh / NHEAD;
    const int h  = bh % NHEAD;
    const int q0 = blockIdx.x * 128;

    const size_t bhBase = (size_t)(b*NHEAD + h) * SEQ * HDIM;

    // K/V cp.async mapping: row lr2 (0..63), 4 x 16B at (tid&3)*4 + j
    const int lr2 = tid >> 2;
    const int jb  = (tid & 3) * 4;
    const float* Ksrc = Kg + bhBase + (size_t)lr2 * HDIM + jb * 4;
    const float* Vsrc = Vg + bhBase + (size_t)lr2 * HDIM + jb * 4;
    const uint32_t kDst = smb + FA_Q*4 + lr2 * (KPAD*4) + jb * 16;
    const uint32_t vDst = smb + (FA_Q + 2*FA_K)*4 + lr2 * (VPAD*4) + jb * 16;

    // ---- prologue: Q tile + K/V stage 0 (+ mask reg) ----
    {
        // Q: 128 rows x 16 chunks; 256 threads -> 8 chunks each
        const int qr = tid >> 1;
        const int qh = (tid & 1) * 8;
        const float* qsrc = Qg + bhBase + (size_t)(q0 + qr) * HDIM + qh * 4;
        uint32_t qdst = smb + qr * (QPAD*4) + qh * 16;
#pragma unroll
        for (int j = 0; j < 8; j++) cp16(qdst + j*16, qsrc + j*4);
#pragma unroll
        for (int j = 0; j < 4; j++) {
            cp16(kDst + j*16, Ksrc + j*4);
            cp16(vDst + j*16, Vsrc + j*4);
        }
        cp_commit();
    }
    int mreg = (tid < 64) ? mask[b*SEQ + tid] : 0;

    float o[8][4];
#pragma unroll
    for (int nt = 0; nt < 8; nt++)
#pragma unroll
        for (int q = 0; q < 4; q++) o[nt][q] = 0.f;
    float mrow0 = -1e30f, mrow1 = -1e30f, lrow0 = 0.f, lrow1 = 0.f;

    for (int c = 0; c < 32; c++) {
        const int st = c & 1;
        cp_wait0();
        __syncthreads();
        if (c + 1 < 32) {
            const float* ks = Ksrc + (size_t)(c+1) * 64 * HDIM;
            const float* vs = Vsrc + (size_t)(c+1) * 64 * HDIM;
            const uint32_t kd = kDst + (st^1) * (FA_K*4);
            const uint32_t vd = vDst + (st^1) * (FA_V*4);
#pragma unroll
            for (int j = 0; j < 4; j++) {
                cp16(kd + j*16, ks + j*4);
                cp16(vd + j*16, vs + j*4);
            }
            cp_commit();
        }
        if (tid < 64) msk[tid] = mreg;
        if (c + 1 < 32 && tid < 64) mreg = mask[b*SEQ + (c+1)*64 + tid];
        __syncthreads();

        const float* Ks = sm + FA_Q + st * FA_K;
        const float* Vs = sm + FA_Q + 2*FA_K + st * FA_V;

        // ---- S = Q K^T : 1 m-tile x 8 n-tiles (Q pre-scaled) ----
        float s[8][4];
#pragma unroll
        for (int nt = 0; nt < 8; nt++)
#pragma unroll
            for (int q = 0; q < 4; q++) s[nt][q] = 0.f;

#pragma unroll
        for (int ks = 0; ks < 8; ks++) {
            const int kb = ks * 8;
            float2 a0 = *(const float2*)&Qs[(qb + g    )*QPAD + kb + 2*tig];
            float2 a1 = *(const float2*)&Qs[(qb + g + 8)*QPAD + kb + 2*tig];
            uint32_t a4[4] = {
                __float_as_uint(a0.x), __float_as_uint(a1.x),
                __float_as_uint(a0.y), __float_as_uint(a1.y) };
#pragma unroll
            for (int nt = 0; nt < 8; nt++) {
                int n = nt*8 + g;
                float2 bb = *(const float2*)&Ks[n*KPAD + kb + 2*tig];
                mma_tf32(s[nt], a4, __float_as_uint(bb.x), __float_as_uint(bb.y));
            }
        }

        // ---- mask + online softmax ----
#pragma unroll
        for (int nt = 0; nt < 8; nt++) {
            int j0 = nt*8 + 2*tig;
            bool k0 = (msk[j0]   != 0);
            bool k1 = (msk[j0+1] != 0);
            s[nt][0] = k0 ? s[nt][0] : NEG_INF_V;
            s[nt][1] = k1 ? s[nt][1] : NEG_INF_V;
            s[nt][2] = k0 ? s[nt][2] : NEG_INF_V;
            s[nt][3] = k1 ? s[nt][3] : NEG_INF_V;
        }
        float rm0 = -1e30f, rm1 = -1e30f;
#pragma unroll
        for (int nt = 0; nt < 8; nt++) {
            rm0 = fmaxf(rm0, fmaxf(s[nt][0], s[nt][1]));
            rm1 = fmaxf(rm1, fmaxf(s[nt][2], s[nt][3]));
        }
        rm0 = fmaxf(rm0, __shfl_xor_sync(0xffffffffu, rm0, 1));
        rm0 = fmaxf(rm0, __shfl_xor_sync(0xffffffffu, rm0, 2));
        rm1 = fmaxf(rm1, __shfl_xor_sync(0xffffffffu, rm1, 1));
        rm1 = fmaxf(rm1, __shfl_xor_sync(0xffffffffu, rm1, 2));

        float mn0 = fmaxf(mrow0, rm0);
        float mn1 = fmaxf(mrow1, rm1);
        float fac0 = __expf(mrow0 - mn0);
        float fac1 = __expf(mrow1 - mn1);
        float rs0 = 0.f, rs1 = 0.f;
#pragma unroll
        for (int nt = 0; nt < 8; nt++) {
            s[nt][0] = __expf(s[nt][0] - mn0);
            s[nt][1] = __expf(s[nt][1] - mn0);
            s[nt][2] = __expf(s[nt][2] - mn1);
            s[nt][3] = __expf(s[nt][3] - mn1);
            rs0 += s[nt][0] + s[nt][1];
            rs1 += s[nt][2] + s[nt][3];
        }
        rs0 += __shfl_xor_sync(0xffffffffu, rs0, 1);
        rs0 += __shfl_xor_sync(0xffffffffu, rs0, 2);
        rs1 += __shfl_xor_sync(0xffffffffu, rs1, 1);
        rs1 += __shfl_xor_sync(0xffffffffu, rs1, 2);
        lrow0 = lrow0*fac0 + rs0;
        lrow1 = lrow1*fac1 + rs1;
        mrow0 = mn0;
        mrow1 = mn1;
#pragma unroll
        for (int nt = 0; nt < 8; nt++) {
            o[nt][0] *= fac0; o[nt][1] *= fac0;
            o[nt][2] *= fac1; o[nt][3] *= fac1;
        }
        // P -> tf32 in registers
#pragma unroll
        for (int nt = 0; nt < 8; nt++) {
            s[nt][0] = f2tf32(s[nt][0]);
            s[nt][1] = f2tf32(s[nt][1]);
            s[nt][2] = f2tf32(s[nt][2]);
            s[nt][3] = f2tf32(s[nt][3]);
        }

        // ---- O += P V (register A-fragment via key permutation) ----
#pragma unroll
        for (int ks = 0; ks < 8; ks++) {
            const int kb = ks * 8;
            uint32_t a4[4] = {
                __float_as_uint(s[ks][0]), __float_as_uint(s[ks][2]),
                __float_as_uint(s[ks][1]), __float_as_uint(s[ks][3]) };
#pragma unroll
            for (int nt = 0; nt < 8; nt++) {
                int n = nt*8 + g;
                uint32_t b0 = __float_as_uint(Vs[(kb + 2*tig    )*VPAD + n]);
                uint32_t b1 = __float_as_uint(Vs[(kb + 2*tig + 1)*VPAD + n]);
                mma_tf32(o[nt], a4, b0, b1);
            }
        }
    }

    // ---- epilogue: normalize, round, permute -> g_O [B,L,D] ----
    const int w0 = 2*tig;
    const int p0 = (w0   < 4) ? 2*w0     : 2*w0 - 7;
    const int p1 = (w0+1 < 4) ? 2*(w0+1) : 2*(w0+1) - 7;
    float inv0 = 1.f / lrow0;
    float inv1 = 1.f / lrow1;
    int qg0 = q0 + qb + g;
    int qg1 = qg0 + 8;
#pragma unroll
    for (int nt = 0; nt < 8; nt++) {
        int dg = h*HDIM + nt*8;
        float* r0 = &Og[(size_t)(b*SEQ + qg0)*DMODEL + dg];
        float* r1 = &Og[(size_t)(b*SEQ + qg1)*DMODEL + dg];
        r0[p0] = f2tf32(o[nt][0]*inv0);
        r0[p1] = f2tf32(o[nt][1]*inv0);
        r1[p0] = f2tf32(o[nt][2]*inv1);
        r1[p1] = f2tf32(o[nt][3]*inv1);
    }
}

// =================================================================
// Host launcher
// =================================================================
extern "C" void kernel_launch(void* const* d_in, const int* in_sizes, int n_in,
                              void* d_out, int out_size)
{
    const float* q    = (const float*)d_in[0];
    const float* k    = (const float*)d_in[1];
    const float* v    = (const float*)d_in[2];
    const int*   am   = (const int*)  d_in[3];
    const float* Wq   = (const float*)d_in[4];
    const float* Wk   = (const float*)d_in[5];
    const float* Wv   = (const float*)d_in[6];
    const float* Wo   = (const float*)d_in[7];
    float* out = (float*)d_out;

    float *gA, *gW, *gQ, *gK, *gV, *gO;
    cudaGetSymbolAddress((void**)&gA, g_A);
    cudaGetSymbolAddress((void**)&gW, g_W);
    cudaGetSymbolAddress((void**)&gQ, g_Q);
    cudaGetSymbolAddress((void**)&gK, g_K);
    cudaGetSymbolAddress((void**)&gV, g_V);
    cudaGetSymbolAddress((void**)&gO, g_O);

    cudaFuncSetAttribute(gemm_mma<0>, cudaFuncAttributeMaxDynamicSharedMemorySize, GT_SMEM_BYTES);
    cudaFuncSetAttribute(gemm_mma<1>, cudaFuncAttributeMaxDynamicSharedMemorySize, GT_SMEM_BYTES);
    cudaFuncSetAttribute(flash_mma,   cudaFuncAttributeMaxDynamicSharedMemorySize, FA_SMEM_BYTES);

    // pre-pass: round + permute A inputs (q,k,v) and weights
    {
        int gpmA = MROWS*DMODEL/8;     // 524288
        dim3 pa((gpmA + 255)/256, 1, 3);
        prep_permute<<<pa, 256>>>(q, k, v, q, gA, gpmA);
        int gpmW = DMODEL*DMODEL/8;    // 131072
        dim3 pw((gpmW + 255)/256, 1, 4);
        prep_permute<<<pw, 256>>>(Wq, Wk, Wv, Wo, gW, gpmW);
    }

    // fused QKV projections
    dim3 gGrid(DMODEL/128, MROWS/128, 3);  // (8, 32, 3)
    gemm_mma<0><<<gGrid, 256, GT_SMEM_BYTES>>>(gA, gW, gQ, gK, gV);

    dim3 aGrid(SEQ/128, BATCH*NHEAD);      // (16, 32)
    flash_mma<<<aGrid, 256, FA_SMEM_BYTES>>>(am, gQ, gK, gV, gO);

    dim3 oGrid(DMODEL/128, MROWS/128, 1);  // (8, 32)
    gemm_mma<1><<<oGrid, 256, GT_SMEM_BYTES>>>(gO, gW + 3u*DMODEL*DMODEL,
                                               out, out, out);
}

// round 9
// speedup vs baseline: 9.1576x; 1.9151x over previous
#include <cuda_runtime.h>
#include <cuda_fp16.h>
#include <cstdint>

// Problem constants
#define BATCH 2
#define SEQ   2048
#define DMODEL 1024
#define NHEAD 16
#define HDIM  64
#define MROWS (BATCH*SEQ)          // 4096
#define NEG_INF_V (-1.0e9f)

// ---------------- scratch (no allocation allowed) ----------------
__device__ __half g_A[3u*MROWS*DMODEL];        // fp16 pair-permuted q,k,v
__device__ __half g_W[4u*DMODEL*DMODEL];       // fp16 pair-permuted Wq,Wk,Wv,Wo
__device__ __half g_Q[BATCH*NHEAD*SEQ*HDIM];   // [B,H,L,Hd] scaled, d-permuted
__device__ __half g_K[BATCH*NHEAD*SEQ*HDIM];   // [B,H,L,Hd] d-permuted
__device__ __half g_Vt[BATCH*NHEAD*HDIM*SEQ];  // [B,H,Hd,L] key-permuted
__device__ __half g_O[BATCH*SEQ*DMODEL];       // [B,L,D] d-permuted

// ---------------- helpers ----------------
__device__ __forceinline__ uint32_t pack2(float a, float b) {
    __half2 h = __floats2half2_rn(a, b);
    return *(uint32_t*)&h;
}
__device__ __forceinline__ void mma_f16(float c[4], uint32_t a0, uint32_t a1,
                                        uint32_t a2, uint32_t a3,
                                        uint32_t b0, uint32_t b1) {
    asm volatile(
        "mma.sync.aligned.m16n8k16.row.col.f32.f16.f16.f32 "
        "{%0,%1,%2,%3},{%4,%5,%6,%7},{%8,%9},{%0,%1,%2,%3};"
        : "+f"(c[0]), "+f"(c[1]), "+f"(c[2]), "+f"(c[3])
        : "r"(a0), "r"(a1), "r"(a2), "r"(a3), "r"(b0), "r"(b1));
}
__device__ __forceinline__ uint32_t smem_u32(const void* p) {
    uint32_t a;
    asm("{ .reg .u64 t; cvta.to.shared.u64 t, %1; cvt.u32.u64 %0, t; }" : "=r"(a) : "l"(p));
    return a;
}
__device__ __forceinline__ void cp16(uint32_t dst, const void* src) {
    asm volatile("cp.async.cg.shared.global [%0], [%1], 16;" :: "r"(dst), "l"(src) : "memory");
}
__device__ __forceinline__ void cp_commit() {
    asm volatile("cp.async.commit_group;" ::: "memory");
}
__device__ __forceinline__ void cp_wait0() {
    asm volatile("cp.async.wait_group 0;" ::: "memory");
}
// pair permutation within 16-elt group: pairs stored [0,4,1,5,2,6,3,7]
// even element d (within group) -> position 2*slot, slot = (p<4 ? 2p : 2p-7), p=d/2
__device__ __forceinline__ int permpos_even(int d16) {
    int p = d16 >> 1;
    int slot = (p < 4) ? 2*p : 2*p - 7;
    return slot * 2;
}

// =================================================================
// Pre-pass: RN-round fp32 -> fp16 and pair-permute 16-elt groups.
// Each thread handles one group of 16 floats -> 32 bytes out.
// =================================================================
__global__ __launch_bounds__(256)
void prep_f16(const float* __restrict__ s0, const float* __restrict__ s1,
              const float* __restrict__ s2, const float* __restrict__ s3,
              __half* __restrict__ dst, int groupsPerMat)
{
    const float* s = (blockIdx.z == 0) ? s0 : (blockIdx.z == 1) ? s1 :
                     (blockIdx.z == 2) ? s2 : s3;
    int i = blockIdx.x * blockDim.x + threadIdx.x;
    if (i >= groupsPerMat) return;
    const float4* sp = (const float4*)(s + (size_t)i * 16);
    float4 a = sp[0], b = sp[1], c = sp[2], d = sp[3];
    // pairs P0..P7; output order P0,P4,P1,P5,P2,P6,P3,P7
    uint32_t P0 = pack2(a.x, a.y), P1 = pack2(a.z, a.w);
    uint32_t P2 = pack2(b.x, b.y), P3 = pack2(b.z, b.w);
    uint32_t P4 = pack2(c.x, c.y), P5 = pack2(c.z, c.w);
    uint32_t P6 = pack2(d.x, d.y), P7 = pack2(d.z, d.w);
    uint4* o = (uint4*)(dst + ((size_t)blockIdx.z * groupsPerMat + i) * 16);
    o[0] = make_uint4(P0, P4, P1, P5);
    o[1] = make_uint4(P2, P6, P3, P7);
}

// =================================================================
// fp16 tensor GEMM, cp.async 2-stage pipeline.
//   C[m,n] = sum_k A[m,k]*W[n,k]; A,W fp16 pair-permuted.
//   CTA tile 128x128, BK=64 halves, 256 threads = 8 warps (2m x 4n).
//   smem stride 80 halves (160B) -> all fragment LDS.64 conflict-free.
// MODE 0: z0 -> g_Q (x0.125, d-permuted), z1 -> g_K (d-permuted),
//         z2 -> g_Vt (transposed [B,H,Hd,L], key-permuted)
// MODE 1: raw fp32 [M,1024] to out
// =================================================================
#define GSTR 80                         // halves per smem row
#define GBUFH (128*GSTR)                // 10240 halves per operand buffer
#define GT_SMEM_BYTES (4*GBUFH*2)       // 81920 B

template<int MODE>
__global__ __launch_bounds__(256, 2)
void gemm_mma(const __half* __restrict__ Abase, const __half* __restrict__ Wbase,
              __half* __restrict__ H0, __half* __restrict__ H1, __half* __restrict__ H2,
              float* __restrict__ Cf)
{
    extern __shared__ __half smh[];
    const uint32_t smb = smem_u32(smh);

    const int z = blockIdx.z;
    const __half* A = Abase + (size_t)z * ((size_t)MROWS * DMODEL);
    const __half* W = Wbase + (size_t)z * ((size_t)DMODEL * DMODEL);

    const int tid  = threadIdx.x;
    const int wid  = tid >> 5;
    const int lane = tid & 31;
    const int g    = lane >> 2;
    const int tig  = lane & 3;
    const int wm   = wid & 1;
    const int wn   = wid >> 1;
    const int m0 = blockIdx.y * 128;
    const int n0 = blockIdx.x * 128;

    // cp.async: row lr (0..127), 8 x 16B chunks; 2 threads/row, 4 chunks each
    const int lr = tid >> 1;
    const int cb = (tid & 1) * 4;
    const __half* Asrc = A + (size_t)(m0 + lr) * DMODEL + cb * 8;
    const __half* Wsrc = W + (size_t)(n0 + lr) * DMODEL + cb * 8;
    const uint32_t aDst = smb + lr * (GSTR*2) + cb * 16;

    float acc[4][4][4];
#pragma unroll
    for (int i = 0; i < 4; i++)
#pragma unroll
        for (int j = 0; j < 4; j++)
#pragma unroll
            for (int q = 0; q < 4; q++) acc[i][j][q] = 0.f;

    {
#pragma unroll
        for (int j = 0; j < 4; j++) {
            cp16(aDst + j*16, Asrc + j*8);
            cp16(aDst + GBUFH*2 + j*16, Wsrc + j*8);
        }
        cp_commit();
    }

    for (int c = 0; c < 16; c++) {
        const int st = c & 1;
        cp_wait0();
        __syncthreads();
        if (c + 1 < 16) {
            const __half* as = Asrc + (c+1)*64;
            const __half* ws = Wsrc + (c+1)*64;
            const uint32_t ad = aDst + (st^1) * (2*GBUFH*2);
#pragma unroll
            for (int j = 0; j < 4; j++) {
                cp16(ad + j*16, as + j*8);
                cp16(ad + GBUFH*2 + j*16, ws + j*8);
            }
            cp_commit();
        }
        const __half* Ab = smh + st * (2*GBUFH);
        const __half* Bb = Ab + GBUFH;
#pragma unroll
        for (int kg = 0; kg < 4; kg++) {
            const int kb = kg * 16 + 4*tig;
            uint2 af0[4], af1[4];
#pragma unroll
            for (int mt = 0; mt < 4; mt++) {
                int row = wm*64 + mt*16 + g;
                af0[mt] = *(const uint2*)&Ab[ row      *GSTR + kb];
                af1[mt] = *(const uint2*)&Ab[(row + 8) *GSTR + kb];
            }
#pragma unroll
            for (int nt = 0; nt < 4; nt++) {
                int n = wn*32 + nt*8 + g;
                uint2 bf = *(const uint2*)&Bb[n*GSTR + kb];
#pragma unroll
                for (int mt = 0; mt < 4; mt++)
                    mma_f16(acc[mt][nt], af0[mt].x, af1[mt].x, af0[mt].y, af1[mt].y,
                            bf.x, bf.y);
            }
        }
    }

    const float sc = (MODE == 0 && z == 0) ? 0.125f : 1.0f;
#pragma unroll
    for (int mt = 0; mt < 4; mt++) {
#pragma unroll
        for (int nt = 0; nt < 4; nt++) {
            int m = m0 + wm*64 + mt*16 + g;
            int n = n0 + wn*32 + nt*8 + 2*tig;
#pragma unroll
            for (int half_ = 0; half_ < 2; half_++) {
                int mm = m + half_*8;
                float vx = acc[mt][nt][half_*2];
                float vy = acc[mt][nt][half_*2+1];
                if (MODE == 0) {
                    int b = mm >> 11;
                    int l = mm & (SEQ - 1);
                    int h = n >> 6;
                    int d = n & (HDIM - 1);
                    if (z == 2) {
                        // Vt [B,H,Hd,L], key(l) pair-permuted
                        int lperm = (l & ~15) | (permpos_even(l & 15) + (l & 1));
                        // l from fragment is even-based? l = m-row: any parity handled:
                        // recompute generally:
                        lperm = (l & ~15);
                        { int x = l & 15; int p = x >> 1, w = x & 1;
                          int slot = (p < 4) ? 2*p : 2*p - 7;
                          lperm += slot*2 + w; }
                        size_t rbase = ((size_t)((b*NHEAD + h)*HDIM)) * SEQ;
                        H2[rbase + (size_t)d     * SEQ + lperm] = __float2half_rn(vx);
                        H2[rbase + (size_t)(d+1) * SEQ + lperm] = __float2half_rn(vy);
                    } else {
                        // Q/K [B,H,L,Hd], d pair-permuted (d even)
                        int pos = (d & ~15) + permpos_even(d & 15);
                        size_t base = ((size_t)((b*NHEAD + h)*SEQ) + l) * HDIM;
                        __half2 hv = __floats2half2_rn(vx*sc, vy*sc);
                        *(__half2*)&((z == 0 ? H0 : H1)[base + pos]) = hv;
                    }
                } else {
                    *(float2*)&Cf[(size_t)mm * DMODEL + n] = make_float2(vx, vy);
                }
            }
        }
    }
}

// =================================================================
// Flash attention v6 (fp16 m16n8k16): 256 thr = 8 warps x 16 q,
// 128 q/block, 64-key chunks, cp.async double-buffered K/Vt.
// S C-fragment feeds PV A-fragment directly (pack only, no perm).
// =================================================================
#define FQS 80
#define FA_Q (128*FQS)                 // 10240 halves
#define FA_K (64*FQS)                  // 5120
#define FA_V (64*FQS)                  // 5120
#define FA_SMEM_BYTES ((FA_Q + 2*FA_K + 2*FA_V)*2)   // 61440 B

__global__ __launch_bounds__(256, 2)
void flash_mma(const int* __restrict__ mask,
               const __half* __restrict__ Qg,
               const __half* __restrict__ Kg,
               const __half* __restrict__ Vtg,
               __half* __restrict__ Og)
{
    extern __shared__ __half smh[];
    const uint32_t smb = smem_u32(smh);
    const __half* Qs = smh;                         // [128][80]
    __shared__ int msk[64];

    const int tid  = threadIdx.x;
    const int lane = tid & 31;
    const int wid  = tid >> 5;
    const int g    = lane >> 2;
    const int tig  = lane & 3;
    const int qb   = wid * 16;

    const int bh = blockIdx.y;
    const int b  = bh / NHEAD;
    const int h  = bh % NHEAD;
    const int q0 = blockIdx.x * 128;

    const size_t bhBase = (size_t)(b*NHEAD + h) * SEQ * HDIM;
    const size_t vtBase = (size_t)((b*NHEAD + h)*HDIM) * SEQ;

    // K/Vt staging: 64 rows x 8 chunks; 4 threads/row, 2 chunks each
    const int lr2 = tid >> 2;
    const int cb2 = (tid & 3) * 2;
    const __half* Ksrc  = Kg  + bhBase + (size_t)lr2 * HDIM + cb2 * 8;
    const __half* Vtsrc = Vtg + vtBase + (size_t)lr2 * SEQ  + cb2 * 8;
    const uint32_t kDst = smb + FA_Q*2 + lr2 * (FQS*2) + cb2 * 16;
    const uint32_t vDst = smb + (FA_Q + 2*FA_K)*2 + lr2 * (FQS*2) + cb2 * 16;

    // prologue: Q (128 rows x 8 chunks; 2 thr/row, 4 chunks each) + K/V stage 0
    {
        const int qr = tid >> 1;
        const int qc = (tid & 1) * 4;
        const __half* qsrc = Qg + bhBase + (size_t)(q0 + qr) * HDIM + qc * 8;
        uint32_t qdst = smb + qr * (FQS*2) + qc * 16;
#pragma unroll
        for (int j = 0; j < 4; j++) cp16(qdst + j*16, qsrc + j*8);
#pragma unroll
        for (int j = 0; j < 2; j++) {
            cp16(kDst + j*16, Ksrc + j*8);
            cp16(vDst + j*16, Vtsrc + j*8);
        }
        cp_commit();
    }
    int mreg = (tid < 64) ? mask[b*SEQ + tid] : 0;

    float o[8][4];
#pragma unroll
    for (int nt = 0; nt < 8; nt++)
#pragma unroll
        for (int q = 0; q < 4; q++) o[nt][q] = 0.f;
    float mrow0 = -1e30f, mrow1 = -1e30f, lrow0 = 0.f, lrow1 = 0.f;

    for (int c = 0; c < 32; c++) {
        const int st = c & 1;
        cp_wait0();
        __syncthreads();
        if (c + 1 < 32) {
            const __half* ks = Ksrc + (size_t)(c+1) * 64 * HDIM;
            const __half* vs = Vtsrc + (size_t)(c+1) * 64;
            const uint32_t kd = kDst + (st^1) * (FA_K*2);
            const uint32_t vd = vDst + (st^1) * (FA_V*2);
#pragma unroll
            for (int j = 0; j < 2; j++) {
                cp16(kd + j*16, ks + j*8);
                cp16(vd + j*16, vs + j*8);
            }
            cp_commit();
        }
        if (tid < 64) msk[tid] = mreg;
        if (c + 1 < 32 && tid < 64) mreg = mask[b*SEQ + (c+1)*64 + tid];
        __syncthreads();

        const __half* Ks = smh + FA_Q + st * FA_K;
        const __half* Vs = smh + FA_Q + 2*FA_K + st * FA_V;

        // ---- S = Q K^T : 4 k16-groups x 8 n-tiles ----
        float s[8][4];
#pragma unroll
        for (int nt = 0; nt < 8; nt++)
#pragma unroll
            for (int q = 0; q < 4; q++) s[nt][q] = 0.f;

#pragma unroll
        for (int kg = 0; kg < 4; kg++) {
            const int kb = kg * 16 + 4*tig;
            uint2 qa0 = *(const uint2*)&Qs[(qb + g    )*FQS + kb];
            uint2 qa1 = *(const uint2*)&Qs[(qb + g + 8)*FQS + kb];
#pragma unroll
            for (int nt = 0; nt < 8; nt++) {
                uint2 kf = *(const uint2*)&Ks[(nt*8 + g)*FQS + kb];
                mma_f16(s[nt], qa0.x, qa1.x, qa0.y, qa1.y, kf.x, kf.y);
            }
        }

        // ---- mask + online softmax (scale pre-folded into Q) ----
#pragma unroll
        for (int nt = 0; nt < 8; nt++) {
            int j0 = nt*8 + 2*tig;
            bool k0 = (msk[j0]   != 0);
            bool k1 = (msk[j0+1] != 0);
            s[nt][0] = k0 ? s[nt][0] : NEG_INF_V;
            s[nt][1] = k1 ? s[nt][1] : NEG_INF_V;
            s[nt][2] = k0 ? s[nt][2] : NEG_INF_V;
            s[nt][3] = k1 ? s[nt][3] : NEG_INF_V;
        }
        float rm0 = -1e30f, rm1 = -1e30f;
#pragma unroll
        for (int nt = 0; nt < 8; nt++) {
            rm0 = fmaxf(rm0, fmaxf(s[nt][0], s[nt][1]));
            rm1 = fmaxf(rm1, fmaxf(s[nt][2], s[nt][3]));
        }
        rm0 = fmaxf(rm0, __shfl_xor_sync(0xffffffffu, rm0, 1));
        rm0 = fmaxf(rm0, __shfl_xor_sync(0xffffffffu, rm0, 2));
        rm1 = fmaxf(rm1, __shfl_xor_sync(0xffffffffu, rm1, 1));
        rm1 = fmaxf(rm1, __shfl_xor_sync(0xffffffffu, rm1, 2));

        float mn0 = fmaxf(mrow0, rm0);
        float mn1 = fmaxf(mrow1, rm1);
        float fac0 = __expf(mrow0 - mn0);
        float fac1 = __expf(mrow1 - mn1);
        float rs0 = 0.f, rs1 = 0.f;
#pragma unroll
        for (int nt = 0; nt < 8; nt++) {
            s[nt][0] = __expf(s[nt][0] - mn0);
            s[nt][1] = __expf(s[nt][1] - mn0);
            s[nt][2] = __expf(s[nt][2] - mn1);
            s[nt][3] = __expf(s[nt][3] - mn1);
            rs0 += s[nt][0] + s[nt][1];
            rs1 += s[nt][2] + s[nt][3];
        }
        rs0 += __shfl_xor_sync(0xffffffffu, rs0, 1);
        rs0 += __shfl_xor_sync(0xffffffffu, rs0, 2);
        rs1 += __shfl_xor_sync(0xffffffffu, rs1, 1);
        rs1 += __shfl_xor_sync(0xffffffffu, rs1, 2);
        lrow0 = lrow0*fac0 + rs0;
        lrow1 = lrow1*fac1 + rs1;
        mrow0 = mn0;
        mrow1 = mn1;
#pragma unroll
        for (int nt = 0; nt < 8; nt++) {
            o[nt][0] *= fac0; o[nt][1] *= fac0;
            o[nt][2] *= fac1; o[nt][3] *= fac1;
        }

        // ---- O += P V : A-fragment packed straight from S registers ----
#pragma unroll
        for (int kg = 0; kg < 4; kg++) {
            uint32_t a0 = pack2(s[2*kg  ][0], s[2*kg  ][1]);
            uint32_t a1 = pack2(s[2*kg  ][2], s[2*kg  ][3]);
            uint32_t a2 = pack2(s[2*kg+1][0], s[2*kg+1][1]);
            uint32_t a3 = pack2(s[2*kg+1][2], s[2*kg+1][3]);
            const int kb = kg * 16 + 4*tig;
#pragma unroll
            for (int nt = 0; nt < 8; nt++) {
                uint2 vf = *(const uint2*)&Vs[(nt*8 + g)*FQS + kb];
                mma_f16(o[nt], a0, a1, a2, a3, vf.x, vf.y);
            }
        }
    }

    // ---- epilogue: normalize, fp16 + d-permute -> g_O [B,L,D] ----
    float inv0 = 1.f / lrow0;
    float inv1 = 1.f / lrow1;
    int qg0 = q0 + qb + g;
    int qg1 = qg0 + 8;
#pragma unroll
    for (int nt = 0; nt < 8; nt++) {
        int d = nt*8 + 2*tig;
        int pos = h*HDIM + (d & ~15) + permpos_even(d & 15);
        *(__half2*)&Og[(size_t)(b*SEQ + qg0)*DMODEL + pos] =
            __floats2half2_rn(o[nt][0]*inv0, o[nt][1]*inv0);
        *(__half2*)&Og[(size_t)(b*SEQ + qg1)*DMODEL + pos] =
            __floats2half2_rn(o[nt][2]*inv1, o[nt][3]*inv1);
    }
}

// =================================================================
// Host launcher
// =================================================================
extern "C" void kernel_launch(void* const* d_in, const int* in_sizes, int n_in,
                              void* d_out, int out_size)
{
    const float* q    = (const float*)d_in[0];
    const float* k    = (const float*)d_in[1];
    const float* v    = (const float*)d_in[2];
    const int*   am   = (const int*)  d_in[3];
    const float* Wq   = (const float*)d_in[4];
    const float* Wk   = (const float*)d_in[5];
    const float* Wv   = (const float*)d_in[6];
    const float* Wo   = (const float*)d_in[7];
    float* out = (float*)d_out;

    __half *gA, *gW, *gQ, *gK, *gVt, *gO;
    cudaGetSymbolAddress((void**)&gA, g_A);
    cudaGetSymbolAddress((void**)&gW, g_W);
    cudaGetSymbolAddress((void**)&gQ, g_Q);
    cudaGetSymbolAddress((void**)&gK, g_K);
    cudaGetSymbolAddress((void**)&gVt, g_Vt);
    cudaGetSymbolAddress((void**)&gO, g_O);

    cudaFuncSetAttribute(gemm_mma<0>, cudaFuncAttributeMaxDynamicSharedMemorySize, GT_SMEM_BYTES);
    cudaFuncSetAttribute(gemm_mma<1>, cudaFuncAttributeMaxDynamicSharedMemorySize, GT_SMEM_BYTES);
    cudaFuncSetAttribute(flash_mma,   cudaFuncAttributeMaxDynamicSharedMemorySize, FA_SMEM_BYTES);

    // pre-pass: fp16 round + pair-permute inputs and weights
    {
        int gpmA = MROWS*DMODEL/16;    // 262144
        dim3 pa((gpmA + 255)/256, 1, 3);
        prep_f16<<<pa, 256>>>(q, k, v, q, gA, gpmA);
        int gpmW = DMODEL*DMODEL/16;   // 65536
        dim3 pw((gpmW + 255)/256, 1, 4);
        prep_f16<<<pw, 256>>>(Wq, Wk, Wv, Wo, gW, gpmW);
    }

    // fused QKV projections
    dim3 gGrid(DMODEL/128, MROWS/128, 3);  // (8, 32, 3)
    gemm_mma<0><<<gGrid, 256, GT_SMEM_BYTES>>>(gA, gW, gQ, gK, gVt, out);

    dim3 aGrid(SEQ/128, BATCH*NHEAD);      // (16, 32)
    flash_mma<<<aGrid, 256, FA_SMEM_BYTES>>>(am, gQ, gK, gVt, gO);

    dim3 oGrid(DMODEL/128, MROWS/128, 1);  // (8, 32)
    gemm_mma<1><<<oGrid, 256, GT_SMEM_BYTES>>>(gO, gW + 3u*DMODEL*DMODEL,
                                               gQ, gK, gVt, out);
}

// round 10
// speedup vs baseline: 9.6305x; 1.0516x over previous
#include <cuda_runtime.h>
#include <cuda_fp16.h>
#include <cstdint>

// Problem constants
#define BATCH 2
#define SEQ   2048
#define DMODEL 1024
#define NHEAD 16
#define HDIM  64
#define MROWS (BATCH*SEQ)          // 4096
#define NEG_INF_V (-1.0e9f)

// ---------------- scratch (no allocation allowed) ----------------
__device__ __half g_A[3u*MROWS*DMODEL];        // fp16 pair-permuted q,k,v
__device__ __half g_W[4u*DMODEL*DMODEL];       // fp16 pair-permuted Wq,Wk,Wv,Wo
__device__ __half g_Q[BATCH*NHEAD*SEQ*HDIM];   // [B,H,L,Hd] scaled, d-permuted
__device__ __half g_K[BATCH*NHEAD*SEQ*HDIM];   // [B,H,L,Hd] d-permuted
__device__ __half g_Vt[BATCH*NHEAD*HDIM*SEQ];  // [B,H,Hd,L] key-permuted
__device__ __half g_O[BATCH*SEQ*DMODEL];       // [B,L,D] d-permuted

// ---------------- helpers ----------------
__device__ __forceinline__ uint32_t pack2(float a, float b) {
    __half2 h = __floats2half2_rn(a, b);
    return *(uint32_t*)&h;
}
__device__ __forceinline__ void mma_f16(float c[4], uint32_t a0, uint32_t a1,
                                        uint32_t a2, uint32_t a3,
                                        uint32_t b0, uint32_t b1) {
    asm volatile(
        "mma.sync.aligned.m16n8k16.row.col.f32.f16.f16.f32 "
        "{%0,%1,%2,%3},{%4,%5,%6,%7},{%8,%9},{%0,%1,%2,%3};"
        : "+f"(c[0]), "+f"(c[1]), "+f"(c[2]), "+f"(c[3])
        : "r"(a0), "r"(a1), "r"(a2), "r"(a3), "r"(b0), "r"(b1));
}
__device__ __forceinline__ uint32_t smem_u32(const void* p) {
    uint32_t a;
    asm("{ .reg .u64 t; cvta.to.shared.u64 t, %1; cvt.u32.u64 %0, t; }" : "=r"(a) : "l"(p));
    return a;
}
__device__ __forceinline__ void cp16(uint32_t dst, const void* src) {
    asm volatile("cp.async.cg.shared.global [%0], [%1], 16;" :: "r"(dst), "l"(src) : "memory");
}
__device__ __forceinline__ void cp_commit() {
    asm volatile("cp.async.commit_group;" ::: "memory");
}
__device__ __forceinline__ void cp_wait0() {
    asm volatile("cp.async.wait_group 0;" ::: "memory");
}
__device__ __forceinline__ void cp_wait1() {
    asm volatile("cp.async.wait_group 1;" ::: "memory");
}
__device__ __forceinline__ void cp_wait2() {
    asm volatile("cp.async.wait_group 2;" ::: "memory");
}
// pair permutation within 16-elt group: pairs stored [0,4,1,5,2,6,3,7]
__device__ __forceinline__ int permpos_even(int d16) {
    int p = d16 >> 1;
    int slot = (p < 4) ? 2*p : 2*p - 7;
    return slot * 2;
}

// =================================================================
// Pre-pass: RN-round fp32 -> fp16 and pair-permute 16-elt groups.
// =================================================================
__global__ __launch_bounds__(256)
void prep_f16(const float* __restrict__ s0, const float* __restrict__ s1,
              const float* __restrict__ s2, const float* __restrict__ s3,
              __half* __restrict__ dst, int groupsPerMat)
{
    const float* s = (blockIdx.z == 0) ? s0 : (blockIdx.z == 1) ? s1 :
                     (blockIdx.z == 2) ? s2 : s3;
    int i = blockIdx.x * blockDim.x + threadIdx.x;
    if (i >= groupsPerMat) return;
    const float4* sp = (const float4*)(s + (size_t)i * 16);
    float4 a = sp[0], b = sp[1], c = sp[2], d = sp[3];
    uint32_t P0 = pack2(a.x, a.y), P1 = pack2(a.z, a.w);
    uint32_t P2 = pack2(b.x, b.y), P3 = pack2(b.z, b.w);
    uint32_t P4 = pack2(c.x, c.y), P5 = pack2(c.z, c.w);
    uint32_t P6 = pack2(d.x, d.y), P7 = pack2(d.z, d.w);
    uint4* o = (uint4*)(dst + ((size_t)blockIdx.z * groupsPerMat + i) * 16);
    o[0] = make_uint4(P0, P4, P1, P5);
    o[1] = make_uint4(P2, P6, P3, P7);
}

// =================================================================
// fp16 tensor GEMM (unchanged from R9).
// =================================================================
#define GSTR 80
#define GBUFH (128*GSTR)
#define GT_SMEM_BYTES (4*GBUFH*2)       // 81920 B

template<int MODE>
__global__ __launch_bounds__(256, 2)
void gemm_mma(const __half* __restrict__ Abase, const __half* __restrict__ Wbase,
              __half* __restrict__ H0, __half* __restrict__ H1, __half* __restrict__ H2,
              float* __restrict__ Cf)
{
    extern __shared__ __half smh[];
    const uint32_t smb = smem_u32(smh);

    const int z = blockIdx.z;
    const __half* A = Abase + (size_t)z * ((size_t)MROWS * DMODEL);
    const __half* W = Wbase + (size_t)z * ((size_t)DMODEL * DMODEL);

    const int tid  = threadIdx.x;
    const int wid  = tid >> 5;
    const int lane = tid & 31;
    const int g    = lane >> 2;
    const int tig  = lane & 3;
    const int wm   = wid & 1;
    const int wn   = wid >> 1;
    const int m0 = blockIdx.y * 128;
    const int n0 = blockIdx.x * 128;

    const int lr = tid >> 1;
    const int cb = (tid & 1) * 4;
    const __half* Asrc = A + (size_t)(m0 + lr) * DMODEL + cb * 8;
    const __half* Wsrc = W + (size_t)(n0 + lr) * DMODEL + cb * 8;
    const uint32_t aDst = smb + lr * (GSTR*2) + cb * 16;

    float acc[4][4][4];
#pragma unroll
    for (int i = 0; i < 4; i++)
#pragma unroll
        for (int j = 0; j < 4; j++)
#pragma unroll
            for (int q = 0; q < 4; q++) acc[i][j][q] = 0.f;

    {
#pragma unroll
        for (int j = 0; j < 4; j++) {
            cp16(aDst + j*16, Asrc + j*8);
            cp16(aDst + GBUFH*2 + j*16, Wsrc + j*8);
        }
        cp_commit();
    }

    for (int c = 0; c < 16; c++) {
        const int st = c & 1;
        cp_wait0();
        __syncthreads();
        if (c + 1 < 16) {
            const __half* as = Asrc + (c+1)*64;
            const __half* ws = Wsrc + (c+1)*64;
            const uint32_t ad = aDst + (st^1) * (2*GBUFH*2);
#pragma unroll
            for (int j = 0; j < 4; j++) {
                cp16(ad + j*16, as + j*8);
                cp16(ad + GBUFH*2 + j*16, ws + j*8);
            }
            cp_commit();
        }
        const __half* Ab = smh + st * (2*GBUFH);
        const __half* Bb = Ab + GBUFH;
#pragma unroll
        for (int kg = 0; kg < 4; kg++) {
            const int kb = kg * 16 + 4*tig;
            uint2 af0[4], af1[4];
#pragma unroll
            for (int mt = 0; mt < 4; mt++) {
                int row = wm*64 + mt*16 + g;
                af0[mt] = *(const uint2*)&Ab[ row      *GSTR + kb];
                af1[mt] = *(const uint2*)&Ab[(row + 8) *GSTR + kb];
            }
#pragma unroll
            for (int nt = 0; nt < 4; nt++) {
                int n = wn*32 + nt*8 + g;
                uint2 bf = *(const uint2*)&Bb[n*GSTR + kb];
#pragma unroll
                for (int mt = 0; mt < 4; mt++)
                    mma_f16(acc[mt][nt], af0[mt].x, af1[mt].x, af0[mt].y, af1[mt].y,
                            bf.x, bf.y);
            }
        }
    }

    const float sc = (MODE == 0 && z == 0) ? 0.125f : 1.0f;
#pragma unroll
    for (int mt = 0; mt < 4; mt++) {
#pragma unroll
        for (int nt = 0; nt < 4; nt++) {
            int m = m0 + wm*64 + mt*16 + g;
            int n = n0 + wn*32 + nt*8 + 2*tig;
#pragma unroll
            for (int half_ = 0; half_ < 2; half_++) {
                int mm = m + half_*8;
                float vx = acc[mt][nt][half_*2];
                float vy = acc[mt][nt][half_*2+1];
                if (MODE == 0) {
                    int b = mm >> 11;
                    int l = mm & (SEQ - 1);
                    int h = n >> 6;
                    int d = n & (HDIM - 1);
                    if (z == 2) {
                        int lperm = (l & ~15);
                        { int x = l & 15; int p = x >> 1, w = x & 1;
                          int slot = (p < 4) ? 2*p : 2*p - 7;
                          lperm += slot*2 + w; }
                        size_t rbase = ((size_t)((b*NHEAD + h)*HDIM)) * SEQ;
                        H2[rbase + (size_t)d     * SEQ + lperm] = __float2half_rn(vx);
                        H2[rbase + (size_t)(d+1) * SEQ + lperm] = __float2half_rn(vy);
                    } else {
                        int pos = (d & ~15) + permpos_even(d & 15);
                        size_t base = ((size_t)((b*NHEAD + h)*SEQ) + l) * HDIM;
                        __half2 hv = __floats2half2_rn(vx*sc, vy*sc);
                        *(__half2*)&((z == 0 ? H0 : H1)[base + pos]) = hv;
                    }
                } else {
                    *(float2*)&Cf[(size_t)mm * DMODEL + n] = make_float2(vx, vy);
                }
            }
        }
    }
}

// =================================================================
// Flash attention v7 (fp16): 256 thr = 8 warps x 16 q, 128 q/block,
// 64-key chunks. Changes vs v6:
//   - Q fragments held in registers (loaded once)
//   - 3-stage cp.async K/V pipeline (wait_group 1 + empty commits)
//   - allvalid mask skip via __syncthreads_and (replaces a barrier)
//   - stable-max skip (elide exp + o-rescale when max unchanged)
// =================================================================
#define FQS 80
#define FA_Q (128*FQS)                 // 10240 halves
#define FA_K (64*FQS)                  // 5120
#define FA_V (64*FQS)                  // 5120
#define FA_SMEM_BYTES ((FA_Q + 3*FA_K + 3*FA_V)*2)   // 81920 B

__global__ __launch_bounds__(256, 2)
void flash_mma(const int* __restrict__ mask,
               const __half* __restrict__ Qg,
               const __half* __restrict__ Kg,
               const __half* __restrict__ Vtg,
               __half* __restrict__ Og)
{
    extern __shared__ __half smh[];
    const uint32_t smb = smem_u32(smh);
    const __half* Qs = smh;                         // [128][80]
    __shared__ int msk[64];

    const int tid  = threadIdx.x;
    const int lane = tid & 31;
    const int wid  = tid >> 5;
    const int g    = lane >> 2;
    const int tig  = lane & 3;
    const int qb   = wid * 16;

    const int bh = blockIdx.y;
    const int b  = bh / NHEAD;
    const int h  = bh % NHEAD;
    const int q0 = blockIdx.x * 128;

    const size_t bhBase = (size_t)(b*NHEAD + h) * SEQ * HDIM;
    const size_t vtBase = (size_t)((b*NHEAD + h)*HDIM) * SEQ;

    // K/Vt staging: 64 rows x 8 chunks; 4 threads/row, 2 chunks each
    const int lr2 = tid >> 2;
    const int cb2 = (tid & 3) * 2;
    const __half* Ksrc  = Kg  + bhBase + (size_t)lr2 * HDIM + cb2 * 8;
    const __half* Vtsrc = Vtg + vtBase + (size_t)lr2 * SEQ  + cb2 * 8;
    const uint32_t kDst0 = smb + FA_Q*2 + lr2 * (FQS*2) + cb2 * 16;
    const uint32_t vDst0 = smb + (FA_Q + 3*FA_K)*2 + lr2 * (FQS*2) + cb2 * 16;

    // ---- prologue: G0 = Q, G1 = KV0, G2 = KV1 ----
    {
        const int qr = tid >> 1;
        const int qc = (tid & 1) * 4;
        const __half* qsrc = Qg + bhBase + (size_t)(q0 + qr) * HDIM + qc * 8;
        uint32_t qdst = smb + qr * (FQS*2) + qc * 16;
#pragma unroll
        for (int j = 0; j < 4; j++) cp16(qdst + j*16, qsrc + j*8);
        cp_commit();   // G0
#pragma unroll
        for (int j = 0; j < 2; j++) {
            cp16(kDst0 + j*16, Ksrc + j*8);
            cp16(vDst0 + j*16, Vtsrc + j*8);
        }
        cp_commit();   // G1
        const __half* ks1 = Ksrc + 64*HDIM;
        const __half* vs1 = Vtsrc + 64;
#pragma unroll
        for (int j = 0; j < 2; j++) {
            cp16(kDst0 + FA_K*2 + j*16, ks1 + j*8);
            cp16(vDst0 + FA_V*2 + j*16, vs1 + j*8);
        }
        cp_commit();   // G2
    }
    int mreg = (tid < 64) ? mask[b*SEQ + tid] : 0;

    // ---- Q fragments to registers (once) ----
    cp_wait2();              // G0 (Q) complete
    __syncthreads();
    uint2 qa0[4], qa1[4];
#pragma unroll
    for (int kg = 0; kg < 4; kg++) {
        qa0[kg] = *(const uint2*)&Qs[(qb + g    )*FQS + kg*16 + 4*tig];
        qa1[kg] = *(const uint2*)&Qs[(qb + g + 8)*FQS + kg*16 + 4*tig];
    }

    float o[8][4];
#pragma unroll
    for (int nt = 0; nt < 8; nt++)
#pragma unroll
        for (int q = 0; q < 4; q++) o[nt][q] = 0.f;
    float mrow0 = -1e30f, mrow1 = -1e30f, lrow0 = 0.f, lrow1 = 0.f;

    int st = 0;
    for (int c = 0; c < 32; c++) {
        cp_wait1();          // chunk c's KV group complete
        if (tid < 64) msk[tid] = mreg;
        int curv = (tid < 64) ? (mreg != 0) : 1;
        if (c + 1 < 32 && tid < 64) mreg = mask[b*SEQ + (c+1)*64 + tid];
        int allv = __syncthreads_and(curv);   // barrier + chunk mask AND

        // issue chunk c+2 (always commit a group to keep wait accounting)
        {
            int st2 = st + 2; if (st2 >= 3) st2 -= 3;
            if (c + 2 < 32) {
                const __half* ks = Ksrc + (size_t)(c+2) * 64 * HDIM;
                const __half* vs = Vtsrc + (size_t)(c+2) * 64;
                const uint32_t kd = kDst0 + st2 * (FA_K*2);
                const uint32_t vd = vDst0 + st2 * (FA_V*2);
#pragma unroll
                for (int j = 0; j < 2; j++) {
                    cp16(kd + j*16, ks + j*8);
                    cp16(vd + j*16, vs + j*8);
                }
            }
            cp_commit();
        }

        const __half* Ks = smh + FA_Q + st * FA_K;
        const __half* Vs = smh + FA_Q + 3*FA_K + st * FA_V;

        // ---- S = Q K^T (Q fragments in regs) ----
        float s[8][4];
#pragma unroll
        for (int nt = 0; nt < 8; nt++)
#pragma unroll
            for (int q = 0; q < 4; q++) s[nt][q] = 0.f;

#pragma unroll
        for (int kg = 0; kg < 4; kg++) {
            const int kb = kg * 16 + 4*tig;
#pragma unroll
            for (int nt = 0; nt < 8; nt++) {
                uint2 kf = *(const uint2*)&Ks[(nt*8 + g)*FQS + kb];
                mma_f16(s[nt], qa0[kg].x, qa1[kg].x, qa0[kg].y, qa1[kg].y,
                        kf.x, kf.y);
            }
        }

        // ---- mask (skipped when chunk fully valid) ----
        if (!allv) {
#pragma unroll
            for (int nt = 0; nt < 8; nt++) {
                int j0 = nt*8 + 2*tig;
                bool k0 = (msk[j0]   != 0);
                bool k1 = (msk[j0+1] != 0);
                s[nt][0] = k0 ? s[nt][0] : NEG_INF_V;
                s[nt][1] = k1 ? s[nt][1] : NEG_INF_V;
                s[nt][2] = k0 ? s[nt][2] : NEG_INF_V;
                s[nt][3] = k1 ? s[nt][3] : NEG_INF_V;
            }
        }

        // ---- online softmax with stable-max elision ----
        float rm0 = -1e30f, rm1 = -1e30f;
#pragma unroll
        for (int nt = 0; nt < 8; nt++) {
            rm0 = fmaxf(rm0, fmaxf(s[nt][0], s[nt][1]));
            rm1 = fmaxf(rm1, fmaxf(s[nt][2], s[nt][3]));
        }
        rm0 = fmaxf(rm0, __shfl_xor_sync(0xffffffffu, rm0, 1));
        rm0 = fmaxf(rm0, __shfl_xor_sync(0xffffffffu, rm0, 2));
        rm1 = fmaxf(rm1, __shfl_xor_sync(0xffffffffu, rm1, 1));
        rm1 = fmaxf(rm1, __shfl_xor_sync(0xffffffffu, rm1, 2));

        float mn0 = fmaxf(mrow0, rm0);
        float mn1 = fmaxf(mrow1, rm1);
        bool stable = __all_sync(0xffffffffu, (mn0 == mrow0) && (mn1 == mrow1));
        if (!stable) {
            float fac0 = __expf(mrow0 - mn0);
            float fac1 = __expf(mrow1 - mn1);
            lrow0 *= fac0;
            lrow1 *= fac1;
#pragma unroll
            for (int nt = 0; nt < 8; nt++) {
                o[nt][0] *= fac0; o[nt][1] *= fac0;
                o[nt][2] *= fac1; o[nt][3] *= fac1;
            }
            mrow0 = mn0;
            mrow1 = mn1;
        }

        float rs0 = 0.f, rs1 = 0.f;
#pragma unroll
        for (int nt = 0; nt < 8; nt++) {
            s[nt][0] = __expf(s[nt][0] - mrow0);
            s[nt][1] = __expf(s[nt][1] - mrow0);
            s[nt][2] = __expf(s[nt][2] - mrow1);
            s[nt][3] = __expf(s[nt][3] - mrow1);
            rs0 += s[nt][0] + s[nt][1];
            rs1 += s[nt][2] + s[nt][3];
        }
        rs0 += __shfl_xor_sync(0xffffffffu, rs0, 1);
        rs0 += __shfl_xor_sync(0xffffffffu, rs0, 2);
        rs1 += __shfl_xor_sync(0xffffffffu, rs1, 1);
        rs1 += __shfl_xor_sync(0xffffffffu, rs1, 2);
        lrow0 += rs0;
        lrow1 += rs1;

        // ---- O += P V : A-fragment packed straight from S registers ----
#pragma unroll
        for (int kg = 0; kg < 4; kg++) {
            uint32_t a0 = pack2(s[2*kg  ][0], s[2*kg  ][1]);
            uint32_t a1 = pack2(s[2*kg  ][2], s[2*kg  ][3]);
            uint32_t a2 = pack2(s[2*kg+1][0], s[2*kg+1][1]);
            uint32_t a3 = pack2(s[2*kg+1][2], s[2*kg+1][3]);
            const int kb = kg * 16 + 4*tig;
#pragma unroll
            for (int nt = 0; nt < 8; nt++) {
                uint2 vf = *(const uint2*)&Vs[(nt*8 + g)*FQS + kb];
                mma_f16(o[nt], a0, a1, a2, a3, vf.x, vf.y);
            }
        }

        st++; if (st == 3) st = 0;
    }

    // ---- epilogue: normalize, fp16 + d-permute -> g_O [B,L,D] ----
    float inv0 = 1.f / lrow0;
    float inv1 = 1.f / lrow1;
    int qg0 = q0 + qb + g;
    int qg1 = qg0 + 8;
#pragma unroll
    for (int nt = 0; nt < 8; nt++) {
        int d = nt*8 + 2*tig;
        int pos = h*HDIM + (d & ~15) + permpos_even(d & 15);
        *(__half2*)&Og[(size_t)(b*SEQ + qg0)*DMODEL + pos] =
            __floats2half2_rn(o[nt][0]*inv0, o[nt][1]*inv0);
        *(__half2*)&Og[(size_t)(b*SEQ + qg1)*DMODEL + pos] =
            __floats2half2_rn(o[nt][2]*inv1, o[nt][3]*inv1);
    }
}

// =================================================================
// Host launcher
// =================================================================
extern "C" void kernel_launch(void* const* d_in, const int* in_sizes, int n_in,
                              void* d_out, int out_size)
{
    const float* q    = (const float*)d_in[0];
    const float* k    = (const float*)d_in[1];
    const float* v    = (const float*)d_in[2];
    const int*   am   = (const int*)  d_in[3];
    const float* Wq   = (const float*)d_in[4];
    const float* Wk   = (const float*)d_in[5];
    const float* Wv   = (const float*)d_in[6];
    const float* Wo   = (const float*)d_in[7];
    float* out = (float*)d_out;

    __half *gA, *gW, *gQ, *gK, *gVt, *gO;
    cudaGetSymbolAddress((void**)&gA, g_A);
    cudaGetSymbolAddress((void**)&gW, g_W);
    cudaGetSymbolAddress((void**)&gQ, g_Q);
    cudaGetSymbolAddress((void**)&gK, g_K);
    cudaGetSymbolAddress((void**)&gVt, g_Vt);
    cudaGetSymbolAddress((void**)&gO, g_O);

    cudaFuncSetAttribute(gemm_mma<0>, cudaFuncAttributeMaxDynamicSharedMemorySize, GT_SMEM_BYTES);
    cudaFuncSetAttribute(gemm_mma<1>, cudaFuncAttributeMaxDynamicSharedMemorySize, GT_SMEM_BYTES);
    cudaFuncSetAttribute(flash_mma,   cudaFuncAttributeMaxDynamicSharedMemorySize, FA_SMEM_BYTES);

    // pre-pass: fp16 round + pair-permute inputs and weights
    {
        int gpmA = MROWS*DMODEL/16;    // 262144
        dim3 pa((gpmA + 255)/256, 1, 3);
        prep_f16<<<pa, 256>>>(q, k, v, q, gA, gpmA);
        int gpmW = DMODEL*DMODEL/16;   // 65536
        dim3 pw((gpmW + 255)/256, 1, 4);
        prep_f16<<<pw, 256>>>(Wq, Wk, Wv, Wo, gW, gpmW);
    }

    // fused QKV projections
    dim3 gGrid(DMODEL/128, MROWS/128, 3);  // (8, 32, 3)
    gemm_mma<0><<<gGrid, 256, GT_SMEM_BYTES>>>(gA, gW, gQ, gK, gVt, out);

    dim3 aGrid(SEQ/128, BATCH*NHEAD);      // (16, 32)
    flash_mma<<<aGrid, 256, FA_SMEM_BYTES>>>(am, gQ, gK, gVt, gO);

    dim3 oGrid(DMODEL/128, MROWS/128, 1);  // (8, 32)
    gemm_mma<1><<<oGrid, 256, GT_SMEM_BYTES>>>(gO, gW + 3u*DMODEL*DMODEL,
                                               gQ, gK, gVt, out);
}

// round 11
// speedup vs baseline: 9.6947x; 1.0067x over previous
#include <cuda_runtime.h>
#include <cuda_fp16.h>
#include <cstdint>

// Problem constants
#define BATCH 2
#define SEQ   2048
#define DMODEL 1024
#define NHEAD 16
#define HDIM  64
#define MROWS (BATCH*SEQ)          // 4096
#define NEG_INF_V (-1.0e9f)
#define ONES2 0x3C003C00u          // half2(1.0, 1.0)

// ---------------- scratch (no allocation allowed) ----------------
__device__ __half g_A[3u*MROWS*DMODEL];        // fp16 pair-permuted q,k,v
__device__ __half g_W[4u*DMODEL*DMODEL];       // fp16 pair-permuted Wq,Wk,Wv,Wo
__device__ __half g_Q[BATCH*NHEAD*SEQ*HDIM];   // [B,H,L,Hd] scaled, d-permuted
__device__ __half g_K[BATCH*NHEAD*SEQ*HDIM];   // [B,H,L,Hd] d-permuted
__device__ __half g_V[BATCH*NHEAD*SEQ*HDIM];   // [B,H,L,Hd] natural
__device__ __half g_O[BATCH*SEQ*DMODEL];       // [B,L,D] d-permuted

// ---------------- helpers ----------------
__device__ __forceinline__ uint32_t pack2(float a, float b) {
    __half2 h = __floats2half2_rn(a, b);
    return *(uint32_t*)&h;
}
__device__ __forceinline__ void mma_f16(float c[4], uint32_t a0, uint32_t a1,
                                        uint32_t a2, uint32_t a3,
                                        uint32_t b0, uint32_t b1) {
    asm volatile(
        "mma.sync.aligned.m16n8k16.row.col.f32.f16.f16.f32 "
        "{%0,%1,%2,%3},{%4,%5,%6,%7},{%8,%9},{%0,%1,%2,%3};"
        : "+f"(c[0]), "+f"(c[1]), "+f"(c[2]), "+f"(c[3])
        : "r"(a0), "r"(a1), "r"(a2), "r"(a3), "r"(b0), "r"(b1));
}
__device__ __forceinline__ void ldsm_x4_t(uint32_t& r0, uint32_t& r1,
                                          uint32_t& r2, uint32_t& r3, uint32_t addr) {
    asm volatile("ldmatrix.sync.aligned.m8n8.x4.trans.shared.b16 {%0,%1,%2,%3}, [%4];"
                 : "=r"(r0), "=r"(r1), "=r"(r2), "=r"(r3) : "r"(addr));
}
__device__ __forceinline__ uint32_t smem_u32(const void* p) {
    uint32_t a;
    asm("{ .reg .u64 t; cvta.to.shared.u64 t, %1; cvt.u32.u64 %0, t; }" : "=r"(a) : "l"(p));
    return a;
}
__device__ __forceinline__ void cp16(uint32_t dst, const void* src) {
    asm volatile("cp.async.cg.shared.global [%0], [%1], 16;" :: "r"(dst), "l"(src) : "memory");
}
__device__ __forceinline__ void cp_commit() {
    asm volatile("cp.async.commit_group;" ::: "memory");
}
__device__ __forceinline__ void cp_wait0() {
    asm volatile("cp.async.wait_group 0;" ::: "memory");
}
__device__ __forceinline__ void cp_wait1() {
    asm volatile("cp.async.wait_group 1;" ::: "memory");
}
__device__ __forceinline__ void cp_wait2() {
    asm volatile("cp.async.wait_group 2;" ::: "memory");
}
// pair permutation within 16-elt group: pairs stored [0,4,1,5,2,6,3,7]
__device__ __forceinline__ int permpos_even(int d16) {
    int p = d16 >> 1;
    int slot = (p < 4) ? 2*p : 2*p - 7;
    return slot * 2;
}

// =================================================================
// Pre-pass: RN-round fp32 -> fp16 and pair-permute 16-elt groups.
// =================================================================
__global__ __launch_bounds__(256)
void prep_f16(const float* __restrict__ s0, const float* __restrict__ s1,
              const float* __restrict__ s2, const float* __restrict__ s3,
              __half* __restrict__ dst, int groupsPerMat)
{
    const float* s = (blockIdx.z == 0) ? s0 : (blockIdx.z == 1) ? s1 :
                     (blockIdx.z == 2) ? s2 : s3;
    int i = blockIdx.x * blockDim.x + threadIdx.x;
    if (i >= groupsPerMat) return;
    const float4* sp = (const float4*)(s + (size_t)i * 16);
    float4 a = sp[0], b = sp[1], c = sp[2], d = sp[3];
    uint32_t P0 = pack2(a.x, a.y), P1 = pack2(a.z, a.w);
    uint32_t P2 = pack2(b.x, b.y), P3 = pack2(b.z, b.w);
    uint32_t P4 = pack2(c.x, c.y), P5 = pack2(c.z, c.w);
    uint32_t P6 = pack2(d.x, d.y), P7 = pack2(d.z, d.w);
    uint4* o = (uint4*)(dst + ((size_t)blockIdx.z * groupsPerMat + i) * 16);
    o[0] = make_uint4(P0, P4, P1, P5);
    o[1] = make_uint4(P2, P6, P3, P7);
}

// =================================================================
// fp16 tensor GEMM, cp.async 2-stage pipeline.
// MODE 0: z0 -> g_Q (x0.125, d-permuted), z1 -> g_K (d-permuted),
//         z2 -> g_V (NATURAL [B,H,L,Hd], coalesced half2 stores)
// MODE 1: raw fp32 [M,1024] to out
// =================================================================
#define GSTR 80
#define GBUFH (128*GSTR)
#define GT_SMEM_BYTES (4*GBUFH*2)       // 81920 B

template<int MODE>
__global__ __launch_bounds__(256, 2)
void gemm_mma(const __half* __restrict__ Abase, const __half* __restrict__ Wbase,
              __half* __restrict__ H0, __half* __restrict__ H1, __half* __restrict__ H2,
              float* __restrict__ Cf)
{
    extern __shared__ __half smh[];
    const uint32_t smb = smem_u32(smh);

    const int z = blockIdx.z;
    const __half* A = Abase + (size_t)z * ((size_t)MROWS * DMODEL);
    const __half* W = Wbase + (size_t)z * ((size_t)DMODEL * DMODEL);

    const int tid  = threadIdx.x;
    const int wid  = tid >> 5;
    const int lane = tid & 31;
    const int g    = lane >> 2;
    const int tig  = lane & 3;
    const int wm   = wid & 1;
    const int wn   = wid >> 1;
    const int m0 = blockIdx.y * 128;
    const int n0 = blockIdx.x * 128;

    const int lr = tid >> 1;
    const int cb = (tid & 1) * 4;
    const __half* Asrc = A + (size_t)(m0 + lr) * DMODEL + cb * 8;
    const __half* Wsrc = W + (size_t)(n0 + lr) * DMODEL + cb * 8;
    const uint32_t aDst = smb + lr * (GSTR*2) + cb * 16;

    float acc[4][4][4];
#pragma unroll
    for (int i = 0; i < 4; i++)
#pragma unroll
        for (int j = 0; j < 4; j++)
#pragma unroll
            for (int q = 0; q < 4; q++) acc[i][j][q] = 0.f;

    {
#pragma unroll
        for (int j = 0; j < 4; j++) {
            cp16(aDst + j*16, Asrc + j*8);
            cp16(aDst + GBUFH*2 + j*16, Wsrc + j*8);
        }
        cp_commit();
    }

    for (int c = 0; c < 16; c++) {
        const int st = c & 1;
        cp_wait0();
        __syncthreads();
        if (c + 1 < 16) {
            const __half* as = Asrc + (c+1)*64;
            const __half* ws = Wsrc + (c+1)*64;
            const uint32_t ad = aDst + (st^1) * (2*GBUFH*2);
#pragma unroll
            for (int j = 0; j < 4; j++) {
                cp16(ad + j*16, as + j*8);
                cp16(ad + GBUFH*2 + j*16, ws + j*8);
            }
            cp_commit();
        }
        const __half* Ab = smh + st * (2*GBUFH);
        const __half* Bb = Ab + GBUFH;
#pragma unroll
        for (int kg = 0; kg < 4; kg++) {
            const int kb = kg * 16 + 4*tig;
            uint2 af0[4], af1[4];
#pragma unroll
            for (int mt = 0; mt < 4; mt++) {
                int row = wm*64 + mt*16 + g;
                af0[mt] = *(const uint2*)&Ab[ row      *GSTR + kb];
                af1[mt] = *(const uint2*)&Ab[(row + 8) *GSTR + kb];
            }
#pragma unroll
            for (int nt = 0; nt < 4; nt++) {
                int n = wn*32 + nt*8 + g;
                uint2 bf = *(const uint2*)&Bb[n*GSTR + kb];
#pragma unroll
                for (int mt = 0; mt < 4; mt++)
                    mma_f16(acc[mt][nt], af0[mt].x, af1[mt].x, af0[mt].y, af1[mt].y,
                            bf.x, bf.y);
            }
        }
    }

    const float sc = (MODE == 0 && z == 0) ? 0.125f : 1.0f;
#pragma unroll
    for (int mt = 0; mt < 4; mt++) {
#pragma unroll
        for (int nt = 0; nt < 4; nt++) {
            int m = m0 + wm*64 + mt*16 + g;
            int n = n0 + wn*32 + nt*8 + 2*tig;
#pragma unroll
            for (int half_ = 0; half_ < 2; half_++) {
                int mm = m + half_*8;
                float vx = acc[mt][nt][half_*2];
                float vy = acc[mt][nt][half_*2+1];
                if (MODE == 0) {
                    int b = mm >> 11;
                    int l = mm & (SEQ - 1);
                    int h = n >> 6;
                    int d = n & (HDIM - 1);
                    size_t base = ((size_t)((b*NHEAD + h)*SEQ) + l) * HDIM;
                    if (z == 2) {
                        // V: natural layout, coalesced half2
                        *(__half2*)&H2[base + d] = __floats2half2_rn(vx, vy);
                    } else {
                        int pos = (d & ~15) + permpos_even(d & 15);
                        __half2 hv = __floats2half2_rn(vx*sc, vy*sc);
                        *(__half2*)&((z == 0 ? H0 : H1)[base + pos]) = hv;
                    }
                } else {
                    *(float2*)&Cf[(size_t)mm * DMODEL + n] = make_float2(vx, vy);
                }
            }
        }
    }
}

// =================================================================
// Flash attention v8 (fp16): 256 thr = 8 warps x 16 q, 128 q/block,
// 64-key chunks, 3-stage cp.async K/V pipeline. Changes vs v7:
//   - V natural [key][d], stride 72 halves; PV B via ldmatrix.x4.trans
//   - row-sum l computed by ones-column MMA (no shfl/FADD reduction)
//   - standard A-fragment order for PV (no key permutation)
// =================================================================
#define FQS 80                         // Q/K smem stride (halves)
#define VSTR 72                        // V smem stride (halves)
#define FA_Q (128*FQS)                 // 10240 halves
#define FA_K (64*FQS)                  // 5120
#define FA_V (64*VSTR)                 // 4608
#define FA_SMEM_BYTES ((FA_Q + 3*FA_K + 3*FA_V)*2)   // 78848 B

__global__ __launch_bounds__(256, 2)
void flash_mma(const int* __restrict__ mask,
               const __half* __restrict__ Qg,
               const __half* __restrict__ Kg,
               const __half* __restrict__ Vg,
               __half* __restrict__ Og)
{
    extern __shared__ __half smh[];
    const uint32_t smb = smem_u32(smh);
    const __half* Qs = smh;                         // [128][80]
    __shared__ int msk[64];

    const int tid  = threadIdx.x;
    const int lane = tid & 31;
    const int wid  = tid >> 5;
    const int g    = lane >> 2;
    const int tig  = lane & 3;
    const int qb   = wid * 16;

    const int bh = blockIdx.y;
    const int b  = bh / NHEAD;
    const int h  = bh % NHEAD;
    const int q0 = blockIdx.x * 128;

    const size_t bhBase = (size_t)(b*NHEAD + h) * SEQ * HDIM;

    // K/V staging: 64 rows x 8 x 16B chunks; 4 threads/row, 2 chunks each
    const int lr2 = tid >> 2;
    const int cb2 = (tid & 3) * 2;
    const __half* Ksrc = Kg + bhBase + (size_t)lr2 * HDIM + cb2 * 8;
    const __half* Vsrc = Vg + bhBase + (size_t)lr2 * HDIM + cb2 * 8;
    const uint32_t kDst0 = smb + FA_Q*2 + lr2 * (FQS*2) + cb2 * 16;
    const uint32_t vDst0 = smb + (FA_Q + 3*FA_K)*2 + lr2 * (VSTR*2) + cb2 * 16;

    // ldmatrix per-lane base: row = lane&15, col-group = (lane>>4)*8
    const int vlrow = lane & 15;
    const int vcol8 = (lane >> 4) * 8;

    // ---- prologue: G0 = Q, G1 = KV0, G2 = KV1 ----
    {
        const int qr = tid >> 1;
        const int qc = (tid & 1) * 4;
        const __half* qsrc = Qg + bhBase + (size_t)(q0 + qr) * HDIM + qc * 8;
        uint32_t qdst = smb + qr * (FQS*2) + qc * 16;
#pragma unroll
        for (int j = 0; j < 4; j++) cp16(qdst + j*16, qsrc + j*8);
        cp_commit();   // G0
#pragma unroll
        for (int j = 0; j < 2; j++) {
            cp16(kDst0 + j*16, Ksrc + j*8);
            cp16(vDst0 + j*16, Vsrc + j*8);
        }
        cp_commit();   // G1
        const __half* ks1 = Ksrc + 64*HDIM;
        const __half* vs1 = Vsrc + 64*HDIM;
#pragma unroll
        for (int j = 0; j < 2; j++) {
            cp16(kDst0 + FA_K*2 + j*16, ks1 + j*8);
            cp16(vDst0 + FA_V*2 + j*16, vs1 + j*8);
        }
        cp_commit();   // G2
    }
    int mreg = (tid < 64) ? mask[b*SEQ + tid] : 0;

    // ---- Q fragments to registers (once) ----
    cp_wait2();              // G0 (Q) complete
    __syncthreads();
    uint2 qa0[4], qa1[4];
#pragma unroll
    for (int kg = 0; kg < 4; kg++) {
        qa0[kg] = *(const uint2*)&Qs[(qb + g    )*FQS + kg*16 + 4*tig];
        qa1[kg] = *(const uint2*)&Qs[(qb + g + 8)*FQS + kg*16 + 4*tig];
    }

    float o[8][4];
#pragma unroll
    for (int nt = 0; nt < 8; nt++)
#pragma unroll
        for (int q = 0; q < 4; q++) o[nt][q] = 0.f;
    float ol[4] = {0.f, 0.f, 0.f, 0.f};     // row-sum accumulator (ones-MMA)
    float mrow0 = -1e30f, mrow1 = -1e30f;

    int st = 0;
    for (int c = 0; c < 32; c++) {
        cp_wait1();          // chunk c's KV group complete
        if (tid < 64) msk[tid] = mreg;
        int curv = (tid < 64) ? (mreg != 0) : 1;
        if (c + 1 < 32 && tid < 64) mreg = mask[b*SEQ + (c+1)*64 + tid];
        int allv = __syncthreads_and(curv);

        // issue chunk c+2 (always commit to keep wait accounting)
        {
            int st2 = st + 2; if (st2 >= 3) st2 -= 3;
            if (c + 2 < 32) {
                const __half* ks = Ksrc + (size_t)(c+2) * 64 * HDIM;
                const __half* vs = Vsrc + (size_t)(c+2) * 64 * HDIM;
                const uint32_t kd = kDst0 + st2 * (FA_K*2);
                const uint32_t vd = vDst0 + st2 * (FA_V*2);
#pragma unroll
                for (int j = 0; j < 2; j++) {
                    cp16(kd + j*16, ks + j*8);
                    cp16(vd + j*16, vs + j*8);
                }
            }
            cp_commit();
        }

        const __half* Ks = smh + FA_Q + st * FA_K;

        // ---- S = Q K^T (Q fragments in regs) ----
        float s[8][4];
#pragma unroll
        for (int nt = 0; nt < 8; nt++)
#pragma unroll
            for (int q = 0; q < 4; q++) s[nt][q] = 0.f;

#pragma unroll
        for (int kg = 0; kg < 4; kg++) {
            const int kb = kg * 16 + 4*tig;
#pragma unroll
            for (int nt = 0; nt < 8; nt++) {
                uint2 kf = *(const uint2*)&Ks[(nt*8 + g)*FQS + kb];
                mma_f16(s[nt], qa0[kg].x, qa1[kg].x, qa0[kg].y, qa1[kg].y,
                        kf.x, kf.y);
            }
        }

        // ---- mask (skipped when chunk fully valid) ----
        if (!allv) {
#pragma unroll
            for (int nt = 0; nt < 8; nt++) {
                int j0 = nt*8 + 2*tig;
                bool k0 = (msk[j0]   != 0);
                bool k1 = (msk[j0+1] != 0);
                s[nt][0] = k0 ? s[nt][0] : NEG_INF_V;
                s[nt][1] = k1 ? s[nt][1] : NEG_INF_V;
                s[nt][2] = k0 ? s[nt][2] : NEG_INF_V;
                s[nt][3] = k1 ? s[nt][3] : NEG_INF_V;
            }
        }

        // ---- online softmax with stable-max elision ----
        float rm0 = -1e30f, rm1 = -1e30f;
#pragma unroll
        for (int nt = 0; nt < 8; nt++) {
            rm0 = fmaxf(rm0, fmaxf(s[nt][0], s[nt][1]));
            rm1 = fmaxf(rm1, fmaxf(s[nt][2], s[nt][3]));
        }
        rm0 = fmaxf(rm0, __shfl_xor_sync(0xffffffffu, rm0, 1));
        rm0 = fmaxf(rm0, __shfl_xor_sync(0xffffffffu, rm0, 2));
        rm1 = fmaxf(rm1, __shfl_xor_sync(0xffffffffu, rm1, 1));
        rm1 = fmaxf(rm1, __shfl_xor_sync(0xffffffffu, rm1, 2));

        float mn0 = fmaxf(mrow0, rm0);
        float mn1 = fmaxf(mrow1, rm1);
        bool stable = __all_sync(0xffffffffu, (mn0 == mrow0) && (mn1 == mrow1));
        if (!stable) {
            float fac0 = __expf(mrow0 - mn0);
            float fac1 = __expf(mrow1 - mn1);
            ol[0] *= fac0;
            ol[2] *= fac1;
#pragma unroll
            for (int nt = 0; nt < 8; nt++) {
                o[nt][0] *= fac0; o[nt][1] *= fac0;
                o[nt][2] *= fac1; o[nt][3] *= fac1;
            }
            mrow0 = mn0;
            mrow1 = mn1;
        }

#pragma unroll
        for (int nt = 0; nt < 8; nt++) {
            s[nt][0] = __expf(s[nt][0] - mrow0);
            s[nt][1] = __expf(s[nt][1] - mrow0);
            s[nt][2] = __expf(s[nt][2] - mrow1);
            s[nt][3] = __expf(s[nt][3] - mrow1);
        }

        // ---- O += P V, l += P 1 : ldmatrix.trans B, ones-MMA for l ----
        const uint32_t vbase = smb + (FA_Q + 3*FA_K + st*FA_V + vlrow*VSTR + vcol8)*2;
#pragma unroll
        for (int kg = 0; kg < 4; kg++) {
            uint32_t a0 = pack2(s[2*kg  ][0], s[2*kg  ][1]);
            uint32_t a1 = pack2(s[2*kg  ][2], s[2*kg  ][3]);
            uint32_t a2 = pack2(s[2*kg+1][0], s[2*kg+1][1]);
            uint32_t a3 = pack2(s[2*kg+1][2], s[2*kg+1][3]);
            mma_f16(ol, a0, a1, a2, a3, ONES2, ONES2);
            const uint32_t rowa = vbase + kg * (16*VSTR*2);
#pragma unroll
            for (int ntp = 0; ntp < 4; ntp++) {
                uint32_t r0, r1, r2, r3;
                ldsm_x4_t(r0, r1, r2, r3, rowa + ntp*32);
                mma_f16(o[2*ntp  ], a0, a1, a2, a3, r0, r1);
                mma_f16(o[2*ntp+1], a0, a1, a2, a3, r2, r3);
            }
        }

        st++; if (st == 3) st = 0;
    }

    // ---- epilogue: normalize, fp16 + d-permute -> g_O [B,L,D] ----
    float inv0 = 1.f / ol[0];
    float inv1 = 1.f / ol[2];
    int qg0 = q0 + qb + g;
    int qg1 = qg0 + 8;
#pragma unroll
    for (int nt = 0; nt < 8; nt++) {
        int d = nt*8 + 2*tig;
        int pos = h*HDIM + (d & ~15) + permpos_even(d & 15);
        *(__half2*)&Og[(size_t)(b*SEQ + qg0)*DMODEL + pos] =
            __floats2half2_rn(o[nt][0]*inv0, o[nt][1]*inv0);
        *(__half2*)&Og[(size_t)(b*SEQ + qg1)*DMODEL + pos] =
            __floats2half2_rn(o[nt][2]*inv1, o[nt][3]*inv1);
    }
}

// =================================================================
// Host launcher
// =================================================================
extern "C" void kernel_launch(void* const* d_in, const int* in_sizes, int n_in,
                              void* d_out, int out_size)
{
    const float* q    = (const float*)d_in[0];
    const float* k    = (const float*)d_in[1];
    const float* v    = (const float*)d_in[2];
    const int*   am   = (const int*)  d_in[3];
    const float* Wq   = (const float*)d_in[4];
    const float* Wk   = (const float*)d_in[5];
    const float* Wv   = (const float*)d_in[6];
    const float* Wo   = (const float*)d_in[7];
    float* out = (float*)d_out;

    __half *gA, *gW, *gQ, *gK, *gV, *gO;
    cudaGetSymbolAddress((void**)&gA, g_A);
    cudaGetSymbolAddress((void**)&gW, g_W);
    cudaGetSymbolAddress((void**)&gQ, g_Q);
    cudaGetSymbolAddress((void**)&gK, g_K);
    cudaGetSymbolAddress((void**)&gV, g_V);
    cudaGetSymbolAddress((void**)&gO, g_O);

    cudaFuncSetAttribute(gemm_mma<0>, cudaFuncAttributeMaxDynamicSharedMemorySize, GT_SMEM_BYTES);
    cudaFuncSetAttribute(gemm_mma<1>, cudaFuncAttributeMaxDynamicSharedMemorySize, GT_SMEM_BYTES);
    cudaFuncSetAttribute(flash_mma,   cudaFuncAttributeMaxDynamicSharedMemorySize, FA_SMEM_BYTES);

    // pre-pass: fp16 round + pair-permute inputs and weights
    {
        int gpmA = MROWS*DMODEL/16;    // 262144
        dim3 pa((gpmA + 255)/256, 1, 3);
        prep_f16<<<pa, 256>>>(q, k, v, q, gA, gpmA);
        int gpmW = DMODEL*DMODEL/16;   // 65536
        dim3 pw((gpmW + 255)/256, 1, 4);
        prep_f16<<<pw, 256>>>(Wq, Wk, Wv, Wo, gW, gpmW);
    }

    // fused QKV projections
    dim3 gGrid(DMODEL/128, MROWS/128, 3);  // (8, 32, 3)
    gemm_mma<0><<<gGrid, 256, GT_SMEM_BYTES>>>(gA, gW, gQ, gK, gV, out);

    dim3 aGrid(SEQ/128, BATCH*NHEAD);      // (16, 32)
    flash_mma<<<aGrid, 256, FA_SMEM_BYTES>>>(am, gQ, gK, gV, gO);

    dim3 oGrid(DMODEL/128, MROWS/128, 1);  // (8, 32)
    gemm_mma<1><<<oGrid, 256, GT_SMEM_BYTES>>>(gO, gW + 3u*DMODEL*DMODEL,
                                               gQ, gK, gV, out);
}

// round 12
// speedup vs baseline: 11.3437x; 1.1701x over previous
#include <cuda_runtime.h>
#include <cuda_fp16.h>
#include <cstdint>

// Problem constants
#define BATCH 2
#define SEQ   2048
#define DMODEL 1024
#define NHEAD 16
#define HDIM  64
#define MROWS (BATCH*SEQ)          // 4096
#define NEG_INF_V (-1.0e9f)
#define ONES2 0x3C003C00u          // half2(1.0, 1.0)
#define QSCALE (0.125f * 1.4426950408889634f)   // 1/sqrt(64) * log2(e)

// ---------------- scratch (no allocation allowed) ----------------
__device__ __half g_A[3u*MROWS*DMODEL];        // fp16 q,k,v (natural)
__device__ __half g_W[4u*DMODEL*DMODEL];       // fp16 Wq,Wk,Wv,Wo (natural)
__device__ __half g_Q[BATCH*NHEAD*SEQ*HDIM];   // [B,H,L,Hd] scaled by QSCALE
__device__ __half g_K[BATCH*NHEAD*SEQ*HDIM];   // [B,H,L,Hd]
__device__ __half g_V[BATCH*NHEAD*SEQ*HDIM];   // [B,H,L,Hd]
__device__ __half g_O[BATCH*SEQ*DMODEL];       // [B,L,D]

// ---------------- helpers ----------------
__device__ __forceinline__ uint32_t pack2(float a, float b) {
    __half2 h = __floats2half2_rn(a, b);
    return *(uint32_t*)&h;
}
__device__ __forceinline__ float ex2f(float x) {
    float r;
    asm("ex2.approx.ftz.f32 %0, %1;" : "=f"(r) : "f"(x));
    return r;
}
__device__ __forceinline__ void mma_f16(float c[4], uint32_t a0, uint32_t a1,
                                        uint32_t a2, uint32_t a3,
                                        uint32_t b0, uint32_t b1) {
    asm volatile(
        "mma.sync.aligned.m16n8k16.row.col.f32.f16.f16.f32 "
        "{%0,%1,%2,%3},{%4,%5,%6,%7},{%8,%9},{%0,%1,%2,%3};"
        : "+f"(c[0]), "+f"(c[1]), "+f"(c[2]), "+f"(c[3])
        : "r"(a0), "r"(a1), "r"(a2), "r"(a3), "r"(b0), "r"(b1));
}
__device__ __forceinline__ void ldsm_x4(uint32_t& r0, uint32_t& r1,
                                        uint32_t& r2, uint32_t& r3, uint32_t addr) {
    asm volatile("ldmatrix.sync.aligned.m8n8.x4.shared.b16 {%0,%1,%2,%3}, [%4];"
                 : "=r"(r0), "=r"(r1), "=r"(r2), "=r"(r3) : "r"(addr));
}
__device__ __forceinline__ void ldsm_x4_t(uint32_t& r0, uint32_t& r1,
                                          uint32_t& r2, uint32_t& r3, uint32_t addr) {
    asm volatile("ldmatrix.sync.aligned.m8n8.x4.trans.shared.b16 {%0,%1,%2,%3}, [%4];"
                 : "=r"(r0), "=r"(r1), "=r"(r2), "=r"(r3) : "r"(addr));
}
__device__ __forceinline__ uint32_t smem_u32(const void* p) {
    uint32_t a;
    asm("{ .reg .u64 t; cvta.to.shared.u64 t, %1; cvt.u32.u64 %0, t; }" : "=r"(a) : "l"(p));
    return a;
}
__device__ __forceinline__ void cp16(uint32_t dst, const void* src) {
    asm volatile("cp.async.cg.shared.global [%0], [%1], 16;" :: "r"(dst), "l"(src) : "memory");
}
__device__ __forceinline__ void cp_commit() {
    asm volatile("cp.async.commit_group;" ::: "memory");
}
__device__ __forceinline__ void cp_wait0() {
    asm volatile("cp.async.wait_group 0;" ::: "memory");
}
__device__ __forceinline__ void cp_wait1() {
    asm volatile("cp.async.wait_group 1;" ::: "memory");
}
__device__ __forceinline__ void cp_wait2() {
    asm volatile("cp.async.wait_group 2;" ::: "memory");
}

// =================================================================
// Pre-pass: RN-round fp32 -> fp16 (natural order).
// =================================================================
__global__ __launch_bounds__(256)
void prep_f16(const float* __restrict__ s0, const float* __restrict__ s1,
              const float* __restrict__ s2, const float* __restrict__ s3,
              __half* __restrict__ dst, int groupsPerMat)
{
    const float* s = (blockIdx.z == 0) ? s0 : (blockIdx.z == 1) ? s1 :
                     (blockIdx.z == 2) ? s2 : s3;
    int i = blockIdx.x * blockDim.x + threadIdx.x;
    if (i >= groupsPerMat) return;
    const float4* sp = (const float4*)(s + (size_t)i * 16);
    float4 a = sp[0], b = sp[1], c = sp[2], d = sp[3];
    uint4* o = (uint4*)(dst + ((size_t)blockIdx.z * groupsPerMat + i) * 16);
    o[0] = make_uint4(pack2(a.x, a.y), pack2(a.z, a.w),
                      pack2(b.x, b.y), pack2(b.z, b.w));
    o[1] = make_uint4(pack2(c.x, c.y), pack2(c.z, c.w),
                      pack2(d.x, d.y), pack2(d.z, d.w));
}

// =================================================================
// fp16 tensor GEMM, cp.async 2-stage pipeline, ldmatrix fragments.
//   CTA 128x128, BK=64 halves, 256 thr = 8 warps (2m x 4n).
//   smem stride 72 halves (144B): 8-row ldmatrix phases conflict-free.
// MODE 0: z0 -> g_Q (x QSCALE), z1 -> g_K, z2 -> g_V  (all natural)
// MODE 1: raw fp32 [M,1024] to out
// =================================================================
#define GSTR 72
#define GBUFH (128*GSTR)                // 9216 halves per operand buffer
#define GT_SMEM_BYTES (4*GBUFH*2)       // 73728 B

template<int MODE>
__global__ __launch_bounds__(256, 2)
void gemm_mma(const __half* __restrict__ Abase, const __half* __restrict__ Wbase,
              __half* __restrict__ H0, __half* __restrict__ H1, __half* __restrict__ H2,
              float* __restrict__ Cf)
{
    extern __shared__ __half smh[];
    const uint32_t smb = smem_u32(smh);

    const int z = blockIdx.z;
    const __half* A = Abase + (size_t)z * ((size_t)MROWS * DMODEL);
    const __half* W = Wbase + (size_t)z * ((size_t)DMODEL * DMODEL);

    const int tid  = threadIdx.x;
    const int wid  = tid >> 5;
    const int lane = tid & 31;
    const int g    = lane >> 2;
    const int tig  = lane & 3;
    const int wm   = wid & 1;
    const int wn   = wid >> 1;
    const int m0 = blockIdx.y * 128;
    const int n0 = blockIdx.x * 128;

    // cp.async: row lr (0..127), 8 x 16B chunks; 2 threads/row, 4 chunks each
    const int lr = tid >> 1;
    const int cb = (tid & 1) * 4;
    const __half* Asrc = A + (size_t)(m0 + lr) * DMODEL + cb * 8;
    const __half* Wsrc = W + (size_t)(n0 + lr) * DMODEL + cb * 8;
    const uint32_t aDst = smb + lr * (GSTR*2) + cb * 16;

    // ldmatrix lane offsets (bytes, within a stage buffer)
    const uint32_t laneA_off = (uint32_t)(wm*64 + (lane & 15)) * (GSTR*2)
                             + (uint32_t)(lane >> 4) * 16;
    const uint32_t laneB_off = (uint32_t)(wn*32 + (lane & 7) + ((lane >> 4) & 1) * 8) * (GSTR*2)
                             + (uint32_t)((lane >> 3) & 1) * 16;

    float acc[4][4][4];
#pragma unroll
    for (int i = 0; i < 4; i++)
#pragma unroll
        for (int j = 0; j < 4; j++)
#pragma unroll
            for (int q = 0; q < 4; q++) acc[i][j][q] = 0.f;

    {
#pragma unroll
        for (int j = 0; j < 4; j++) {
            cp16(aDst + j*16, Asrc + j*8);
            cp16(aDst + GBUFH*2 + j*16, Wsrc + j*8);
        }
        cp_commit();
    }

    for (int c = 0; c < 16; c++) {
        const int st = c & 1;
        cp_wait0();
        __syncthreads();
        if (c + 1 < 16) {
            const __half* as = Asrc + (c+1)*64;
            const __half* ws = Wsrc + (c+1)*64;
            const uint32_t ad = aDst + (st^1) * (2*GBUFH*2);
#pragma unroll
            for (int j = 0; j < 4; j++) {
                cp16(ad + j*16, as + j*8);
                cp16(ad + GBUFH*2 + j*16, ws + j*8);
            }
            cp_commit();
        }
        const uint32_t aBase = smb + st * (2*GBUFH*2) + laneA_off;
        const uint32_t bBase = smb + st * (2*GBUFH*2) + GBUFH*2 + laneB_off;
#pragma unroll
        for (int kg = 0; kg < 4; kg++) {
            uint32_t a[4][4];
#pragma unroll
            for (int mt = 0; mt < 4; mt++)
                ldsm_x4(a[mt][0], a[mt][1], a[mt][2], a[mt][3],
                        aBase + mt * (16*GSTR*2) + kg*32);
#pragma unroll
            for (int ntp = 0; ntp < 2; ntp++) {
                uint32_t b0, b1, b2, b3;
                ldsm_x4(b0, b1, b2, b3, bBase + ntp * (16*GSTR*2) + kg*32);
#pragma unroll
                for (int mt = 0; mt < 4; mt++) {
                    mma_f16(acc[mt][2*ntp  ], a[mt][0], a[mt][1], a[mt][2], a[mt][3], b0, b1);
                    mma_f16(acc[mt][2*ntp+1], a[mt][0], a[mt][1], a[mt][2], a[mt][3], b2, b3);
                }
            }
        }
    }

    const float sc = (MODE == 0 && z == 0) ? QSCALE : 1.0f;
    __half* Hm = (z == 0) ? H0 : (z == 1) ? H1 : H2;
#pragma unroll
    for (int mt = 0; mt < 4; mt++) {
#pragma unroll
        for (int nt = 0; nt < 4; nt++) {
            int m = m0 + wm*64 + mt*16 + g;
            int n = n0 + wn*32 + nt*8 + 2*tig;
#pragma unroll
            for (int half_ = 0; half_ < 2; half_++) {
                int mm = m + half_*8;
                float vx = acc[mt][nt][half_*2];
                float vy = acc[mt][nt][half_*2+1];
                if (MODE == 0) {
                    int b = mm >> 11;
                    int l = mm & (SEQ - 1);
                    int h = n >> 6;
                    int d = n & (HDIM - 1);
                    size_t base = ((size_t)((b*NHEAD + h)*SEQ) + l) * HDIM;
                    *(__half2*)&Hm[base + d] = __floats2half2_rn(vx*sc, vy*sc);
                } else {
                    *(float2*)&Cf[(size_t)mm * DMODEL + n] = make_float2(vx, vy);
                }
            }
        }
    }
}

// =================================================================
// Flash attention v9 (fp16, log2-domain softmax, ldmatrix everywhere):
//   256 thr = 8 warps x 16 q, 128 q/block, 64-key chunks,
//   3-stage cp.async K/V pipeline, natural layouts.
//   - Q holds QSCALE = 0.125*log2e -> P = ex2(s - m)
//   - whole-sequence mask precheck skips all per-chunk mask work
//   - K fragments via ldmatrix.x4 (2 n-tiles per inst)
//   - V via ldmatrix.x4.trans; row-sum l via ones-column MMA
// =================================================================
#define FQS 72
#define FA_Q (128*FQS)                 // 9216 halves
#define FA_K (64*FQS)                  // 4608
#define FA_V (64*FQS)                  // 4608
#define FA_SMEM_BYTES ((FA_Q + 3*FA_K + 3*FA_V)*2)   // 73728 B

__global__ __launch_bounds__(256, 2)
void flash_mma(const int* __restrict__ mask,
               const __half* __restrict__ Qg,
               const __half* __restrict__ Kg,
               const __half* __restrict__ Vg,
               __half* __restrict__ Og)
{
    extern __shared__ __half smh[];
    const uint32_t smb = smem_u32(smh);
    __shared__ int msk[64];

    const int tid  = threadIdx.x;
    const int lane = tid & 31;
    const int wid  = tid >> 5;
    const int g    = lane >> 2;
    const int tig  = lane & 3;
    const int qb   = wid * 16;

    const int bh = blockIdx.y;
    const int b  = bh / NHEAD;
    const int h  = bh % NHEAD;
    const int q0 = blockIdx.x * 128;

    const size_t bhBase = (size_t)(b*NHEAD + h) * SEQ * HDIM;

    // K/V staging: 64 rows x 8 x 16B; 4 threads/row, 2 chunks each
    const int lr2 = tid >> 2;
    const int cb2 = (tid & 3) * 2;
    const __half* Ksrc = Kg + bhBase + (size_t)lr2 * HDIM + cb2 * 8;
    const __half* Vsrc = Vg + bhBase + (size_t)lr2 * HDIM + cb2 * 8;
    const uint32_t kDst0 = smb + FA_Q*2 + lr2 * (FQS*2) + cb2 * 16;
    const uint32_t vDst0 = smb + (FA_Q + 3*FA_K)*2 + lr2 * (FQS*2) + cb2 * 16;

    // ldmatrix lane offsets (bytes)
    const uint32_t laneQ_off = (uint32_t)(qb + (lane & 15)) * (FQS*2)
                             + (uint32_t)(lane >> 4) * 16;
    const uint32_t laneK_off = (uint32_t)((lane & 7) + ((lane >> 4) & 1) * 8) * (FQS*2)
                             + (uint32_t)((lane >> 3) & 1) * 16;
    const uint32_t laneV_off = (uint32_t)(lane & 15) * (FQS*2)
                             + (uint32_t)(lane >> 4) * 16;

    // ---- prologue: G0 = Q, G1 = KV0, G2 = KV1 ----
    {
        const int qr = tid >> 1;
        const int qc = (tid & 1) * 4;
        const __half* qsrc = Qg + bhBase + (size_t)(q0 + qr) * HDIM + qc * 8;
        uint32_t qdst = smb + qr * (FQS*2) + qc * 16;
#pragma unroll
        for (int j = 0; j < 4; j++) cp16(qdst + j*16, qsrc + j*8);
        cp_commit();   // G0
#pragma unroll
        for (int j = 0; j < 2; j++) {
            cp16(kDst0 + j*16, Ksrc + j*8);
            cp16(vDst0 + j*16, Vsrc + j*8);
        }
        cp_commit();   // G1
        const __half* ks1 = Ksrc + 64*HDIM;
        const __half* vs1 = Vsrc + 64*HDIM;
#pragma unroll
        for (int j = 0; j < 2; j++) {
            cp16(kDst0 + FA_K*2 + j*16, ks1 + j*8);
            cp16(vDst0 + FA_V*2 + j*16, vs1 + j*8);
        }
        cp_commit();   // G2
    }

    // ---- whole-sequence mask precheck ----
    int sv = 1;
#pragma unroll
    for (int j = 0; j < 8; j++)
        sv &= (mask[b*SEQ + tid + j*256] != 0);
    const int allSeq = __syncthreads_and(sv);
    int mreg = 0;
    if (!allSeq && tid < 64) mreg = mask[b*SEQ + tid];

    // ---- Q fragments to registers (once) ----
    cp_wait2();              // G0 (Q) complete
    __syncthreads();
    uint32_t qa[4][4];
#pragma unroll
    for (int kg = 0; kg < 4; kg++)
        ldsm_x4(qa[kg][0], qa[kg][1], qa[kg][2], qa[kg][3],
                smb + laneQ_off + kg*32);

    float o[8][4];
#pragma unroll
    for (int nt = 0; nt < 8; nt++)
#pragma unroll
        for (int q = 0; q < 4; q++) o[nt][q] = 0.f;
    float ol[4] = {0.f, 0.f, 0.f, 0.f};
    float mrow0 = -1e30f, mrow1 = -1e30f;

    int st = 0;
    for (int c = 0; c < 32; c++) {
        cp_wait1();
        int allv;
        if (!allSeq) {
            if (tid < 64) msk[tid] = mreg;
            int curv = (tid < 64) ? (mreg != 0) : 1;
            if (c + 1 < 32 && tid < 64) mreg = mask[b*SEQ + (c+1)*64 + tid];
            allv = __syncthreads_and(curv);
        } else {
            __syncthreads();
            allv = 1;
        }

        // issue chunk c+2 (always commit to keep wait accounting)
        {
            int st2 = st + 2; if (st2 >= 3) st2 -= 3;
            if (c + 2 < 32) {
                const __half* ks = Ksrc + (size_t)(c+2) * 64 * HDIM;
                const __half* vs = Vsrc + (size_t)(c+2) * 64 * HDIM;
                const uint32_t kd = kDst0 + st2 * (FA_K*2);
                const uint32_t vd = vDst0 + st2 * (FA_V*2);
#pragma unroll
                for (int j = 0; j < 2; j++) {
                    cp16(kd + j*16, ks + j*8);
                    cp16(vd + j*16, vs + j*8);
                }
            }
            cp_commit();
        }

        const uint32_t kBase = smb + FA_Q*2 + st * (FA_K*2) + laneK_off;

        // ---- S = Q K^T (ldmatrix.x4 for 2 n-tiles at a time) ----
        float s[8][4];
#pragma unroll
        for (int nt = 0; nt < 8; nt++)
#pragma unroll
            for (int q = 0; q < 4; q++) s[nt][q] = 0.f;

#pragma unroll
        for (int kg = 0; kg < 4; kg++) {
#pragma unroll
            for (int ntp = 0; ntp < 4; ntp++) {
                uint32_t b0, b1, b2, b3;
                ldsm_x4(b0, b1, b2, b3, kBase + ntp * (16*FQS*2) + kg*32);
                mma_f16(s[2*ntp  ], qa[kg][0], qa[kg][1], qa[kg][2], qa[kg][3], b0, b1);
                mma_f16(s[2*ntp+1], qa[kg][0], qa[kg][1], qa[kg][2], qa[kg][3], b2, b3);
            }
        }

        // ---- mask (skipped when chunk fully valid) ----
        if (!allv) {
#pragma unroll
            for (int nt = 0; nt < 8; nt++) {
                int j0 = nt*8 + 2*tig;
                bool k0 = (msk[j0]   != 0);
                bool k1 = (msk[j0+1] != 0);
                s[nt][0] = k0 ? s[nt][0] : NEG_INF_V;
                s[nt][1] = k1 ? s[nt][1] : NEG_INF_V;
                s[nt][2] = k0 ? s[nt][2] : NEG_INF_V;
                s[nt][3] = k1 ? s[nt][3] : NEG_INF_V;
            }
        }

        // ---- online softmax (log2 domain) with stable-max elision ----
        float rm0 = -1e30f, rm1 = -1e30f;
#pragma unroll
        for (int nt = 0; nt < 8; nt++) {
            rm0 = fmaxf(rm0, fmaxf(s[nt][0], s[nt][1]));
            rm1 = fmaxf(rm1, fmaxf(s[nt][2], s[nt][3]));
        }
        rm0 = fmaxf(rm0, __shfl_xor_sync(0xffffffffu, rm0, 1));
        rm0 = fmaxf(rm0, __shfl_xor_sync(0xffffffffu, rm0, 2));
        rm1 = fmaxf(rm1, __shfl_xor_sync(0xffffffffu, rm1, 1));
        rm1 = fmaxf(rm1, __shfl_xor_sync(0xffffffffu, rm1, 2));

        float mn0 = fmaxf(mrow0, rm0);
        float mn1 = fmaxf(mrow1, rm1);
        bool stable = __all_sync(0xffffffffu, (mn0 == mrow0) && (mn1 == mrow1));
        if (!stable) {
            float fac0 = ex2f(mrow0 - mn0);
            float fac1 = ex2f(mrow1 - mn1);
            ol[0] *= fac0;
            ol[2] *= fac1;
#pragma unroll
            for (int nt = 0; nt < 8; nt++) {
                o[nt][0] *= fac0; o[nt][1] *= fac0;
                o[nt][2] *= fac1; o[nt][3] *= fac1;
            }
            mrow0 = mn0;
            mrow1 = mn1;
        }

#pragma unroll
        for (int nt = 0; nt < 8; nt++) {
            s[nt][0] = ex2f(s[nt][0] - mrow0);
            s[nt][1] = ex2f(s[nt][1] - mrow0);
            s[nt][2] = ex2f(s[nt][2] - mrow1);
            s[nt][3] = ex2f(s[nt][3] - mrow1);
        }

        // ---- O += P V, l += P 1 (ldmatrix.trans B, ones-MMA) ----
        const uint32_t vBase = smb + (FA_Q + 3*FA_K)*2 + st * (FA_V*2) + laneV_off;
#pragma unroll
        for (int kg = 0; kg < 4; kg++) {
            uint32_t a0 = pack2(s[2*kg  ][0], s[2*kg  ][1]);
            uint32_t a1 = pack2(s[2*kg  ][2], s[2*kg  ][3]);
            uint32_t a2 = pack2(s[2*kg+1][0], s[2*kg+1][1]);
            uint32_t a3 = pack2(s[2*kg+1][2], s[2*kg+1][3]);
            mma_f16(ol, a0, a1, a2, a3, ONES2, ONES2);
            const uint32_t rowa = vBase + kg * (16*FQS*2);
#pragma unroll
            for (int ntp = 0; ntp < 4; ntp++) {
                uint32_t r0, r1, r2, r3;
                ldsm_x4_t(r0, r1, r2, r3, rowa + ntp*32);
                mma_f16(o[2*ntp  ], a0, a1, a2, a3, r0, r1);
                mma_f16(o[2*ntp+1], a0, a1, a2, a3, r2, r3);
            }
        }

        st++; if (st == 3) st = 0;
    }

    // ---- epilogue: normalize, fp16 -> g_O [B,L,D] (natural) ----
    float inv0 = 1.f / ol[0];
    float inv1 = 1.f / ol[2];
    int qg0 = q0 + qb + g;
    int qg1 = qg0 + 8;
#pragma unroll
    for (int nt = 0; nt < 8; nt++) {
        int pos = h*HDIM + nt*8 + 2*tig;
        *(__half2*)&Og[(size_t)(b*SEQ + qg0)*DMODEL + pos] =
            __floats2half2_rn(o[nt][0]*inv0, o[nt][1]*inv0);
        *(__half2*)&Og[(size_t)(b*SEQ + qg1)*DMODEL + pos] =
            __floats2half2_rn(o[nt][2]*inv1, o[nt][3]*inv1);
    }
}

// =================================================================
// Host launcher
// =================================================================
extern "C" void kernel_launch(void* const* d_in, const int* in_sizes, int n_in,
                              void* d_out, int out_size)
{
    const float* q    = (const float*)d_in[0];
    const float* k    = (const float*)d_in[1];
    const float* v    = (const float*)d_in[2];
    const int*   am   = (const int*)  d_in[3];
    const float* Wq   = (const float*)d_in[4];
    const float* Wk   = (const float*)d_in[5];
    const float* Wv   = (const float*)d_in[6];
    const float* Wo   = (const float*)d_in[7];
    float* out = (float*)d_out;

    __half *gA, *gW, *gQ, *gK, *gV, *gO;
    cudaGetSymbolAddress((void**)&gA, g_A);
    cudaGetSymbolAddress((void**)&gW, g_W);
    cudaGetSymbolAddress((void**)&gQ, g_Q);
    cudaGetSymbolAddress((void**)&gK, g_K);
    cudaGetSymbolAddress((void**)&gV, g_V);
    cudaGetSymbolAddress((void**)&gO, g_O);

    cudaFuncSetAttribute(gemm_mma<0>, cudaFuncAttributeMaxDynamicSharedMemorySize, GT_SMEM_BYTES);
    cudaFuncSetAttribute(gemm_mma<1>, cudaFuncAttributeMaxDynamicSharedMemorySize, GT_SMEM_BYTES);
    cudaFuncSetAttribute(flash_mma,   cudaFuncAttributeMaxDynamicSharedMemorySize, FA_SMEM_BYTES);

    // pre-pass: fp16 round (natural order)
    {
        int gpmA = MROWS*DMODEL/16;    // 262144
        dim3 pa((gpmA + 255)/256, 1, 3);
        prep_f16<<<pa, 256>>>(q, k, v, q, gA, gpmA);
        int gpmW = DMODEL*DMODEL/16;   // 65536
        dim3 pw((gpmW + 255)/256, 1, 4);
        prep_f16<<<pw, 256>>>(Wq, Wk, Wv, Wo, gW, gpmW);
    }

    // fused QKV projections
    dim3 gGrid(DMODEL/128, MROWS/128, 3);  // (8, 32, 3)
    gemm_mma<0><<<gGrid, 256, GT_SMEM_BYTES>>>(gA, gW, gQ, gK, gV, out);

    dim3 aGrid(SEQ/128, BATCH*NHEAD);      // (16, 32)
    flash_mma<<<aGrid, 256, FA_SMEM_BYTES>>>(am, gQ, gK, gV, gO);

    dim3 oGrid(DMODEL/128, MROWS/128, 1);  // (8, 32)
    gemm_mma<1><<<oGrid, 256, GT_SMEM_BYTES>>>(gO, gW + 3u*DMODEL*DMODEL,
                                               gQ, gK, gV, out);
}

// round 13
// speedup vs baseline: 11.4305x; 1.0076x over previous
#include <cuda_runtime.h>
#include <cuda_fp16.h>
#include <cstdint>

// Problem constants
#define BATCH 2
#define SEQ   2048
#define DMODEL 1024
#define NHEAD 16
#define HDIM  64
#define MROWS (BATCH*SEQ)          // 4096
#define NEG_INF_V (-1.0e9f)
#define ONES2 0x3C003C00u          // half2(1.0, 1.0)
#define QSCALE (0.125f * 1.4426950408889634f)   // 1/sqrt(64) * log2(e)

// ---------------- scratch (no allocation allowed) ----------------
__device__ __half g_A[3u*MROWS*DMODEL];        // fp16 q,k,v (natural)
__device__ __half g_W[4u*DMODEL*DMODEL];       // fp16 Wq,Wk,Wv,Wo (natural)
__device__ __half g_Q[BATCH*NHEAD*SEQ*HDIM];   // [B,H,L,Hd] scaled by QSCALE
__device__ __half g_K[BATCH*NHEAD*SEQ*HDIM];   // [B,H,L,Hd]
__device__ __half g_V[BATCH*NHEAD*SEQ*HDIM];   // [B,H,L,Hd]
__device__ __half g_O[BATCH*SEQ*DMODEL];       // [B,L,D]

// ---------------- helpers ----------------
__device__ __forceinline__ uint32_t pack2(float a, float b) {
    __half2 h = __floats2half2_rn(a, b);
    return *(uint32_t*)&h;
}
__device__ __forceinline__ float ex2f(float x) {
    float r;
    asm("ex2.approx.ftz.f32 %0, %1;" : "=f"(r) : "f"(x));
    return r;
}
__device__ __forceinline__ uint32_t h2ex2(uint32_t x) {
    uint32_t r;
    asm("ex2.approx.f16x2 %0, %1;" : "=r"(r) : "r"(x));
    return r;
}
__device__ __forceinline__ void mma_f16(float c[4], uint32_t a0, uint32_t a1,
                                        uint32_t a2, uint32_t a3,
                                        uint32_t b0, uint32_t b1) {
    asm volatile(
        "mma.sync.aligned.m16n8k16.row.col.f32.f16.f16.f32 "
        "{%0,%1,%2,%3},{%4,%5,%6,%7},{%8,%9},{%0,%1,%2,%3};"
        : "+f"(c[0]), "+f"(c[1]), "+f"(c[2]), "+f"(c[3])
        : "r"(a0), "r"(a1), "r"(a2), "r"(a3), "r"(b0), "r"(b1));
}
__device__ __forceinline__ void ldsm_x4(uint32_t& r0, uint32_t& r1,
                                        uint32_t& r2, uint32_t& r3, uint32_t addr) {
    asm volatile("ldmatrix.sync.aligned.m8n8.x4.shared.b16 {%0,%1,%2,%3}, [%4];"
                 : "=r"(r0), "=r"(r1), "=r"(r2), "=r"(r3) : "r"(addr));
}
__device__ __forceinline__ void ldsm_x4_t(uint32_t& r0, uint32_t& r1,
                                          uint32_t& r2, uint32_t& r3, uint32_t addr) {
    asm volatile("ldmatrix.sync.aligned.m8n8.x4.trans.shared.b16 {%0,%1,%2,%3}, [%4];"
                 : "=r"(r0), "=r"(r1), "=r"(r2), "=r"(r3) : "r"(addr));
}
__device__ __forceinline__ uint32_t smem_u32(const void* p) {
    uint32_t a;
    asm("{ .reg .u64 t; cvta.to.shared.u64 t, %1; cvt.u32.u64 %0, t; }" : "=r"(a) : "l"(p));
    return a;
}
__device__ __forceinline__ void cp16(uint32_t dst, const void* src) {
    asm volatile("cp.async.cg.shared.global [%0], [%1], 16;" :: "r"(dst), "l"(src) : "memory");
}
__device__ __forceinline__ void cp_commit() {
    asm volatile("cp.async.commit_group;" ::: "memory");
}
__device__ __forceinline__ void cp_wait1() {
    asm volatile("cp.async.wait_group 1;" ::: "memory");
}
__device__ __forceinline__ void cp_wait2() {
    asm volatile("cp.async.wait_group 2;" ::: "memory");
}

// =================================================================
// Pre-pass: RN-round fp32 -> fp16 (natural order).
// =================================================================
__global__ __launch_bounds__(256)
void prep_f16(const float* __restrict__ s0, const float* __restrict__ s1,
              const float* __restrict__ s2, const float* __restrict__ s3,
              __half* __restrict__ dst, int groupsPerMat)
{
    const float* s = (blockIdx.z == 0) ? s0 : (blockIdx.z == 1) ? s1 :
                     (blockIdx.z == 2) ? s2 : s3;
    int i = blockIdx.x * blockDim.x + threadIdx.x;
    if (i >= groupsPerMat) return;
    const float4* sp = (const float4*)(s + (size_t)i * 16);
    float4 a = sp[0], b = sp[1], c = sp[2], d = sp[3];
    uint4* o = (uint4*)(dst + ((size_t)blockIdx.z * groupsPerMat + i) * 16);
    o[0] = make_uint4(pack2(a.x, a.y), pack2(a.z, a.w),
                      pack2(b.x, b.y), pack2(b.z, b.w));
    o[1] = make_uint4(pack2(c.x, c.y), pack2(c.z, c.w),
                      pack2(d.x, d.y), pack2(d.z, d.w));
}

// =================================================================
// fp16 tensor GEMM, cp.async 3-stage pipeline, ldmatrix fragments.
//   CTA 128x128, BK=64 halves, 256 thr = 8 warps (2m x 4n).
//   smem stride 72 halves (144B): 8-row ldmatrix phases conflict-free.
// MODE 0: z0 -> g_Q (x QSCALE), z1 -> g_K, z2 -> g_V  (all natural)
// MODE 1: raw fp32 [M,1024] to out
// =================================================================
#define GSTR 72
#define GBUFH (128*GSTR)                // 9216 halves per operand buffer
#define GSTG  (2*GBUFH*2)               // stage size in bytes (A+B) = 36864
#define GT_SMEM_BYTES (3*GSTG)          // 110592 B (3 stages)

template<int MODE>
__global__ __launch_bounds__(256, 2)
void gemm_mma(const __half* __restrict__ Abase, const __half* __restrict__ Wbase,
              __half* __restrict__ H0, __half* __restrict__ H1, __half* __restrict__ H2,
              float* __restrict__ Cf)
{
    extern __shared__ __half smh[];
    const uint32_t smb = smem_u32(smh);

    const int z = blockIdx.z;
    const __half* A = Abase + (size_t)z * ((size_t)MROWS * DMODEL);
    const __half* W = Wbase + (size_t)z * ((size_t)DMODEL * DMODEL);

    const int tid  = threadIdx.x;
    const int wid  = tid >> 5;
    const int lane = tid & 31;
    const int g    = lane >> 2;
    const int tig  = lane & 3;
    const int wm   = wid & 1;
    const int wn   = wid >> 1;
    const int m0 = blockIdx.y * 128;
    const int n0 = blockIdx.x * 128;

    // cp.async: row lr (0..127), 8 x 16B chunks; 2 threads/row, 4 chunks each
    const int lr = tid >> 1;
    const int cb = (tid & 1) * 4;
    const __half* Asrc = A + (size_t)(m0 + lr) * DMODEL + cb * 8;
    const __half* Wsrc = W + (size_t)(n0 + lr) * DMODEL + cb * 8;
    const uint32_t aDst = smb + lr * (GSTR*2) + cb * 16;

    // ldmatrix lane offsets (bytes, within a stage buffer)
    const uint32_t laneA_off = (uint32_t)(wm*64 + (lane & 15)) * (GSTR*2)
                             + (uint32_t)(lane >> 4) * 16;
    const uint32_t laneB_off = (uint32_t)(wn*32 + (lane & 7) + ((lane >> 4) & 1) * 8) * (GSTR*2)
                             + (uint32_t)((lane >> 3) & 1) * 16;

    float acc[4][4][4];
#pragma unroll
    for (int i = 0; i < 4; i++)
#pragma unroll
        for (int j = 0; j < 4; j++)
#pragma unroll
            for (int q = 0; q < 4; q++) acc[i][j][q] = 0.f;

    // prologue: stage 0 = chunk 0, stage 1 = chunk 1
#pragma unroll
    for (int j = 0; j < 4; j++) {
        cp16(aDst + j*16, Asrc + j*8);
        cp16(aDst + GBUFH*2 + j*16, Wsrc + j*8);
    }
    cp_commit();
#pragma unroll
    for (int j = 0; j < 4; j++) {
        cp16(aDst + GSTG + j*16, Asrc + 64 + j*8);
        cp16(aDst + GSTG + GBUFH*2 + j*16, Wsrc + 64 + j*8);
    }
    cp_commit();

    int st = 0;
    for (int c = 0; c < 16; c++) {
        cp_wait1();          // chunk c complete (c+1 may be in flight)
        __syncthreads();
        {
            int st2 = st + 2; if (st2 >= 3) st2 -= 3;
            if (c + 2 < 16) {
                const __half* as = Asrc + (c+2)*64;
                const __half* ws = Wsrc + (c+2)*64;
                const uint32_t ad = aDst + st2 * GSTG;
#pragma unroll
                for (int j = 0; j < 4; j++) {
                    cp16(ad + j*16, as + j*8);
                    cp16(ad + GBUFH*2 + j*16, ws + j*8);
                }
            }
            cp_commit();
        }
        const uint32_t aBase = smb + st * GSTG + laneA_off;
        const uint32_t bBase = smb + st * GSTG + GBUFH*2 + laneB_off;
#pragma unroll
        for (int kg = 0; kg < 4; kg++) {
            uint32_t a[4][4];
#pragma unroll
            for (int mt = 0; mt < 4; mt++)
                ldsm_x4(a[mt][0], a[mt][1], a[mt][2], a[mt][3],
                        aBase + mt * (16*GSTR*2) + kg*32);
#pragma unroll
            for (int ntp = 0; ntp < 2; ntp++) {
                uint32_t b0, b1, b2, b3;
                ldsm_x4(b0, b1, b2, b3, bBase + ntp * (16*GSTR*2) + kg*32);
#pragma unroll
                for (int mt = 0; mt < 4; mt++) {
                    mma_f16(acc[mt][2*ntp  ], a[mt][0], a[mt][1], a[mt][2], a[mt][3], b0, b1);
                    mma_f16(acc[mt][2*ntp+1], a[mt][0], a[mt][1], a[mt][2], a[mt][3], b2, b3);
                }
            }
        }
        st++; if (st == 3) st = 0;
    }

    const float sc = (MODE == 0 && z == 0) ? QSCALE : 1.0f;
    __half* Hm = (z == 0) ? H0 : (z == 1) ? H1 : H2;
#pragma unroll
    for (int mt = 0; mt < 4; mt++) {
#pragma unroll
        for (int nt = 0; nt < 4; nt++) {
            int m = m0 + wm*64 + mt*16 + g;
            int n = n0 + wn*32 + nt*8 + 2*tig;
#pragma unroll
            for (int half_ = 0; half_ < 2; half_++) {
                int mm = m + half_*8;
                float vx = acc[mt][nt][half_*2];
                float vy = acc[mt][nt][half_*2+1];
                if (MODE == 0) {
                    int b = mm >> 11;
                    int l = mm & (SEQ - 1);
                    int h = n >> 6;
                    int d = n & (HDIM - 1);
                    size_t base = ((size_t)((b*NHEAD + h)*SEQ) + l) * HDIM;
                    *(__half2*)&Hm[base + d] = __floats2half2_rn(vx*sc, vy*sc);
                } else {
                    *(float2*)&Cf[(size_t)mm * DMODEL + n] = make_float2(vx, vy);
                }
            }
        }
    }
}

// =================================================================
// Flash attention v10 (fp16, log2 softmax, f16x2 exponentials):
//   256 thr = 8 warps x 16 q, 128 q/block, 64-key chunks,
//   3-stage cp.async K/V pipeline, ldmatrix fragments.
// =================================================================
#define FQS 72
#define FA_Q (128*FQS)                 // 9216 halves
#define FA_K (64*FQS)                  // 4608
#define FA_V (64*FQS)                  // 4608
#define FA_SMEM_BYTES ((FA_Q + 3*FA_K + 3*FA_V)*2)   // 73728 B

__global__ __launch_bounds__(256, 2)
void flash_mma(const int* __restrict__ mask,
               const __half* __restrict__ Qg,
               const __half* __restrict__ Kg,
               const __half* __restrict__ Vg,
               __half* __restrict__ Og)
{
    extern __shared__ __half smh[];
    const uint32_t smb = smem_u32(smh);
    __shared__ int msk[64];

    const int tid  = threadIdx.x;
    const int lane = tid & 31;
    const int wid  = tid >> 5;
    const int g    = lane >> 2;
    const int tig  = lane & 3;
    const int qb   = wid * 16;

    const int bh = blockIdx.y;
    const int b  = bh / NHEAD;
    const int h  = bh % NHEAD;
    const int q0 = blockIdx.x * 128;

    const size_t bhBase = (size_t)(b*NHEAD + h) * SEQ * HDIM;

    // K/V staging: 64 rows x 8 x 16B; 4 threads/row, 2 chunks each
    const int lr2 = tid >> 2;
    const int cb2 = (tid & 3) * 2;
    const __half* Ksrc = Kg + bhBase + (size_t)lr2 * HDIM + cb2 * 8;
    const __half* Vsrc = Vg + bhBase + (size_t)lr2 * HDIM + cb2 * 8;
    const uint32_t kDst0 = smb + FA_Q*2 + lr2 * (FQS*2) + cb2 * 16;
    const uint32_t vDst0 = smb + (FA_Q + 3*FA_K)*2 + lr2 * (FQS*2) + cb2 * 16;

    // ldmatrix lane offsets (bytes)
    const uint32_t laneQ_off = (uint32_t)(qb + (lane & 15)) * (FQS*2)
                             + (uint32_t)(lane >> 4) * 16;
    const uint32_t laneK_off = (uint32_t)((lane & 7) + ((lane >> 4) & 1) * 8) * (FQS*2)
                             + (uint32_t)((lane >> 3) & 1) * 16;
    const uint32_t laneV_off = (uint32_t)(lane & 15) * (FQS*2)
                             + (uint32_t)(lane >> 4) * 16;

    // ---- prologue: G0 = Q, G1 = KV0, G2 = KV1 ----
    {
        const int qr = tid >> 1;
        const int qc = (tid & 1) * 4;
        const __half* qsrc = Qg + bhBase + (size_t)(q0 + qr) * HDIM + qc * 8;
        uint32_t qdst = smb + qr * (FQS*2) + qc * 16;
#pragma unroll
        for (int j = 0; j < 4; j++) cp16(qdst + j*16, qsrc + j*8);
        cp_commit();   // G0
#pragma unroll
        for (int j = 0; j < 2; j++) {
            cp16(kDst0 + j*16, Ksrc + j*8);
            cp16(vDst0 + j*16, Vsrc + j*8);
        }
        cp_commit();   // G1
        const __half* ks1 = Ksrc + 64*HDIM;
        const __half* vs1 = Vsrc + 64*HDIM;
#pragma unroll
        for (int j = 0; j < 2; j++) {
            cp16(kDst0 + FA_K*2 + j*16, ks1 + j*8);
            cp16(vDst0 + FA_V*2 + j*16, vs1 + j*8);
        }
        cp_commit();   // G2
    }

    // ---- whole-sequence mask precheck ----
    int sv = 1;
#pragma unroll
    for (int j = 0; j < 8; j++)
        sv &= (mask[b*SEQ + tid + j*256] != 0);
    const int allSeq = __syncthreads_and(sv);
    int mreg = 0;
    if (!allSeq && tid < 64) mreg = mask[b*SEQ + tid];

    // ---- Q fragments to registers (once) ----
    cp_wait2();              // G0 (Q) complete
    __syncthreads();
    uint32_t qa[4][4];
#pragma unroll
    for (int kg = 0; kg < 4; kg++)
        ldsm_x4(qa[kg][0], qa[kg][1], qa[kg][2], qa[kg][3],
                smb + laneQ_off + kg*32);

    float o[8][4];
#pragma unroll
    for (int nt = 0; nt < 8; nt++)
#pragma unroll
        for (int q = 0; q < 4; q++) o[nt][q] = 0.f;
    float ol[4] = {0.f, 0.f, 0.f, 0.f};
    float mrow0 = -1e30f, mrow1 = -1e30f;

    int st = 0;
    for (int c = 0; c < 32; c++) {
        cp_wait1();
        int allv;
        if (!allSeq) {
            if (tid < 64) msk[tid] = mreg;
            int curv = (tid < 64) ? (mreg != 0) : 1;
            if (c + 1 < 32 && tid < 64) mreg = mask[b*SEQ + (c+1)*64 + tid];
            allv = __syncthreads_and(curv);
        } else {
            __syncthreads();
            allv = 1;
        }

        // issue chunk c+2 (always commit to keep wait accounting)
        {
            int st2 = st + 2; if (st2 >= 3) st2 -= 3;
            if (c + 2 < 32) {
                const __half* ks = Ksrc + (size_t)(c+2) * 64 * HDIM;
                const __half* vs = Vsrc + (size_t)(c+2) * 64 * HDIM;
                const uint32_t kd = kDst0 + st2 * (FA_K*2);
                const uint32_t vd = vDst0 + st2 * (FA_V*2);
#pragma unroll
                for (int j = 0; j < 2; j++) {
                    cp16(kd + j*16, ks + j*8);
                    cp16(vd + j*16, vs + j*8);
                }
            }
            cp_commit();
        }

        const uint32_t kBase = smb + FA_Q*2 + st * (FA_K*2) + laneK_off;

        // ---- S = Q K^T (ldmatrix.x4 for 2 n-tiles at a time) ----
        float s[8][4];
#pragma unroll
        for (int nt = 0; nt < 8; nt++)
#pragma unroll
            for (int q = 0; q < 4; q++) s[nt][q] = 0.f;

#pragma unroll
        for (int kg = 0; kg < 4; kg++) {
#pragma unroll
            for (int ntp = 0; ntp < 4; ntp++) {
                uint32_t b0, b1, b2, b3;
                ldsm_x4(b0, b1, b2, b3, kBase + ntp * (16*FQS*2) + kg*32);
                mma_f16(s[2*ntp  ], qa[kg][0], qa[kg][1], qa[kg][2], qa[kg][3], b0, b1);
                mma_f16(s[2*ntp+1], qa[kg][0], qa[kg][1], qa[kg][2], qa[kg][3], b2, b3);
            }
        }

        // ---- mask (skipped when chunk fully valid) ----
        if (!allv) {
#pragma unroll
            for (int nt = 0; nt < 8; nt++) {
                int j0 = nt*8 + 2*tig;
                bool k0 = (msk[j0]   != 0);
                bool k1 = (msk[j0+1] != 0);
                s[nt][0] = k0 ? s[nt][0] : NEG_INF_V;
                s[nt][1] = k1 ? s[nt][1] : NEG_INF_V;
                s[nt][2] = k0 ? s[nt][2] : NEG_INF_V;
                s[nt][3] = k1 ? s[nt][3] : NEG_INF_V;
            }
        }

        // ---- online softmax (log2 domain) with stable-max elision ----
        float rm0 = -1e30f, rm1 = -1e30f;
#pragma unroll
        for (int nt = 0; nt < 8; nt++) {
            rm0 = fmaxf(rm0, fmaxf(s[nt][0], s[nt][1]));
            rm1 = fmaxf(rm1, fmaxf(s[nt][2], s[nt][3]));
        }
        rm0 = fmaxf(rm0, __shfl_xor_sync(0xffffffffu, rm0, 1));
        rm0 = fmaxf(rm0, __shfl_xor_sync(0xffffffffu, rm0, 2));
        rm1 = fmaxf(rm1, __shfl_xor_sync(0xffffffffu, rm1, 1));
        rm1 = fmaxf(rm1, __shfl_xor_sync(0xffffffffu, rm1, 2));

        float mn0 = fmaxf(mrow0, rm0);
        float mn1 = fmaxf(mrow1, rm1);
        bool stable = __all_sync(0xffffffffu, (mn0 == mrow0) && (mn1 == mrow1));
        if (!stable) {
            float fac0 = ex2f(mrow0 - mn0);
            float fac1 = ex2f(mrow1 - mn1);
            ol[0] *= fac0;
            ol[2] *= fac1;
#pragma unroll
            for (int nt = 0; nt < 8; nt++) {
                o[nt][0] *= fac0; o[nt][1] *= fac0;
                o[nt][2] *= fac1; o[nt][3] *= fac1;
            }
            mrow0 = mn0;
            mrow1 = mn1;
        }

        // ---- O += P V, l += P 1 : P computed as ex2.f16x2 of (s - m) ----
        const uint32_t vBase = smb + (FA_Q + 3*FA_K)*2 + st * (FA_V*2) + laneV_off;
#pragma unroll
        for (int kg = 0; kg < 4; kg++) {
            uint32_t a0 = h2ex2(pack2(s[2*kg  ][0] - mrow0, s[2*kg  ][1] - mrow0));
            uint32_t a1 = h2ex2(pack2(s[2*kg  ][2] - mrow1, s[2*kg  ][3] - mrow1));
            uint32_t a2 = h2ex2(pack2(s[2*kg+1][0] - mrow0, s[2*kg+1][1] - mrow0));
            uint32_t a3 = h2ex2(pack2(s[2*kg+1][2] - mrow1, s[2*kg+1][3] - mrow1));
            mma_f16(ol, a0, a1, a2, a3, ONES2, ONES2);
            const uint32_t rowa = vBase + kg * (16*FQS*2);
#pragma unroll
            for (int ntp = 0; ntp < 4; ntp++) {
                uint32_t r0, r1, r2, r3;
                ldsm_x4_t(r0, r1, r2, r3, rowa + ntp*32);
                mma_f16(o[2*ntp  ], a0, a1, a2, a3, r0, r1);
                mma_f16(o[2*ntp+1], a0, a1, a2, a3, r2, r3);
            }
        }

        st++; if (st == 3) st = 0;
    }

    // ---- epilogue: normalize, fp16 -> g_O [B,L,D] (natural) ----
    float inv0 = 1.f / ol[0];
    float inv1 = 1.f / ol[2];
    int qg0 = q0 + qb + g;
    int qg1 = qg0 + 8;
#pragma unroll
    for (int nt = 0; nt < 8; nt++) {
        int pos = h*HDIM + nt*8 + 2*tig;
        *(__half2*)&Og[(size_t)(b*SEQ + qg0)*DMODEL + pos] =
            __floats2half2_rn(o[nt][0]*inv0, o[nt][1]*inv0);
        *(__half2*)&Og[(size_t)(b*SEQ + qg1)*DMODEL + pos] =
            __floats2half2_rn(o[nt][2]*inv1, o[nt][3]*inv1);
    }
}

// =================================================================
// Host launcher
// =================================================================
extern "C" void kernel_launch(void* const* d_in, const int* in_sizes, int n_in,
                              void* d_out, int out_size)
{
    const float* q    = (const float*)d_in[0];
    const float* k    = (const float*)d_in[1];
    const float* v    = (const float*)d_in[2];
    const int*   am   = (const int*)  d_in[3];
    const float* Wq   = (const float*)d_in[4];
    const float* Wk   = (const float*)d_in[5];
    const float* Wv   = (const float*)d_in[6];
    const float* Wo   = (const float*)d_in[7];
    float* out = (float*)d_out;

    __half *gA, *gW, *gQ, *gK, *gV, *gO;
    cudaGetSymbolAddress((void**)&gA, g_A);
    cudaGetSymbolAddress((void**)&gW, g_W);
    cudaGetSymbolAddress((void**)&gQ, g_Q);
    cudaGetSymbolAddress((void**)&gK, g_K);
    cudaGetSymbolAddress((void**)&gV, g_V);
    cudaGetSymbolAddress((void**)&gO, g_O);

    cudaFuncSetAttribute(gemm_mma<0>, cudaFuncAttributeMaxDynamicSharedMemorySize, GT_SMEM_BYTES);
    cudaFuncSetAttribute(gemm_mma<1>, cudaFuncAttributeMaxDynamicSharedMemorySize, GT_SMEM_BYTES);
    cudaFuncSetAttribute(flash_mma,   cudaFuncAttributeMaxDynamicSharedMemorySize, FA_SMEM_BYTES);

    // pre-pass: fp16 round (natural order)
    {
        int gpmA = MROWS*DMODEL/16;    // 262144
        dim3 pa((gpmA + 255)/256, 1, 3);
        prep_f16<<<pa, 256>>>(q, k, v, q, gA, gpmA);
        int gpmW = DMODEL*DMODEL/16;   // 65536
        dim3 pw((gpmW + 255)/256, 1, 4);
        prep_f16<<<pw, 256>>>(Wq, Wk, Wv, Wo, gW, gpmW);
    }

    // fused QKV projections
    dim3 gGrid(DMODEL/128, MROWS/128, 3);  // (8, 32, 3)
    gemm_mma<0><<<gGrid, 256, GT_SMEM_BYTES>>>(gA, gW, gQ, gK, gV, out);

    dim3 aGrid(SEQ/128, BATCH*NHEAD);      // (16, 32)
    flash_mma<<<aGrid, 256, FA_SMEM_BYTES>>>(am, gQ, gK, gV, gO);

    dim3 oGrid(DMODEL/128, MROWS/128, 1);  // (8, 32)
    gemm_mma<1><<<oGrid, 256, GT_SMEM_BYTES>>>(gO, gW + 3u*DMODEL*DMODEL,
                                               gQ, gK, gV, out);
}

// round 14
// speedup vs baseline: 12.5365x; 1.0968x over previous
#include <cuda_runtime.h>
#include <cuda_fp16.h>
#include <cstdint>

// Problem constants
#define BATCH 2
#define SEQ   2048
#define DMODEL 1024
#define NHEAD 16
#define HDIM  64
#define MROWS (BATCH*SEQ)          // 4096
#define NEG_INF_V (-1.0e9f)
#define ONES2 0x3C003C00u          // half2(1.0, 1.0)
#define QSCALE (0.125f * 1.4426950408889634f)   // 1/sqrt(64) * log2(e)

// ---------------- scratch (no allocation allowed) ----------------
__device__ __half g_A[3u*MROWS*DMODEL];        // fp16 q,k,v (natural)
__device__ __half g_W[4u*DMODEL*DMODEL];       // fp16 Wq,Wk,Wv,Wo (natural)
__device__ __half g_Q[BATCH*NHEAD*SEQ*HDIM];   // [B,H,L,Hd] scaled by QSCALE
__device__ __half g_K[BATCH*NHEAD*SEQ*HDIM];   // [B,H,L,Hd]
__device__ __half g_V[BATCH*NHEAD*SEQ*HDIM];   // [B,H,L,Hd]
__device__ __half g_O[BATCH*SEQ*DMODEL];       // [B,L,D]

// ---------------- helpers ----------------
__device__ __forceinline__ uint32_t pack2(float a, float b) {
    __half2 h = __floats2half2_rn(a, b);
    return *(uint32_t*)&h;
}
__device__ __forceinline__ float ex2f(float x) {
    float r;
    asm("ex2.approx.ftz.f32 %0, %1;" : "=f"(r) : "f"(x));
    return r;
}
__device__ __forceinline__ uint32_t h2ex2(uint32_t x) {
    uint32_t r;
    asm("ex2.approx.f16x2 %0, %1;" : "=r"(r) : "r"(x));
    return r;
}
__device__ __forceinline__ void mma_f16(float c[4], uint32_t a0, uint32_t a1,
                                        uint32_t a2, uint32_t a3,
                                        uint32_t b0, uint32_t b1) {
    asm volatile(
        "mma.sync.aligned.m16n8k16.row.col.f32.f16.f16.f32 "
        "{%0,%1,%2,%3},{%4,%5,%6,%7},{%8,%9},{%0,%1,%2,%3};"
        : "+f"(c[0]), "+f"(c[1]), "+f"(c[2]), "+f"(c[3])
        : "r"(a0), "r"(a1), "r"(a2), "r"(a3), "r"(b0), "r"(b1));
}
__device__ __forceinline__ void ldsm_x4(uint32_t& r0, uint32_t& r1,
                                        uint32_t& r2, uint32_t& r3, uint32_t addr) {
    asm volatile("ldmatrix.sync.aligned.m8n8.x4.shared.b16 {%0,%1,%2,%3}, [%4];"
                 : "=r"(r0), "=r"(r1), "=r"(r2), "=r"(r3) : "r"(addr));
}
__device__ __forceinline__ void ldsm_x4_t(uint32_t& r0, uint32_t& r1,
                                          uint32_t& r2, uint32_t& r3, uint32_t addr) {
    asm volatile("ldmatrix.sync.aligned.m8n8.x4.trans.shared.b16 {%0,%1,%2,%3}, [%4];"
                 : "=r"(r0), "=r"(r1), "=r"(r2), "=r"(r3) : "r"(addr));
}
__device__ __forceinline__ uint32_t smem_u32(const void* p) {
    uint32_t a;
    asm("{ .reg .u64 t; cvta.to.shared.u64 t, %1; cvt.u32.u64 %0, t; }" : "=r"(a) : "l"(p));
    return a;
}
__device__ __forceinline__ void cp16(uint32_t dst, const void* src) {
    asm volatile("cp.async.cg.shared.global [%0], [%1], 16;" :: "r"(dst), "l"(src) : "memory");
}
__device__ __forceinline__ void cp_commit() {
    asm volatile("cp.async.commit_group;" ::: "memory");
}
__device__ __forceinline__ void cp_wait0() {
    asm volatile("cp.async.wait_group 0;" ::: "memory");
}
__device__ __forceinline__ void cp_wait1() {
    asm volatile("cp.async.wait_group 1;" ::: "memory");
}
__device__ __forceinline__ void cp_wait2() {
    asm volatile("cp.async.wait_group 2;" ::: "memory");
}

// =================================================================
// Pre-pass: RN-round fp32 -> fp16 (natural order).
// =================================================================
__global__ __launch_bounds__(256)
void prep_f16(const float* __restrict__ s0, const float* __restrict__ s1,
              const float* __restrict__ s2, const float* __restrict__ s3,
              __half* __restrict__ dst, int groupsPerMat)
{
    const float* s = (blockIdx.z == 0) ? s0 : (blockIdx.z == 1) ? s1 :
                     (blockIdx.z == 2) ? s2 : s3;
    int i = blockIdx.x * blockDim.x + threadIdx.x;
    if (i >= groupsPerMat) return;
    const float4* sp = (const float4*)(s + (size_t)i * 16);
    float4 a = sp[0], b = sp[1], c = sp[2], d = sp[3];
    uint4* o = (uint4*)(dst + ((size_t)blockIdx.z * groupsPerMat + i) * 16);
    o[0] = make_uint4(pack2(a.x, a.y), pack2(a.z, a.w),
                      pack2(b.x, b.y), pack2(b.z, b.w));
    o[1] = make_uint4(pack2(c.x, c.y), pack2(c.z, c.w),
                      pack2(d.x, d.y), pack2(d.z, d.w));
}

// =================================================================
// fp16 tensor GEMM v2: 512 threads = 16 warps (4m x 4n) of 32x32,
//   CTA tile 128x128, BK=64 halves, 2-stage cp.async pipeline,
//   ldmatrix fragments, smem stride 72 halves (conflict-free).
//   2 CTAs/SM -> 32 warps/SM.
// MODE 0: z0 -> g_Q (x QSCALE), z1 -> g_K, z2 -> g_V  (all natural)
// MODE 1: raw fp32 [M,1024] to out
// =================================================================
#define GSTR 72
#define GBUFH (128*GSTR)                // 9216 halves per operand buffer
#define GSTG  (2*GBUFH*2)               // stage bytes (A+B) = 36864
#define GT_SMEM_BYTES (2*GSTG)          // 73728 B

template<int MODE>
__global__ __launch_bounds__(512, 2)
void gemm_mma(const __half* __restrict__ Abase, const __half* __restrict__ Wbase,
              __half* __restrict__ H0, __half* __restrict__ H1, __half* __restrict__ H2,
              float* __restrict__ Cf)
{
    extern __shared__ __half smh[];
    const uint32_t smb = smem_u32(smh);

    const int z = blockIdx.z;
    const __half* A = Abase + (size_t)z * ((size_t)MROWS * DMODEL);
    const __half* W = Wbase + (size_t)z * ((size_t)DMODEL * DMODEL);

    const int tid  = threadIdx.x;
    const int wid  = tid >> 5;
    const int lane = tid & 31;
    const int g    = lane >> 2;
    const int tig  = lane & 3;
    const int wm   = wid & 3;          // 4 m-warps of 32 rows
    const int wn   = wid >> 2;         // 4 n-warps of 32 cols
    const int m0 = blockIdx.y * 128;
    const int n0 = blockIdx.x * 128;

    // cp.async staging: row lr (0..127), 4 threads/row, 2 x 16B chunks each
    const int lr = tid >> 2;
    const int cb = (tid & 3) * 2;      // chunk index (of 8 per row)
    const __half* Asrc = A + (size_t)(m0 + lr) * DMODEL + cb * 8;
    const __half* Wsrc = W + (size_t)(n0 + lr) * DMODEL + cb * 8;
    const uint32_t aDst = smb + lr * (GSTR*2) + cb * 16;

    // ldmatrix lane offsets (bytes, within a stage buffer)
    const uint32_t laneA_off = (uint32_t)(wm*32 + (lane & 15)) * (GSTR*2)
                             + (uint32_t)(lane >> 4) * 16;
    const uint32_t laneB_off = (uint32_t)(wn*32 + (lane & 7) + ((lane >> 4) & 1) * 8) * (GSTR*2)
                             + (uint32_t)((lane >> 3) & 1) * 16;

    float acc[2][4][4];
#pragma unroll
    for (int i = 0; i < 2; i++)
#pragma unroll
        for (int j = 0; j < 4; j++)
#pragma unroll
            for (int q = 0; q < 4; q++) acc[i][j][q] = 0.f;

    // prologue: chunk 0 into stage 0
#pragma unroll
    for (int j = 0; j < 2; j++) {
        cp16(aDst + j*16, Asrc + j*8);
        cp16(aDst + GBUFH*2 + j*16, Wsrc + j*8);
    }
    cp_commit();

    for (int c = 0; c < 16; c++) {
        const int st = c & 1;
        cp_wait0();
        __syncthreads();
        if (c + 1 < 16) {
            const __half* as = Asrc + (c+1)*64;
            const __half* ws = Wsrc + (c+1)*64;
            const uint32_t ad = aDst + (st^1) * GSTG;
#pragma unroll
            for (int j = 0; j < 2; j++) {
                cp16(ad + j*16, as + j*8);
                cp16(ad + GBUFH*2 + j*16, ws + j*8);
            }
            cp_commit();
        }
        const uint32_t aBase = smb + st * GSTG + laneA_off;
        const uint32_t bBase = smb + st * GSTG + GBUFH*2 + laneB_off;
#pragma unroll
        for (int kg = 0; kg < 4; kg++) {
            uint32_t a[2][4];
#pragma unroll
            for (int mt = 0; mt < 2; mt++)
                ldsm_x4(a[mt][0], a[mt][1], a[mt][2], a[mt][3],
                        aBase + mt * (16*GSTR*2) + kg*32);
#pragma unroll
            for (int ntp = 0; ntp < 2; ntp++) {
                uint32_t b0, b1, b2, b3;
                ldsm_x4(b0, b1, b2, b3, bBase + ntp * (16*GSTR*2) + kg*32);
#pragma unroll
                for (int mt = 0; mt < 2; mt++) {
                    mma_f16(acc[mt][2*ntp  ], a[mt][0], a[mt][1], a[mt][2], a[mt][3], b0, b1);
                    mma_f16(acc[mt][2*ntp+1], a[mt][0], a[mt][1], a[mt][2], a[mt][3], b2, b3);
                }
            }
        }
    }

    const float sc = (MODE == 0 && z == 0) ? QSCALE : 1.0f;
    __half* Hm = (z == 0) ? H0 : (z == 1) ? H1 : H2;
#pragma unroll
    for (int mt = 0; mt < 2; mt++) {
#pragma unroll
        for (int nt = 0; nt < 4; nt++) {
            int m = m0 + wm*32 + mt*16 + g;
            int n = n0 + wn*32 + nt*8 + 2*tig;
#pragma unroll
            for (int half_ = 0; half_ < 2; half_++) {
                int mm = m + half_*8;
                float vx = acc[mt][nt][half_*2];
                float vy = acc[mt][nt][half_*2+1];
                if (MODE == 0) {
                    int b = mm >> 11;
                    int l = mm & (SEQ - 1);
                    int h = n >> 6;
                    int d = n & (HDIM - 1);
                    size_t base = ((size_t)((b*NHEAD + h)*SEQ) + l) * HDIM;
                    *(__half2*)&Hm[base + d] = __floats2half2_rn(vx*sc, vy*sc);
                } else {
                    *(float2*)&Cf[(size_t)mm * DMODEL + n] = make_float2(vx, vy);
                }
            }
        }
    }
}

// =================================================================
// Flash attention v10 (unchanged from R13): fp16, log2 softmax,
// f16x2 exponentials, 256 thr = 8 warps x 16 q, 128 q/block,
// 64-key chunks, 3-stage cp.async K/V pipeline, ldmatrix fragments.
// =================================================================
#define FQS 72
#define FA_Q (128*FQS)                 // 9216 halves
#define FA_K (64*FQS)                  // 4608
#define FA_V (64*FQS)                  // 4608
#define FA_SMEM_BYTES ((FA_Q + 3*FA_K + 3*FA_V)*2)   // 73728 B

__global__ __launch_bounds__(256, 2)
void flash_mma(const int* __restrict__ mask,
               const __half* __restrict__ Qg,
               const __half* __restrict__ Kg,
               const __half* __restrict__ Vg,
               __half* __restrict__ Og)
{
    extern __shared__ __half smh[];
    const uint32_t smb = smem_u32(smh);
    __shared__ int msk[64];

    const int tid  = threadIdx.x;
    const int lane = tid & 31;
    const int wid  = tid >> 5;
    const int g    = lane >> 2;
    const int tig  = lane & 3;
    const int qb   = wid * 16;

    const int bh = blockIdx.y;
    const int b  = bh / NHEAD;
    const int h  = bh % NHEAD;
    const int q0 = blockIdx.x * 128;

    const size_t bhBase = (size_t)(b*NHEAD + h) * SEQ * HDIM;

    // K/V staging: 64 rows x 8 x 16B; 4 threads/row, 2 chunks each
    const int lr2 = tid >> 2;
    const int cb2 = (tid & 3) * 2;
    const __half* Ksrc = Kg + bhBase + (size_t)lr2 * HDIM + cb2 * 8;
    const __half* Vsrc = Vg + bhBase + (size_t)lr2 * HDIM + cb2 * 8;
    const uint32_t kDst0 = smb + FA_Q*2 + lr2 * (FQS*2) + cb2 * 16;
    const uint32_t vDst0 = smb + (FA_Q + 3*FA_K)*2 + lr2 * (FQS*2) + cb2 * 16;

    // ldmatrix lane offsets (bytes)
    const uint32_t laneQ_off = (uint32_t)(qb + (lane & 15)) * (FQS*2)
                             + (uint32_t)(lane >> 4) * 16;
    const uint32_t laneK_off = (uint32_t)((lane & 7) + ((lane >> 4) & 1) * 8) * (FQS*2)
                             + (uint32_t)((lane >> 3) & 1) * 16;
    const uint32_t laneV_off = (uint32_t)(lane & 15) * (FQS*2)
                             + (uint32_t)(lane >> 4) * 16;

    // ---- prologue: G0 = Q, G1 = KV0, G2 = KV1 ----
    {
        const int qr = tid >> 1;
        const int qc = (tid & 1) * 4;
        const __half* qsrc = Qg + bhBase + (size_t)(q0 + qr) * HDIM + qc * 8;
        uint32_t qdst = smb + qr * (FQS*2) + qc * 16;
#pragma unroll
        for (int j = 0; j < 4; j++) cp16(qdst + j*16, qsrc + j*8);
        cp_commit();   // G0
#pragma unroll
        for (int j = 0; j < 2; j++) {
            cp16(kDst0 + j*16, Ksrc + j*8);
            cp16(vDst0 + j*16, Vsrc + j*8);
        }
        cp_commit();   // G1
        const __half* ks1 = Ksrc + 64*HDIM;
        const __half* vs1 = Vsrc + 64*HDIM;
#pragma unroll
        for (int j = 0; j < 2; j++) {
            cp16(kDst0 + FA_K*2 + j*16, ks1 + j*8);
            cp16(vDst0 + FA_V*2 + j*16, vs1 + j*8);
        }
        cp_commit();   // G2
    }

    // ---- whole-sequence mask precheck ----
    int sv = 1;
#pragma unroll
    for (int j = 0; j < 8; j++)
        sv &= (mask[b*SEQ + tid + j*256] != 0);
    const int allSeq = __syncthreads_and(sv);
    int mreg = 0;
    if (!allSeq && tid < 64) mreg = mask[b*SEQ + tid];

    // ---- Q fragments to registers (once) ----
    cp_wait2();              // G0 (Q) complete
    __syncthreads();
    uint32_t qa[4][4];
#pragma unroll
    for (int kg = 0; kg < 4; kg++)
        ldsm_x4(qa[kg][0], qa[kg][1], qa[kg][2], qa[kg][3],
                smb + laneQ_off + kg*32);

    float o[8][4];
#pragma unroll
    for (int nt = 0; nt < 8; nt++)
#pragma unroll
        for (int q = 0; q < 4; q++) o[nt][q] = 0.f;
    float ol[4] = {0.f, 0.f, 0.f, 0.f};
    float mrow0 = -1e30f, mrow1 = -1e30f;

    int st = 0;
    for (int c = 0; c < 32; c++) {
        cp_wait1();
        int allv;
        if (!allSeq) {
            if (tid < 64) msk[tid] = mreg;
            int curv = (tid < 64) ? (mreg != 0) : 1;
            if (c + 1 < 32 && tid < 64) mreg = mask[b*SEQ + (c+1)*64 + tid];
            allv = __syncthreads_and(curv);
        } else {
            __syncthreads();
            allv = 1;
        }

        // issue chunk c+2 (always commit to keep wait accounting)
        {
            int st2 = st + 2; if (st2 >= 3) st2 -= 3;
            if (c + 2 < 32) {
                const __half* ks = Ksrc + (size_t)(c+2) * 64 * HDIM;
                const __half* vs = Vsrc + (size_t)(c+2) * 64 * HDIM;
                const uint32_t kd = kDst0 + st2 * (FA_K*2);
                const uint32_t vd = vDst0 + st2 * (FA_V*2);
#pragma unroll
                for (int j = 0; j < 2; j++) {
                    cp16(kd + j*16, ks + j*8);
                    cp16(vd + j*16, vs + j*8);
                }
            }
            cp_commit();
        }

        const uint32_t kBase = smb + FA_Q*2 + st * (FA_K*2) + laneK_off;

        // ---- S = Q K^T (ldmatrix.x4 for 2 n-tiles at a time) ----
        float s[8][4];
#pragma unroll
        for (int nt = 0; nt < 8; nt++)
#pragma unroll
            for (int q = 0; q < 4; q++) s[nt][q] = 0.f;

#pragma unroll
        for (int kg = 0; kg < 4; kg++) {
#pragma unroll
            for (int ntp = 0; ntp < 4; ntp++) {
                uint32_t b0, b1, b2, b3;
                ldsm_x4(b0, b1, b2, b3, kBase + ntp * (16*FQS*2) + kg*32);
                mma_f16(s[2*ntp  ], qa[kg][0], qa[kg][1], qa[kg][2], qa[kg][3], b0, b1);
                mma_f16(s[2*ntp+1], qa[kg][0], qa[kg][1], qa[kg][2], qa[kg][3], b2, b3);
            }
        }

        // ---- mask (skipped when chunk fully valid) ----
        if (!allv) {
#pragma unroll
            for (int nt = 0; nt < 8; nt++) {
                int j0 = nt*8 + 2*tig;
                bool k0 = (msk[j0]   != 0);
                bool k1 = (msk[j0+1] != 0);
                s[nt][0] = k0 ? s[nt][0] : NEG_INF_V;
                s[nt][1] = k1 ? s[nt][1] : NEG_INF_V;
                s[nt][2] = k0 ? s[nt][2] : NEG_INF_V;
                s[nt][3] = k1 ? s[nt][3] : NEG_INF_V;
            }
        }

        // ---- online softmax (log2 domain) with stable-max elision ----
        float rm0 = -1e30f, rm1 = -1e30f;
#pragma unroll
        for (int nt = 0; nt < 8; nt++) {
            rm0 = fmaxf(rm0, fmaxf(s[nt][0], s[nt][1]));
            rm1 = fmaxf(rm1, fmaxf(s[nt][2], s[nt][3]));
        }
        rm0 = fmaxf(rm0, __shfl_xor_sync(0xffffffffu, rm0, 1));
        rm0 = fmaxf(rm0, __shfl_xor_sync(0xffffffffu, rm0, 2));
        rm1 = fmaxf(rm1, __shfl_xor_sync(0xffffffffu, rm1, 1));
        rm1 = fmaxf(rm1, __shfl_xor_sync(0xffffffffu, rm1, 2));

        float mn0 = fmaxf(mrow0, rm0);
        float mn1 = fmaxf(mrow1, rm1);
        bool stable = __all_sync(0xffffffffu, (mn0 == mrow0) && (mn1 == mrow1));
        if (!stable) {
            float fac0 = ex2f(mrow0 - mn0);
            float fac1 = ex2f(mrow1 - mn1);
            ol[0] *= fac0;
            ol[2] *= fac1;
#pragma unroll
            for (int nt = 0; nt < 8; nt++) {
                o[nt][0] *= fac0; o[nt][1] *= fac0;
                o[nt][2] *= fac1; o[nt][3] *= fac1;
            }
            mrow0 = mn0;
            mrow1 = mn1;
        }

        // ---- O += P V, l += P 1 : P computed as ex2.f16x2 of (s - m) ----
        const uint32_t vBase = smb + (FA_Q + 3*FA_K)*2 + st * (FA_V*2) + laneV_off;
#pragma unroll
        for (int kg = 0; kg < 4; kg++) {
            uint32_t a0 = h2ex2(pack2(s[2*kg  ][0] - mrow0, s[2*kg  ][1] - mrow0));
            uint32_t a1 = h2ex2(pack2(s[2*kg  ][2] - mrow1, s[2*kg  ][3] - mrow1));
            uint32_t a2 = h2ex2(pack2(s[2*kg+1][0] - mrow0, s[2*kg+1][1] - mrow0));
            uint32_t a3 = h2ex2(pack2(s[2*kg+1][2] - mrow1, s[2*kg+1][3] - mrow1));
            mma_f16(ol, a0, a1, a2, a3, ONES2, ONES2);
            const uint32_t rowa = vBase + kg * (16*FQS*2);
#pragma unroll
            for (int ntp = 0; ntp < 4; ntp++) {
                uint32_t r0, r1, r2, r3;
                ldsm_x4_t(r0, r1, r2, r3, rowa + ntp*32);
                mma_f16(o[2*ntp  ], a0, a1, a2, a3, r0, r1);
                mma_f16(o[2*ntp+1], a0, a1, a2, a3, r2, r3);
            }
        }

        st++; if (st == 3) st = 0;
    }

    // ---- epilogue: normalize, fp16 -> g_O [B,L,D] (natural) ----
    float inv0 = 1.f / ol[0];
    float inv1 = 1.f / ol[2];
    int qg0 = q0 + qb + g;
    int qg1 = qg0 + 8;
#pragma unroll
    for (int nt = 0; nt < 8; nt++) {
        int pos = h*HDIM + nt*8 + 2*tig;
        *(__half2*)&Og[(size_t)(b*SEQ + qg0)*DMODEL + pos] =
            __floats2half2_rn(o[nt][0]*inv0, o[nt][1]*inv0);
        *(__half2*)&Og[(size_t)(b*SEQ + qg1)*DMODEL + pos] =
            __floats2half2_rn(o[nt][2]*inv1, o[nt][3]*inv1);
    }
}

// =================================================================
// Host launcher
// =================================================================
extern "C" void kernel_launch(void* const* d_in, const int* in_sizes, int n_in,
                              void* d_out, int out_size)
{
    const float* q    = (const float*)d_in[0];
    const float* k    = (const float*)d_in[1];
    const float* v    = (const float*)d_in[2];
    const int*   am   = (const int*)  d_in[3];
    const float* Wq   = (const float*)d_in[4];
    const float* Wk   = (const float*)d_in[5];
    const float* Wv   = (const float*)d_in[6];
    const float* Wo   = (const float*)d_in[7];
    float* out = (float*)d_out;

    __half *gA, *gW, *gQ, *gK, *gV, *gO;
    cudaGetSymbolAddress((void**)&gA, g_A);
    cudaGetSymbolAddress((void**)&gW, g_W);
    cudaGetSymbolAddress((void**)&gQ, g_Q);
    cudaGetSymbolAddress((void**)&gK, g_K);
    cudaGetSymbolAddress((void**)&gV, g_V);
    cudaGetSymbolAddress((void**)&gO, g_O);

    cudaFuncSetAttribute(gemm_mma<0>, cudaFuncAttributeMaxDynamicSharedMemorySize, GT_SMEM_BYTES);
    cudaFuncSetAttribute(gemm_mma<1>, cudaFuncAttributeMaxDynamicSharedMemorySize, GT_SMEM_BYTES);
    cudaFuncSetAttribute(flash_mma,   cudaFuncAttributeMaxDynamicSharedMemorySize, FA_SMEM_BYTES);

    // pre-pass: fp16 round (natural order)
    {
        int gpmA = MROWS*DMODEL/16;    // 262144
        dim3 pa((gpmA + 255)/256, 1, 3);
        prep_f16<<<pa, 256>>>(q, k, v, q, gA, gpmA);
        int gpmW = DMODEL*DMODEL/16;   // 65536
        dim3 pw((gpmW + 255)/256, 1, 4);
        prep_f16<<<pw, 256>>>(Wq, Wk, Wv, Wo, gW, gpmW);
    }

    // fused QKV projections (512-thread CTAs)
    dim3 gGrid(DMODEL/128, MROWS/128, 3);  // (8, 32, 3)
    gemm_mma<0><<<gGrid, 512, GT_SMEM_BYTES>>>(gA, gW, gQ, gK, gV, out);

    dim3 aGrid(SEQ/128, BATCH*NHEAD);      // (16, 32)
    flash_mma<<<aGrid, 256, FA_SMEM_BYTES>>>(am, gQ, gK, gV, gO);

    dim3 oGrid(DMODEL/128, MROWS/128, 1);  // (8, 32)
    gemm_mma<1><<<oGrid, 512, GT_SMEM_BYTES>>>(gO, gW + 3u*DMODEL*DMODEL,
                                               gQ, gK, gV, out);
}

// round 15
// speedup vs baseline: 12.6320x; 1.0076x over previous
#include <cuda_runtime.h>
#include <cuda_fp16.h>
#include <cstdint>

// Problem constants
#define BATCH 2
#define SEQ   2048
#define DMODEL 1024
#define NHEAD 16
#define HDIM  64
#define MROWS (BATCH*SEQ)          // 4096
#define NEG_INF_V (-1.0e9f)
#define ONES2 0x3C003C00u          // half2(1.0, 1.0)
#define QSCALE (0.125f * 1.4426950408889634f)   // 1/sqrt(64) * log2(e)

// ---------------- scratch (no allocation allowed) ----------------
__device__ __half g_A[3u*MROWS*DMODEL];        // fp16 q,k,v (natural)
__device__ __half g_W[4u*DMODEL*DMODEL];       // fp16 Wq,Wk,Wv,Wo (natural)
__device__ __half g_Q[BATCH*NHEAD*SEQ*HDIM];   // [B,H,L,Hd] scaled by QSCALE
__device__ __half g_K[BATCH*NHEAD*SEQ*HDIM];   // [B,H,L,Hd]
__device__ __half g_V[BATCH*NHEAD*SEQ*HDIM];   // [B,H,L,Hd]
__device__ __half g_O[BATCH*SEQ*DMODEL];       // [B,L,D]

// ---------------- helpers ----------------
__device__ __forceinline__ uint32_t pack2(float a, float b) {
    __half2 h = __floats2half2_rn(a, b);
    return *(uint32_t*)&h;
}
__device__ __forceinline__ float ex2f(float x) {
    float r;
    asm("ex2.approx.ftz.f32 %0, %1;" : "=f"(r) : "f"(x));
    return r;
}
__device__ __forceinline__ uint32_t h2ex2(uint32_t x) {
    uint32_t r;
    asm("ex2.approx.f16x2 %0, %1;" : "=r"(r) : "r"(x));
    return r;
}
__device__ __forceinline__ void mma_f16(float c[4], uint32_t a0, uint32_t a1,
                                        uint32_t a2, uint32_t a3,
                                        uint32_t b0, uint32_t b1) {
    asm volatile(
        "mma.sync.aligned.m16n8k16.row.col.f32.f16.f16.f32 "
        "{%0,%1,%2,%3},{%4,%5,%6,%7},{%8,%9},{%0,%1,%2,%3};"
        : "+f"(c[0]), "+f"(c[1]), "+f"(c[2]), "+f"(c[3])
        : "r"(a0), "r"(a1), "r"(a2), "r"(a3), "r"(b0), "r"(b1));
}
__device__ __forceinline__ void ldsm_x4(uint32_t& r0, uint32_t& r1,
                                        uint32_t& r2, uint32_t& r3, uint32_t addr) {
    asm volatile("ldmatrix.sync.aligned.m8n8.x4.shared.b16 {%0,%1,%2,%3}, [%4];"
                 : "=r"(r0), "=r"(r1), "=r"(r2), "=r"(r3) : "r"(addr));
}
__device__ __forceinline__ void ldsm_x4_t(uint32_t& r0, uint32_t& r1,
                                          uint32_t& r2, uint32_t& r3, uint32_t addr) {
    asm volatile("ldmatrix.sync.aligned.m8n8.x4.trans.shared.b16 {%0,%1,%2,%3}, [%4];"
                 : "=r"(r0), "=r"(r1), "=r"(r2), "=r"(r3) : "r"(addr));
}
__device__ __forceinline__ uint32_t smem_u32(const void* p) {
    uint32_t a;
    asm("{ .reg .u64 t; cvta.to.shared.u64 t, %1; cvt.u32.u64 %0, t; }" : "=r"(a) : "l"(p));
    return a;
}
__device__ __forceinline__ void cp16(uint32_t dst, const void* src) {
    asm volatile("cp.async.cg.shared.global [%0], [%1], 16;" :: "r"(dst), "l"(src) : "memory");
}
__device__ __forceinline__ void cp_commit() {
    asm volatile("cp.async.commit_group;" ::: "memory");
}
__device__ __forceinline__ void cp_wait1() {
    asm volatile("cp.async.wait_group 1;" ::: "memory");
}
__device__ __forceinline__ void cp_wait2() {
    asm volatile("cp.async.wait_group 2;" ::: "memory");
}

// =================================================================
// Pre-pass (single launch): RN-round fp32 -> fp16, 7 matrices.
//   z 0..2 -> q,k,v into g_A; z 3..6 -> Wq,Wk,Wv,Wo into g_W.
// =================================================================
__global__ __launch_bounds__(256)
void prep_all(const float* __restrict__ q, const float* __restrict__ k,
              const float* __restrict__ v,
              const float* __restrict__ Wq, const float* __restrict__ Wk,
              const float* __restrict__ Wv, const float* __restrict__ Wo,
              __half* __restrict__ dstA, __half* __restrict__ dstW)
{
    const int z = blockIdx.z;
    const float* s;
    __half* d;
    int gpm;
    if (z < 3) {
        s = (z == 0) ? q : (z == 1) ? k : v;
        gpm = MROWS*DMODEL/16;
        d = dstA + (size_t)z * ((size_t)MROWS*DMODEL);
    } else {
        int w = z - 3;
        s = (w == 0) ? Wq : (w == 1) ? Wk : (w == 2) ? Wv : Wo;
        gpm = DMODEL*DMODEL/16;
        d = dstW + (size_t)w * ((size_t)DMODEL*DMODEL);
    }
    int i = blockIdx.x * blockDim.x + threadIdx.x;
    if (i >= gpm) return;
    const float4* sp = (const float4*)(s + (size_t)i * 16);
    float4 a = sp[0], b = sp[1], c = sp[2], e = sp[3];
    uint4* o = (uint4*)(d + (size_t)i * 16);
    o[0] = make_uint4(pack2(a.x, a.y), pack2(a.z, a.w),
                      pack2(b.x, b.y), pack2(b.z, b.w));
    o[1] = make_uint4(pack2(c.x, c.y), pack2(c.z, c.w),
                      pack2(e.x, e.y), pack2(e.z, e.w));
}

// =================================================================
// fp16 tensor GEMM v3: 512 threads = 16 warps (4m x 4n) of 32x32,
//   CTA tile 128x128, BK=64 halves, 3-stage cp.async + wait_group 1,
//   ldmatrix fragments, smem stride 72 halves (conflict-free).
//   smem 110592 B -> 2 CTAs/SM (221 KB of 228 KB carveout).
// MODE 0: z0 -> g_Q (x QSCALE), z1 -> g_K, z2 -> g_V  (all natural)
// MODE 1: raw fp32 [M,1024] to out
// =================================================================
#define GSTR 72
#define GBUFH (128*GSTR)                // 9216 halves per operand buffer
#define GSTG  (2*GBUFH*2)               // stage bytes (A+B) = 36864
#define GT_SMEM_BYTES (3*GSTG)          // 110592 B (3 stages)

template<int MODE>
__global__ __launch_bounds__(512, 2)
void gemm_mma(const __half* __restrict__ Abase, const __half* __restrict__ Wbase,
              __half* __restrict__ H0, __half* __restrict__ H1, __half* __restrict__ H2,
              float* __restrict__ Cf)
{
    extern __shared__ __half smh[];
    const uint32_t smb = smem_u32(smh);

    const int z = blockIdx.z;
    const __half* A = Abase + (size_t)z * ((size_t)MROWS * DMODEL);
    const __half* W = Wbase + (size_t)z * ((size_t)DMODEL * DMODEL);

    const int tid  = threadIdx.x;
    const int wid  = tid >> 5;
    const int lane = tid & 31;
    const int g    = lane >> 2;
    const int tig  = lane & 3;
    const int wm   = wid & 3;          // 4 m-warps of 32 rows
    const int wn   = wid >> 2;         // 4 n-warps of 32 cols
    const int m0 = blockIdx.y * 128;
    const int n0 = blockIdx.x * 128;

    // cp.async staging: row lr (0..127), 4 threads/row, 2 x 16B chunks each
    const int lr = tid >> 2;
    const int cb = (tid & 3) * 2;      // chunk index (of 8 per row)
    const __half* Asrc = A + (size_t)(m0 + lr) * DMODEL + cb * 8;
    const __half* Wsrc = W + (size_t)(n0 + lr) * DMODEL + cb * 8;
    const uint32_t aDst = smb + lr * (GSTR*2) + cb * 16;

    // ldmatrix lane offsets (bytes, within a stage buffer)
    const uint32_t laneA_off = (uint32_t)(wm*32 + (lane & 15)) * (GSTR*2)
                             + (uint32_t)(lane >> 4) * 16;
    const uint32_t laneB_off = (uint32_t)(wn*32 + (lane & 7) + ((lane >> 4) & 1) * 8) * (GSTR*2)
                             + (uint32_t)((lane >> 3) & 1) * 16;

    float acc[2][4][4];
#pragma unroll
    for (int i = 0; i < 2; i++)
#pragma unroll
        for (int j = 0; j < 4; j++)
#pragma unroll
            for (int q = 0; q < 4; q++) acc[i][j][q] = 0.f;

    // prologue: chunk 0 -> stage 0, chunk 1 -> stage 1
#pragma unroll
    for (int j = 0; j < 2; j++) {
        cp16(aDst + j*16, Asrc + j*8);
        cp16(aDst + GBUFH*2 + j*16, Wsrc + j*8);
    }
    cp_commit();
#pragma unroll
    for (int j = 0; j < 2; j++) {
        cp16(aDst + GSTG + j*16, Asrc + 64 + j*8);
        cp16(aDst + GSTG + GBUFH*2 + j*16, Wsrc + 64 + j*8);
    }
    cp_commit();

    int st = 0;
    for (int c = 0; c < 16; c++) {
        cp_wait1();          // chunk c landed (c+1 may be in flight)
        __syncthreads();
        {
            int st2 = st + 2; if (st2 >= 3) st2 -= 3;
            if (c + 2 < 16) {
                const __half* as = Asrc + (c+2)*64;
                const __half* ws = Wsrc + (c+2)*64;
                const uint32_t ad = aDst + st2 * GSTG;
#pragma unroll
                for (int j = 0; j < 2; j++) {
                    cp16(ad + j*16, as + j*8);
                    cp16(ad + GBUFH*2 + j*16, ws + j*8);
                }
            }
            cp_commit();     // always commit to keep wait accounting exact
        }
        const uint32_t aBase = smb + st * GSTG + laneA_off;
        const uint32_t bBase = smb + st * GSTG + GBUFH*2 + laneB_off;
#pragma unroll
        for (int kg = 0; kg < 4; kg++) {
            uint32_t a[2][4];
#pragma unroll
            for (int mt = 0; mt < 2; mt++)
                ldsm_x4(a[mt][0], a[mt][1], a[mt][2], a[mt][3],
                        aBase + mt * (16*GSTR*2) + kg*32);
#pragma unroll
            for (int ntp = 0; ntp < 2; ntp++) {
                uint32_t b0, b1, b2, b3;
                ldsm_x4(b0, b1, b2, b3, bBase + ntp * (16*GSTR*2) + kg*32);
#pragma unroll
                for (int mt = 0; mt < 2; mt++) {
                    mma_f16(acc[mt][2*ntp  ], a[mt][0], a[mt][1], a[mt][2], a[mt][3], b0, b1);
                    mma_f16(acc[mt][2*ntp+1], a[mt][0], a[mt][1], a[mt][2], a[mt][3], b2, b3);
                }
            }
        }
        st++; if (st == 3) st = 0;
    }

    const float sc = (MODE == 0 && z == 0) ? QSCALE : 1.0f;
    __half* Hm = (z == 0) ? H0 : (z == 1) ? H1 : H2;
#pragma unroll
    for (int mt = 0; mt < 2; mt++) {
#pragma unroll
        for (int nt = 0; nt < 4; nt++) {
            int m = m0 + wm*32 + mt*16 + g;
            int n = n0 + wn*32 + nt*8 + 2*tig;
#pragma unroll
            for (int half_ = 0; half_ < 2; half_++) {
                int mm = m + half_*8;
                float vx = acc[mt][nt][half_*2];
                float vy = acc[mt][nt][half_*2+1];
                if (MODE == 0) {
                    int b = mm >> 11;
                    int l = mm & (SEQ - 1);
                    int h = n >> 6;
                    int d = n & (HDIM - 1);
                    size_t base = ((size_t)((b*NHEAD + h)*SEQ) + l) * HDIM;
                    *(__half2*)&Hm[base + d] = __floats2half2_rn(vx*sc, vy*sc);
                } else {
                    *(float2*)&Cf[(size_t)mm * DMODEL + n] = make_float2(vx, vy);
                }
            }
        }
    }
}

// =================================================================
// Flash attention v10 (unchanged from R13/R14): fp16, log2 softmax,
// f16x2 exponentials, 256 thr = 8 warps x 16 q, 128 q/block,
// 64-key chunks, 3-stage cp.async K/V pipeline, ldmatrix fragments.
// =================================================================
#define FQS 72
#define FA_Q (128*FQS)                 // 9216 halves
#define FA_K (64*FQS)                  // 4608
#define FA_V (64*FQS)                  // 4608
#define FA_SMEM_BYTES ((FA_Q + 3*FA_K + 3*FA_V)*2)   // 73728 B

__global__ __launch_bounds__(256, 2)
void flash_mma(const int* __restrict__ mask,
               const __half* __restrict__ Qg,
               const __half* __restrict__ Kg,
               const __half* __restrict__ Vg,
               __half* __restrict__ Og)
{
    extern __shared__ __half smh[];
    const uint32_t smb = smem_u32(smh);
    __shared__ int msk[64];

    const int tid  = threadIdx.x;
    const int lane = tid & 31;
    const int wid  = tid >> 5;
    const int g    = lane >> 2;
    const int tig  = lane & 3;
    const int qb   = wid * 16;

    const int bh = blockIdx.y;
    const int b  = bh / NHEAD;
    const int h  = bh % NHEAD;
    const int q0 = blockIdx.x * 128;

    const size_t bhBase = (size_t)(b*NHEAD + h) * SEQ * HDIM;

    // K/V staging: 64 rows x 8 x 16B; 4 threads/row, 2 chunks each
    const int lr2 = tid >> 2;
    const int cb2 = (tid & 3) * 2;
    const __half* Ksrc = Kg + bhBase + (size_t)lr2 * HDIM + cb2 * 8;
    const __half* Vsrc = Vg + bhBase + (size_t)lr2 * HDIM + cb2 * 8;
    const uint32_t kDst0 = smb + FA_Q*2 + lr2 * (FQS*2) + cb2 * 16;
    const uint32_t vDst0 = smb + (FA_Q + 3*FA_K)*2 + lr2 * (FQS*2) + cb2 * 16;

    // ldmatrix lane offsets (bytes)
    const uint32_t laneQ_off = (uint32_t)(qb + (lane & 15)) * (FQS*2)
                             + (uint32_t)(lane >> 4) * 16;
    const uint32_t laneK_off = (uint32_t)((lane & 7) + ((lane >> 4) & 1) * 8) * (FQS*2)
                             + (uint32_t)((lane >> 3) & 1) * 16;
    const uint32_t laneV_off = (uint32_t)(lane & 15) * (FQS*2)
                             + (uint32_t)(lane >> 4) * 16;

    // ---- prologue: G0 = Q, G1 = KV0, G2 = KV1 ----
    {
        const int qr = tid >> 1;
        const int qc = (tid & 1) * 4;
        const __half* qsrc = Qg + bhBase + (size_t)(q0 + qr) * HDIM + qc * 8;
        uint32_t qdst = smb + qr * (FQS*2) + qc * 16;
#pragma unroll
        for (int j = 0; j < 4; j++) cp16(qdst + j*16, qsrc + j*8);
        cp_commit();   // G0
#pragma unroll
        for (int j = 0; j < 2; j++) {
            cp16(kDst0 + j*16, Ksrc + j*8);
            cp16(vDst0 + j*16, Vsrc + j*8);
        }
        cp_commit();   // G1
        const __half* ks1 = Ksrc + 64*HDIM;
        const __half* vs1 = Vsrc + 64*HDIM;
#pragma unroll
        for (int j = 0; j < 2; j++) {
            cp16(kDst0 + FA_K*2 + j*16, ks1 + j*8);
            cp16(vDst0 + FA_V*2 + j*16, vs1 + j*8);
        }
        cp_commit();   // G2
    }

    // ---- whole-sequence mask precheck ----
    int sv = 1;
#pragma unroll
    for (int j = 0; j < 8; j++)
        sv &= (mask[b*SEQ + tid + j*256] != 0);
    const int allSeq = __syncthreads_and(sv);
    int mreg = 0;
    if (!allSeq && tid < 64) mreg = mask[b*SEQ + tid];

    // ---- Q fragments to registers (once) ----
    cp_wait2();              // G0 (Q) complete
    __syncthreads();
    uint32_t qa[4][4];
#pragma unroll
    for (int kg = 0; kg < 4; kg++)
        ldsm_x4(qa[kg][0], qa[kg][1], qa[kg][2], qa[kg][3],
                smb + laneQ_off + kg*32);

    float o[8][4];
#pragma unroll
    for (int nt = 0; nt < 8; nt++)
#pragma unroll
        for (int q = 0; q < 4; q++) o[nt][q] = 0.f;
    float ol[4] = {0.f, 0.f, 0.f, 0.f};
    float mrow0 = -1e30f, mrow1 = -1e30f;

    int st = 0;
    for (int c = 0; c < 32; c++) {
        cp_wait1();
        int allv;
        if (!allSeq) {
            if (tid < 64) msk[tid] = mreg;
            int curv = (tid < 64) ? (mreg != 0) : 1;
            if (c + 1 < 32 && tid < 64) mreg = mask[b*SEQ + (c+1)*64 + tid];
            allv = __syncthreads_and(curv);
        } else {
            __syncthreads();
            allv = 1;
        }

        // issue chunk c+2 (always commit to keep wait accounting)
        {
            int st2 = st + 2; if (st2 >= 3) st2 -= 3;
            if (c + 2 < 32) {
                const __half* ks = Ksrc + (size_t)(c+2) * 64 * HDIM;
                const __half* vs = Vsrc + (size_t)(c+2) * 64 * HDIM;
                const uint32_t kd = kDst0 + st2 * (FA_K*2);
                const uint32_t vd = vDst0 + st2 * (FA_V*2);
#pragma unroll
                for (int j = 0; j < 2; j++) {
                    cp16(kd + j*16, ks + j*8);
                    cp16(vd + j*16, vs + j*8);
                }
            }
            cp_commit();
        }

        const uint32_t kBase = smb + FA_Q*2 + st * (FA_K*2) + laneK_off;

        // ---- S = Q K^T (ldmatrix.x4 for 2 n-tiles at a time) ----
        float s[8][4];
#pragma unroll
        for (int nt = 0; nt < 8; nt++)
#pragma unroll
            for (int q = 0; q < 4; q++) s[nt][q] = 0.f;

#pragma unroll
        for (int kg = 0; kg < 4; kg++) {
#pragma unroll
            for (int ntp = 0; ntp < 4; ntp++) {
                uint32_t b0, b1, b2, b3;
                ldsm_x4(b0, b1, b2, b3, kBase + ntp * (16*FQS*2) + kg*32);
                mma_f16(s[2*ntp  ], qa[kg][0], qa[kg][1], qa[kg][2], qa[kg][3], b0, b1);
                mma_f16(s[2*ntp+1], qa[kg][0], qa[kg][1], qa[kg][2], qa[kg][3], b2, b3);
            }
        }

        // ---- mask (skipped when chunk fully valid) ----
        if (!allv) {
#pragma unroll
            for (int nt = 0; nt < 8; nt++) {
                int j0 = nt*8 + 2*tig;
                bool k0 = (msk[j0]   != 0);
                bool k1 = (msk[j0+1] != 0);
                s[nt][0] = k0 ? s[nt][0] : NEG_INF_V;
                s[nt][1] = k1 ? s[nt][1] : NEG_INF_V;
                s[nt][2] = k0 ? s[nt][2] : NEG_INF_V;
                s[nt][3] = k1 ? s[nt][3] : NEG_INF_V;
            }
        }

        // ---- online softmax (log2 domain) with stable-max elision ----
        float rm0 = -1e30f, rm1 = -1e30f;
#pragma unroll
        for (int nt = 0; nt < 8; nt++) {
            rm0 = fmaxf(rm0, fmaxf(s[nt][0], s[nt][1]));
            rm1 = fmaxf(rm1, fmaxf(s[nt][2], s[nt][3]));
        }
        rm0 = fmaxf(rm0, __shfl_xor_sync(0xffffffffu, rm0, 1));
        rm0 = fmaxf(rm0, __shfl_xor_sync(0xffffffffu, rm0, 2));
        rm1 = fmaxf(rm1, __shfl_xor_sync(0xffffffffu, rm1, 1));
        rm1 = fmaxf(rm1, __shfl_xor_sync(0xffffffffu, rm1, 2));

        float mn0 = fmaxf(mrow0, rm0);
        float mn1 = fmaxf(mrow1, rm1);
        bool stable = __all_sync(0xffffffffu, (mn0 == mrow0) && (mn1 == mrow1));
        if (!stable) {
            float fac0 = ex2f(mrow0 - mn0);
            float fac1 = ex2f(mrow1 - mn1);
            ol[0] *= fac0;
            ol[2] *= fac1;
#pragma unroll
            for (int nt = 0; nt < 8; nt++) {
                o[nt][0] *= fac0; o[nt][1] *= fac0;
                o[nt][2] *= fac1; o[nt][3] *= fac1;
            }
            mrow0 = mn0;
            mrow1 = mn1;
        }

        // ---- O += P V, l += P 1 : P computed as ex2.f16x2 of (s - m) ----
        const uint32_t vBase = smb + (FA_Q + 3*FA_K)*2 + st * (FA_V*2) + laneV_off;
#pragma unroll
        for (int kg = 0; kg < 4; kg++) {
            uint32_t a0 = h2ex2(pack2(s[2*kg  ][0] - mrow0, s[2*kg  ][1] - mrow0));
            uint32_t a1 = h2ex2(pack2(s[2*kg  ][2] - mrow1, s[2*kg  ][3] - mrow1));
            uint32_t a2 = h2ex2(pack2(s[2*kg+1][0] - mrow0, s[2*kg+1][1] - mrow0));
            uint32_t a3 = h2ex2(pack2(s[2*kg+1][2] - mrow1, s[2*kg+1][3] - mrow1));
            mma_f16(ol, a0, a1, a2, a3, ONES2, ONES2);
            const uint32_t rowa = vBase + kg * (16*FQS*2);
#pragma unroll
            for (int ntp = 0; ntp < 4; ntp++) {
                uint32_t r0, r1, r2, r3;
                ldsm_x4_t(r0, r1, r2, r3, rowa + ntp*32);
                mma_f16(o[2*ntp  ], a0, a1, a2, a3, r0, r1);
                mma_f16(o[2*ntp+1], a0, a1, a2, a3, r2, r3);
            }
        }

        st++; if (st == 3) st = 0;
    }

    // ---- epilogue: normalize, fp16 -> g_O [B,L,D] (natural) ----
    float inv0 = 1.f / ol[0];
    float inv1 = 1.f / ol[2];
    int qg0 = q0 + qb + g;
    int qg1 = qg0 + 8;
#pragma unroll
    for (int nt = 0; nt < 8; nt++) {
        int pos = h*HDIM + nt*8 + 2*tig;
        *(__half2*)&Og[(size_t)(b*SEQ + qg0)*DMODEL + pos] =
            __floats2half2_rn(o[nt][0]*inv0, o[nt][1]*inv0);
        *(__half2*)&Og[(size_t)(b*SEQ + qg1)*DMODEL + pos] =
            __floats2half2_rn(o[nt][2]*inv1, o[nt][3]*inv1);
    }
}

// =================================================================
// Host launcher
// =================================================================
extern "C" void kernel_launch(void* const* d_in, const int* in_sizes, int n_in,
                              void* d_out, int out_size)
{
    const float* q    = (const float*)d_in[0];
    const float* k    = (const float*)d_in[1];
    const float* v    = (const float*)d_in[2];
    const int*   am   = (const int*)  d_in[3];
    const float* Wq   = (const float*)d_in[4];
    const float* Wk   = (const float*)d_in[5];
    const float* Wv   = (const float*)d_in[6];
    const float* Wo   = (const float*)d_in[7];
    float* out = (float*)d_out;

    __half *gA, *gW, *gQ, *gK, *gV, *gO;
    cudaGetSymbolAddress((void**)&gA, g_A);
    cudaGetSymbolAddress((void**)&gW, g_W);
    cudaGetSymbolAddress((void**)&gQ, g_Q);
    cudaGetSymbolAddress((void**)&gK, g_K);
    cudaGetSymbolAddress((void**)&gV, g_V);
    cudaGetSymbolAddress((void**)&gO, g_O);

    cudaFuncSetAttribute(gemm_mma<0>, cudaFuncAttributeMaxDynamicSharedMemorySize, GT_SMEM_BYTES);
    cudaFuncSetAttribute(gemm_mma<1>, cudaFuncAttributeMaxDynamicSharedMemorySize, GT_SMEM_BYTES);
    cudaFuncSetAttribute(flash_mma,   cudaFuncAttributeMaxDynamicSharedMemorySize, FA_SMEM_BYTES);

    // pre-pass: fp16 round, all 7 matrices in one launch
    {
        int gpmA = MROWS*DMODEL/16;    // 262144 groups (largest)
        dim3 pg((gpmA + 255)/256, 1, 7);
        prep_all<<<pg, 256>>>(q, k, v, Wq, Wk, Wv, Wo, gA, gW);
    }

    // fused QKV projections (512-thread CTAs, 3-stage pipeline)
    dim3 gGrid(DMODEL/128, MROWS/128, 3);  // (8, 32, 3)
    gemm_mma<0><<<gGrid, 512, GT_SMEM_BYTES>>>(gA, gW, gQ, gK, gV, out);

    dim3 aGrid(SEQ/128, BATCH*NHEAD);      // (16, 32)
    flash_mma<<<aGrid, 256, FA_SMEM_BYTES>>>(am, gQ, gK, gV, gO);

    dim3 oGrid(DMODEL/128, MROWS/128, 1);  // (8, 32)
    gemm_mma<1><<<oGrid, 512, GT_SMEM_BYTES>>>(gO, gW + 3u*DMODEL*DMODEL,
                                               gQ, gK, gV, out);
}